// round 7
// baseline (speedup 1.0000x reference)
#include <cuda_runtime.h>
#include <cuda_fp16.h>
#include <math.h>
#include <stdint.h>

#define B_  16
#define L_  4096
#define H_  512
#define NT_ 8
#define IN_ 10
#define OUT_ 1032
#define KP   1056            // padded K (66 chunks of 16)
#define NCH16 66
#define HH_ 256
#define NC_ 16
#define CH_ 256
#define EPS_ 1e-5f
#define NROW (B_*L_)
#define NTILE (NROW/64)

// ---------------- device scratch (static, allocation-free) ----------------
__device__ float g_xc[NROW*IN_];
__device__ float g_F [(size_t)NROW*KP];             // features (dead regions stay 0)
__device__ float g_W [4][H_][IN_];
__device__ float g_bias[4][H_];
__device__ __half g_Gh[(size_t)NCH16*32*128];       // B fp16 fragment-major (pads 0)
__device__ float g_sv[HH_];
__device__ float g_cv[HH_];
__device__ int   g_tilef[NTILE];                    // per-64-row-tile nonzero flags

// ---------------- zero accumulators / flags --------------------------------
__global__ void k_zero() {
    int i = blockIdx.x*blockDim.x + threadIdx.x;
    if (i < 4*H_*IN_) ((float*)g_W)[i] = 0.f;
    if (i < 4*H_)     ((float*)g_bias)[i] = 0.f;
    if (i < HH_)      { g_sv[i] = 0.f; g_cv[i] = 0.f; }
    if (i < NTILE)    g_tilef[i] = 0;
}

// ---------------- fold gate weights through the 10-dim projection ----------
__global__ void k_fold(const float* __restrict__ fz, const float* __restrict__ fh,
                       const float* __restrict__ bz, const float* __restrict__ bh,
                       const float* __restrict__ fzb, const float* __restrict__ fhb,
                       const float* __restrict__ bzb, const float* __restrict__ bhb,
                       const float* __restrict__ fp, const float* __restrict__ fpb,
                       const float* __restrict__ bp, const float* __restrict__ bpb) {
    int p = blockIdx.x, sl = blockIdx.y;
    int h = threadIdx.x;
    const float* zw = (p==0)?fz:(p==1)?fh:(p==2)?bz:bh;
    const float* zb = (p==0)?fzb:(p==1)?fhb:(p==2)?bzb:bhb;
    const float* pw = (p<2)?fp:bp;
    const float* pb = (p<2)?fpb:bpb;
    float acc[IN_]; float ab = 0.f;
    #pragma unroll
    for (int i=0;i<IN_;i++) acc[i]=0.f;
    for (int d=sl*64; d<sl*64+64; d++) {
        float w = zw[h*H_+d];
        #pragma unroll
        for (int i=0;i<IN_;i++) acc[i] += w*pw[d*IN_+i];
        ab += w*pb[d];
    }
    #pragma unroll
    for (int i=0;i<IN_;i++) atomicAdd(&g_W[p][h][i], acc[i]);
    atomicAdd(&g_bias[p][h], ab + ((sl==0)? zb[h] : 0.f));
}

// ---------------- fold LN affine into gh_w1, emit fp16 fragment-major B ----
__global__ void k_prepG(const float* __restrict__ gw1, const float* __restrict__ gb1,
                        const float* __restrict__ lng, const float* __restrict__ lnb,
                        const float* __restrict__ tscp) {
    int k = threadIdx.x;                 // output col n, 0..255
    int j0 = blockIdx.x * (OUT_/8);
    float tsc = tscp[0];
    int nt = k >> 3, ng = k & 7;
    float s = 0.f, c = 0.f;
    for (int j=j0; j<j0+OUT_/8; j++) {
        float sc = (j >= OUT_-NT_) ? tsc : 1.0f;
        float w  = gw1[k*OUT_+j];
        __half Gh = __float2half_rn(lng[j]*sc*w);
        int kt = j >> 4, kin = j & 15;
        int lane = ng*4 + ((kin & 7) >> 1);
        int reg = kin >> 3, hs = kin & 1;
        g_Gh[(((size_t)(kt*32 + nt)*32 + lane)*2 + reg)*2 + hs] = Gh;
        s += __half2float(Gh);
        c += lnb[j]*sc*w;
    }
    atomicAdd(&g_sv[k], s);
    atomicAdd(&g_cv[k], c + ((blockIdx.x==0)? gb1[k] : 0.f));
}

// ---------------- time embedding + xc, te into F ---------------------------
__global__ void k_te(const float* __restrict__ x, const float* __restrict__ t,
                     const float* __restrict__ w1, const float* __restrict__ b1,
                     const float* __restrict__ w2, const float* __restrict__ b2) {
    int row = blockIdx.x*blockDim.x + threadIdx.x;
    if (row >= NROW) return;
    int b = row / L_;
    float ts = t[row] - t[b*L_];
    float r[NT_];
    #pragma unroll
    for (int j=0;j<NT_;j++) r[j] = fmaxf(ts*w1[j] + b1[j], 0.0f);
    float te[NT_];
    #pragma unroll
    for (int k=0;k<NT_;k++) {
        float a = b2[k];
        #pragma unroll
        for (int j=0;j<NT_;j++) a += r[j]*w2[k*NT_+j];
        te[k] = a;
        g_xc[row*IN_+2+k] = a;
    }
    float* fte = g_F + (size_t)row*KP + (OUT_-NT_);
    *(float4*)(fte)     = make_float4(te[0], te[1], te[2], te[3]);
    *(float4*)(fte + 4) = make_float4(te[4], te[5], te[6], te[7]);
    g_xc[row*IN_+0] = x[row*2+0];
    g_xc[row*IN_+1] = x[row*2+1];
}

// fast sigmoid pieces
__device__ __forceinline__ void fsig(float arg, float& z, float& omz) {
    float e = __expf(-arg);
    z = __fdividef(1.0f, 1.0f + e);
    omz = e * z;
}

// ---------------- MERGED sequential scan (replaces A,B1,C1,B2,C2) ---------
// grid (B_, 2), block 512. Bit-identical fp op order to the chunked version
// over the live prefix; dead region stays exact 0 via static init.
__global__ void k_scan() {
    int b = blockIdx.x, dir = blockIdx.y;
    int h = threadIdx.x;
    __shared__ float xs[CH_][IN_];
    __shared__ int sred[H_];
    float wz[IN_], wh[IN_]; float bz, bh;
    int pz = dir*2, ph = dir*2+1;
    #pragma unroll
    for (int i=0;i<IN_;i++) { wz[i]=g_W[pz][h][i]; wh[i]=g_W[ph][h][i]; }
    bz = g_bias[pz][h]; bh = g_bias[ph][h];

    float A = 1.0f, S = 0.0f;
    int zstep = 0;
    size_t fofs = (dir==0)? (size_t)h : (size_t)(H_ + h);
    size_t rowbase = (size_t)b*L_;
    int alive = 1;

    for (int c=0; c<NC_ && alive; c++) {
        int cc = dir ? (NC_-1-c) : c;
        const float* xcb = g_xc + (rowbase + (size_t)cc*CH_)*IN_;
        for (int i=h; i<CH_*IN_; i+=H_) ((float*)xs)[i] = xcb[i];
        __syncthreads();
        for (int grp=0; grp<CH_/32 && alive; grp++) {
            #pragma unroll
            for (int kk=0; kk<32; kk++) {
                int kin = grp*32 + kk;            // step within chunk
                int s   = dir ? (CH_-1-kin) : kin;
                int lg  = c*CH_ + kin;            // global step in scan order
                int l   = dir ? (L_-1-lg) : lg;   // actual sequence position
                if (A != 0.f) zstep = lg + 1;     // predicated, no branch
                g_F[(rowbase + l)*KP + fofs] = A*S;   // state BEFORE consuming l
                float az = bz, ah = bh;
                #pragma unroll
                for (int i=0;i<IN_;i++) { float xv = xs[s][i]; az += xv*wz[i]; ah += xv*wh[i]; }
                float z, omz; fsig(az, z, omz);
                A *= omz;
                S += __fdividef(z*ah, fmaxf(A, 1e-12f));
            }
            alive = __syncthreads_or(A != 0.f);   // uniform vote (also a barrier)
        }
    }

    // block-max of zstep -> tile flags
    sred[h] = zstep;
    __syncthreads();
    #pragma unroll
    for (int off=256; off>0; off>>=1) {
        if (h < off) sred[h] = max(sred[h], sred[h+off]);
        __syncthreads();
    }
    if (h == 0) {
        int zmax = sred[0];
        int nt = (zmax + 63) >> 6;
        int base = (b*L_) >> 6;
        for (int j=0; j<nt; j++) {
            int lt = dir ? (L_/64 - 1 - j) : j;
            atomicOr(&g_tilef[base + lt], 1 << dir);
        }
    }
}

// ---------------- fp16 mma GEMM (R6, contiguous live range) ----------------
#define GBM 64
__global__ __launch_bounds__(512, 1) void k_gemm3(const float* __restrict__ w2,
                                                  const float* __restrict__ b2p,
                                                  float* __restrict__ out) {
    __shared__ float s_s[HH_], s_c[HH_], s_w2[HH_];
    __shared__ float s_sum[GBM], s_sq[GBM];
    __shared__ float s_mu[GBM], s_rs[GBM];
    __shared__ float s_part[GBM][4];

    int t = threadIdx.x;
    int lane = t & 31, warp = t >> 5;
    int wm = warp >> 2, wn = warp & 3;      // 4m x 4n warp grid
    int g  = lane >> 2, tig = lane & 3;
    int row0 = blockIdx.x * GBM;
    int r0 = row0 + wm*16 + g;

    if (t < HH_) { s_s[t] = g_sv[t]; s_c[t] = g_cv[t]; s_w2[t] = w2[t]; }

    int flag = g_tilef[blockIdx.x] & 3;
    int c0 = (flag & 1) ? 0 : 32;           // contiguous live chunk range start
    int n  = (flag == 3) ? 64 : (flag ? 32 : 0);
    int total = n + 1;                      // + te chunk (64)

    float acc[8][4];
    #pragma unroll
    for (int i=0;i<8;i++) { acc[i][0]=0.f; acc[i][1]=0.f; acc[i][2]=0.f; acc[i][3]=0.f; }

    const float* Ar0 = g_F + (size_t)r0*KP     + tig*2;
    const float* Ar8 = Ar0 + 8*KP;
    const uint2* Bp  = ((const uint2*)g_Gh) + ((size_t)wn*8)*32 + lane;

    int ci = (0 < n) ? c0 : 64;
    float2 fA0 = __ldg((const float2*)(Ar0 + ci*16));
    float2 fA1 = __ldg((const float2*)(Ar8 + ci*16));
    float2 fA2 = __ldg((const float2*)(Ar0 + ci*16 + 8));
    float2 fA3 = __ldg((const float2*)(Ar8 + ci*16 + 8));
    uint2 fB[8];
    {
        const uint2* Bn = Bp + (size_t)ci*1024;
        #pragma unroll
        for (int nt=0; nt<8; nt++) fB[nt] = __ldg(Bn + nt*32);
    }

    float ps0=0.f, pq0=0.f, ps1=0.f, pq1=0.f;

    for (int it=0; it<total; it++) {
        if (wn == 0) {
            ps0 += fA0.x+fA0.y+fA2.x+fA2.y;
            pq0 += fA0.x*fA0.x + fA0.y*fA0.y + fA2.x*fA2.x + fA2.y*fA2.y;
            ps1 += fA1.x+fA1.y+fA3.x+fA3.y;
            pq1 += fA1.x*fA1.x + fA1.y*fA1.y + fA3.x*fA3.x + fA3.y*fA3.y;
        }
        __half2 h0 = __floats2half2_rn(fA0.x, fA0.y);
        __half2 h1 = __floats2half2_rn(fA1.x, fA1.y);
        __half2 h2 = __floats2half2_rn(fA2.x, fA2.y);
        __half2 h3 = __floats2half2_rn(fA3.x, fA3.y);
        uint32_t a0 = *reinterpret_cast<uint32_t*>(&h0);
        uint32_t a1 = *reinterpret_cast<uint32_t*>(&h1);
        uint32_t a2 = *reinterpret_cast<uint32_t*>(&h2);
        uint32_t a3 = *reinterpret_cast<uint32_t*>(&h3);
        #pragma unroll
        for (int nt=0; nt<8; nt++) {
            asm volatile(
                "mma.sync.aligned.m16n8k16.row.col.f32.f16.f16.f32 "
                "{%0,%1,%2,%3}, {%4,%5,%6,%7}, {%8,%9}, {%0,%1,%2,%3};"
                : "+f"(acc[nt][0]), "+f"(acc[nt][1]), "+f"(acc[nt][2]), "+f"(acc[nt][3])
                : "r"(a0), "r"(a1), "r"(a2), "r"(a3), "r"(fB[nt].x), "r"(fB[nt].y));
        }
        if (it+1 < total) {
            int itn = it+1;
            ci = (itn < n) ? (c0 + itn) : 64;   // branchless select
            fA0 = __ldg((const float2*)(Ar0 + ci*16));
            fA1 = __ldg((const float2*)(Ar8 + ci*16));
            fA2 = __ldg((const float2*)(Ar0 + ci*16 + 8));
            fA3 = __ldg((const float2*)(Ar8 + ci*16 + 8));
            const uint2* Bn = Bp + (size_t)ci*1024;
            #pragma unroll
            for (int nt=0; nt<8; nt++) fB[nt] = __ldg(Bn + nt*32);
        }
    }

    if (wn == 0) {
        #pragma unroll
        for (int off=1; off<4; off<<=1) {
            ps0 += __shfl_xor_sync(0xffffffffu, ps0, off);
            pq0 += __shfl_xor_sync(0xffffffffu, pq0, off);
            ps1 += __shfl_xor_sync(0xffffffffu, ps1, off);
            pq1 += __shfl_xor_sync(0xffffffffu, pq1, off);
        }
        if (tig == 0) {
            s_sum[wm*16+g]   = ps0;  s_sq[wm*16+g]   = pq0;
            s_sum[wm*16+g+8] = ps1;  s_sq[wm*16+g+8] = pq1;
        }
    }
    __syncthreads();
    if (t < GBM) {
        float m = s_sum[t] * (1.0f/(float)OUT_);
        float v = s_sq[t]  * (1.0f/(float)OUT_) - m*m;
        s_mu[t] = m;
        s_rs[t] = rsqrtf(v + EPS_);
    }
    __syncthreads();

    float mu0 = s_mu[wm*16+g],   rs0 = s_rs[wm*16+g];
    float mu1 = s_mu[wm*16+g+8], rs1 = s_rs[wm*16+g+8];
    float po0 = 0.f, po1 = 0.f;
    #pragma unroll
    for (int nt=0; nt<8; nt++) {
        #pragma unroll
        for (int e=0; e<2; e++) {
            int col = wn*64 + nt*8 + tig*2 + e;
            float sS = s_s[col], sC = s_c[col], wv = s_w2[col];
            float v0 = (acc[nt][e]   - mu0*sS)*rs0 + sC;
            float v1 = (acc[nt][2+e] - mu1*sS)*rs1 + sC;
            float h0 = 0.5f*v0*(1.0f + erff(v0*0.70710678118654752440f));
            float h1 = 0.5f*v1*(1.0f + erff(v1*0.70710678118654752440f));
            po0 += h0*wv;
            po1 += h1*wv;
        }
    }
    #pragma unroll
    for (int off=1; off<4; off<<=1) {
        po0 += __shfl_xor_sync(0xffffffffu, po0, off);
        po1 += __shfl_xor_sync(0xffffffffu, po1, off);
    }
    if (tig == 0) {
        s_part[wm*16+g][wn]   = po0;
        s_part[wm*16+g+8][wn] = po1;
    }
    __syncthreads();
    if (t < GBM) {
        out[row0 + t] = b2p[0] + s_part[t][0] + s_part[t][1] + s_part[t][2] + s_part[t][3];
    }
}

// ---------------- launch ---------------------------------------------------
extern "C" void kernel_launch(void* const* d_in, const int* in_sizes, int n_in,
                              void* d_out, int out_size) {
    const float* x      = (const float*)d_in[0];
    const float* t      = (const float*)d_in[1];
    const float* te_w1  = (const float*)d_in[2];
    const float* te_b1  = (const float*)d_in[3];
    const float* te_w2  = (const float*)d_in[4];
    const float* te_b2  = (const float*)d_in[5];
    const float* fproj_w= (const float*)d_in[6];
    const float* fproj_b= (const float*)d_in[7];
    const float* bproj_w= (const float*)d_in[8];
    const float* bproj_b= (const float*)d_in[9];
    const float* fz_w   = (const float*)d_in[10];
    const float* fz_b   = (const float*)d_in[11];
    const float* fh_w   = (const float*)d_in[12];
    const float* fh_b   = (const float*)d_in[13];
    const float* bz_w   = (const float*)d_in[14];
    const float* bz_b   = (const float*)d_in[15];
    const float* bh_w   = (const float*)d_in[16];
    const float* bh_b   = (const float*)d_in[17];
    const float* ln_g   = (const float*)d_in[18];
    const float* ln_b   = (const float*)d_in[19];
    const float* tsc    = (const float*)d_in[20];
    const float* gh_w1  = (const float*)d_in[21];
    const float* gh_b1  = (const float*)d_in[22];
    const float* gh_w2  = (const float*)d_in[23];
    const float* gh_b2  = (const float*)d_in[24];
    float* out = (float*)d_out;

    k_zero<<<(4*H_*IN_ + 255)/256, 256>>>();
    k_fold<<<dim3(4, 8), H_>>>(fz_w, fh_w, bz_w, bh_w, fz_b, fh_b, bz_b, bh_b,
                               fproj_w, fproj_b, bproj_w, bproj_b);
    k_prepG<<<8, HH_>>>(gh_w1, gh_b1, ln_g, ln_b, tsc);
    k_te<<<NROW/256, 256>>>(x, t, te_w1, te_b1, te_w2, te_b2);
    k_scan<<<dim3(B_, 2), H_>>>();
    k_gemm3<<<NROW/GBM, 512>>>(gh_w2, gh_b2, out);
}

// round 10
// speedup vs baseline: 1.1447x; 1.1447x over previous
#include <cuda_runtime.h>
#include <cuda_fp16.h>
#include <math.h>
#include <stdint.h>

#define B_  16
#define L_  4096
#define H_  512
#define NT_ 8
#define IN_ 10
#define OUT_ 1032
#define KP   1056            // padded K (66 chunks of 16)
#define NCH16 66
#define HH_ 256
#define NC_ 16
#define CH_ 256
#define EPS_ 1e-5f
#define NROW (B_*L_)
#define NTILE (NROW/64)

// ---------------- device scratch (static, allocation-free) ----------------
__device__ float g_xc[NROW*IN_];
__device__ float g_F [(size_t)NROW*KP];             // features (dead regions stay 0)
__device__ float g_W [4][H_][IN_];
__device__ float g_bias[4][H_];
__device__ float g_Ae[2][B_][NC_][H_];              // sequential cumprod entry states
__device__ float g_Lc[2][B_][NC_][H_];
__device__ float g_Se[2][B_][NC_][H_];
__device__ __half g_Gh[(size_t)NCH16*32*128];       // B fp16 fragment-major (pads 0)
__device__ float g_sv[HH_];
__device__ float g_cv[HH_];
__device__ int   g_tilef[NTILE];                    // per-64-row-tile nonzero flags

// ---------------- zero accumulators / flags --------------------------------
__global__ void k_zero() {
    int i = blockIdx.x*blockDim.x + threadIdx.x;
    if (i < 4*H_*IN_) ((float*)g_W)[i] = 0.f;
    if (i < 4*H_)     ((float*)g_bias)[i] = 0.f;
    if (i < HH_)      { g_sv[i] = 0.f; g_cv[i] = 0.f; }
    if (i < NTILE)    g_tilef[i] = 0;
}

// ---------------- fold gate weights through the 10-dim projection ----------
__global__ void k_fold(const float* __restrict__ fz, const float* __restrict__ fh,
                       const float* __restrict__ bz, const float* __restrict__ bh,
                       const float* __restrict__ fzb, const float* __restrict__ fhb,
                       const float* __restrict__ bzb, const float* __restrict__ bhb,
                       const float* __restrict__ fp, const float* __restrict__ fpb,
                       const float* __restrict__ bp, const float* __restrict__ bpb) {
    int p = blockIdx.x, sl = blockIdx.y;   // 16 slices of 32 rows
    int h = threadIdx.x;
    const float* zw = (p==0)?fz:(p==1)?fh:(p==2)?bz:bh;
    const float* zb = (p==0)?fzb:(p==1)?fhb:(p==2)?bzb:bhb;
    const float* pw = (p<2)?fp:bp;
    const float* pb = (p<2)?fpb:bpb;
    float acc[IN_]; float ab = 0.f;
    #pragma unroll
    for (int i=0;i<IN_;i++) acc[i]=0.f;
    for (int d=sl*32; d<sl*32+32; d++) {
        float w = zw[h*H_+d];
        #pragma unroll
        for (int i=0;i<IN_;i++) acc[i] += w*pw[d*IN_+i];
        ab += w*pb[d];
    }
    #pragma unroll
    for (int i=0;i<IN_;i++) atomicAdd(&g_W[p][h][i], acc[i]);
    atomicAdd(&g_bias[p][h], ab + ((sl==0)? zb[h] : 0.f));
}

// ---------------- fold LN affine into gh_w1, emit fp16 fragment-major B ----
__global__ void k_prepG(const float* __restrict__ gw1, const float* __restrict__ gb1,
                        const float* __restrict__ lng, const float* __restrict__ lnb,
                        const float* __restrict__ tscp) {
    int k = threadIdx.x;                 // output col n, 0..255
    int j0 = blockIdx.x * 43;            // 24 blocks x 43 = 1032
    float tsc = tscp[0];
    int nt = k >> 3, ng = k & 7;
    float s = 0.f, c = 0.f;
    for (int j=j0; j<j0+43; j++) {
        float sc = (j >= OUT_-NT_) ? tsc : 1.0f;
        float w  = gw1[k*OUT_+j];
        __half Gh = __float2half_rn(lng[j]*sc*w);
        int kt = j >> 4, kin = j & 15;
        int lane = ng*4 + ((kin & 7) >> 1);
        int reg = kin >> 3, hs = kin & 1;
        g_Gh[(((size_t)(kt*32 + nt)*32 + lane)*2 + reg)*2 + hs] = Gh;
        s += __half2float(Gh);
        c += lnb[j]*sc*w;
    }
    atomicAdd(&g_sv[k], s);
    atomicAdd(&g_cv[k], c + ((blockIdx.x==0)? gb1[k] : 0.f));
}

// ---------------- time embedding + xc, te into F ---------------------------
__global__ void k_te(const float* __restrict__ x, const float* __restrict__ t,
                     const float* __restrict__ w1, const float* __restrict__ b1,
                     const float* __restrict__ w2, const float* __restrict__ b2) {
    int row = blockIdx.x*blockDim.x + threadIdx.x;
    if (row >= NROW) return;
    int b = row / L_;
    float ts = t[row] - t[b*L_];
    float r[NT_];
    #pragma unroll
    for (int j=0;j<NT_;j++) r[j] = fmaxf(ts*w1[j] + b1[j], 0.0f);
    float te[NT_];
    #pragma unroll
    for (int k=0;k<NT_;k++) {
        float a = b2[k];
        #pragma unroll
        for (int j=0;j<NT_;j++) a += r[j]*w2[k*NT_+j];
        te[k] = a;
        g_xc[row*IN_+2+k] = a;
    }
    float* fte = g_F + (size_t)row*KP + (OUT_-NT_);
    *(float4*)(fte)     = make_float4(te[0], te[1], te[2], te[3]);
    *(float4*)(fte + 4) = make_float4(te[4], te[5], te[6], te[7]);
    g_xc[row*IN_+0] = x[row*2+0];
    g_xc[row*IN_+1] = x[row*2+1];
}

// fast sigmoid pieces
__device__ __forceinline__ void fsig(float arg, float& z, float& omz) {
    float e = __expf(-arg);
    z = __fdividef(1.0f, 1.0f + e);
    omz = e * z;
}

// ---------------- merged A+B1: sequential cumprod entry states -------------
// grid (B_,2), 512 thr. R6 code shape: unroll 4, branch-free inner loop,
// UNIFORM per-chunk vote only (no per-step breaks).
__global__ void k_scanAB1() {
    int b = blockIdx.x, dir = blockIdx.y;
    int h = threadIdx.x;
    __shared__ float xs[CH_][IN_];
    float wz[IN_]; float bz;
    int pz = dir*2;
    #pragma unroll
    for (int i=0;i<IN_;i++) wz[i] = g_W[pz][h][i];
    bz = g_bias[pz][h];
    float run = 1.0f;
    int c = 0;
    for (; c<NC_; c++) {
        int cc = dir ? (NC_-1-c) : c;
        g_Ae[dir][b][cc][h] = run;
        if (!__syncthreads_or(run != 0.f)) break;   // uniform exit (also barrier)
        const float* xcb = g_xc + ((size_t)b*L_ + (size_t)cc*CH_)*IN_;
        for (int i=h; i<CH_*IN_; i+=H_) ((float*)xs)[i] = xcb[i];
        __syncthreads();
        int s0 = dir ? CH_-1 : 0;
        int ds = dir ? -1 : 1;
        #pragma unroll 4
        for (int k=0;k<CH_;k++) {
            int s = s0 + k*ds;
            float arg = bz;
            #pragma unroll
            for (int i=0;i<IN_;i++) arg += xs[s][i]*wz[i];
            float z, omz; fsig(arg, z, omz);
            run *= omz;
        }
        __syncthreads();    // xs reuse hazard vs next chunk's fill
    }
    for (c = c+1; c<NC_; c++) {
        int cc = dir ? (NC_-1-c) : c;
        g_Ae[dir][b][cc][h] = 0.f;                  // run==0 for all h here
    }
}

// ---------------- scan pass C1: chunk local sums (R6) ----------------------
__global__ void k_scanC1() {
    int c = blockIdx.x, b = blockIdx.y, dir = blockIdx.z;
    int h = threadIdx.x;
    __shared__ float xs[CH_][IN_];
    float A = g_Ae[dir][b][c][h];
    if (!__syncthreads_or(A != 0.f)) { g_Lc[dir][b][c][h] = 0.f; return; }
    const float* xcb = g_xc + ((size_t)b*L_ + (size_t)c*CH_)*IN_;
    for (int i=h; i<CH_*IN_; i+=H_) ((float*)xs)[i] = xcb[i];
    float wz[IN_], wh[IN_]; float bz, bh;
    int pz = dir*2, ph = dir*2+1;
    #pragma unroll
    for (int i=0;i<IN_;i++) { wz[i]=g_W[pz][h][i]; wh[i]=g_W[ph][h][i]; }
    bz = g_bias[pz][h]; bh = g_bias[ph][h];
    __syncthreads();
    float Ls = 0.0f;
    int s0  = (dir==0)? 0 : CH_-1;
    int ds  = (dir==0)? 1 : -1;
    #pragma unroll 4
    for (int k=0;k<CH_;k++) {
        int s = s0 + k*ds;
        float az = bz, ah = bh;
        #pragma unroll
        for (int i=0;i<IN_;i++) { float xv = xs[s][i]; az += xv*wz[i]; ah += xv*wh[i]; }
        float z, omz; fsig(az, z, omz);
        A *= omz;
        Ls += __fdividef(z*ah, fmaxf(A, 1e-12f));
    }
    g_Lc[dir][b][c][h] = Ls;
}

// ---------------- scan pass B2: chunk-entry cumsum states (R6) -------------
__global__ void k_scanB2() {
    int b = blockIdx.x, dir = blockIdx.y, h = threadIdx.x;
    float run = 0.0f;
    if (dir==0) { for (int c=0;c<NC_;c++)    { g_Se[0][b][c][h]=run; run += g_Lc[0][b][c][h]; } }
    else        { for (int c=NC_-1;c>=0;c--) { g_Se[1][b][c][h]=run; run += g_Lc[1][b][c][h]; } }
}

// ---------------- scan pass C2: emit h = A*S (R6) --------------------------
__global__ void k_scanC2() {
    int c = blockIdx.x, b = blockIdx.y, dir = blockIdx.z;
    int h = threadIdx.x;
    __shared__ float xs[CH_][IN_];
    float A = g_Ae[dir][b][c][h];
    if (!__syncthreads_or(A != 0.f)) return;    // region stays exact 0
    const float* xcb = g_xc + ((size_t)b*L_ + (size_t)c*CH_)*IN_;
    for (int i=h; i<CH_*IN_; i+=H_) ((float*)xs)[i] = xcb[i];
    float wz[IN_], wh[IN_]; float bz, bh;
    int pz = dir*2, ph = dir*2+1;
    #pragma unroll
    for (int i=0;i<IN_;i++) { wz[i]=g_W[pz][h][i]; wh[i]=g_W[ph][h][i]; }
    bz = g_bias[pz][h]; bh = g_bias[ph][h];
    float S = g_Se[dir][b][c][h];
    __syncthreads();
    int s0  = (dir==0)? 0 : CH_-1;
    int ds  = (dir==0)? 1 : -1;
    size_t fofs = (dir==0)? (size_t)h : (size_t)(H_ + h);
    int zstep = 0;
    #pragma unroll 4
    for (int k=0;k<CH_;k++) {
        int s = s0 + k*ds;
        int l = c*CH_ + s;
        if (A != 0.f) zstep = k+1;              // predicated select, no branch
        g_F[((size_t)(b*L_ + l))*KP + fofs] = A*S;   // state BEFORE consuming l
        float az = bz, ah = bh;
        #pragma unroll
        for (int i=0;i<IN_;i++) { float xv = xs[s][i]; az += xv*wz[i]; ah += xv*wh[i]; }
        float z, omz; fsig(az, z, omz);
        A *= omz;
        S += __fdividef(z*ah, fmaxf(A, 1e-12f));
    }
    // tile flags: fwd writes ascending from chunk start; bwd descending from end
    int tile0 = (b*L_ + c*CH_) >> 6;
    #pragma unroll
    for (int ti=0; ti<4; ti++) {
        int thr = (dir==0) ? ti*64 : (192 - ti*64);
        int ta = __syncthreads_or(zstep > thr);
        if (ta && h == 0) atomicOr(&g_tilef[tile0 + ti], 1 << dir);
    }
}

// ---------------- fp16 mma GEMM (R6, contiguous live range) ----------------
#define GBM 64
__global__ __launch_bounds__(512, 1) void k_gemm3(const float* __restrict__ w2,
                                                  const float* __restrict__ b2p,
                                                  float* __restrict__ out) {
    __shared__ float s_s[HH_], s_c[HH_], s_w2[HH_];
    __shared__ float s_sum[GBM], s_sq[GBM];
    __shared__ float s_mu[GBM], s_rs[GBM];
    __shared__ float s_part[GBM][4];

    int t = threadIdx.x;
    int lane = t & 31, warp = t >> 5;
    int wm = warp >> 2, wn = warp & 3;      // 4m x 4n warp grid
    int g  = lane >> 2, tig = lane & 3;
    int row0 = blockIdx.x * GBM;
    int r0 = row0 + wm*16 + g;

    if (t < HH_) { s_s[t] = g_sv[t]; s_c[t] = g_cv[t]; s_w2[t] = w2[t]; }

    int flag = g_tilef[blockIdx.x] & 3;
    int c0 = (flag & 1) ? 0 : 32;           // contiguous live chunk range start
    int n  = (flag == 3) ? 64 : (flag ? 32 : 0);
    int total = n + 1;                      // + te chunk (64)

    float acc[8][4];
    #pragma unroll
    for (int i=0;i<8;i++) { acc[i][0]=0.f; acc[i][1]=0.f; acc[i][2]=0.f; acc[i][3]=0.f; }

    const float* Ar0 = g_F + (size_t)r0*KP     + tig*2;
    const float* Ar8 = Ar0 + 8*KP;
    const uint2* Bp  = ((const uint2*)g_Gh) + ((size_t)wn*8)*32 + lane;

    int ci = (0 < n) ? c0 : 64;
    float2 fA0 = __ldg((const float2*)(Ar0 + ci*16));
    float2 fA1 = __ldg((const float2*)(Ar8 + ci*16));
    float2 fA2 = __ldg((const float2*)(Ar0 + ci*16 + 8));
    float2 fA3 = __ldg((const float2*)(Ar8 + ci*16 + 8));
    uint2 fB[8];
    {
        const uint2* Bn = Bp + (size_t)ci*1024;
        #pragma unroll
        for (int nt=0; nt<8; nt++) fB[nt] = __ldg(Bn + nt*32);
    }

    float ps0=0.f, pq0=0.f, ps1=0.f, pq1=0.f;

    for (int it=0; it<total; it++) {
        if (wn == 0) {
            ps0 += fA0.x+fA0.y+fA2.x+fA2.y;
            pq0 += fA0.x*fA0.x + fA0.y*fA0.y + fA2.x*fA2.x + fA2.y*fA2.y;
            ps1 += fA1.x+fA1.y+fA3.x+fA3.y;
            pq1 += fA1.x*fA1.x + fA1.y*fA1.y + fA3.x*fA3.x + fA3.y*fA3.y;
        }
        __half2 h0 = __floats2half2_rn(fA0.x, fA0.y);
        __half2 h1 = __floats2half2_rn(fA1.x, fA1.y);
        __half2 h2 = __floats2half2_rn(fA2.x, fA2.y);
        __half2 h3 = __floats2half2_rn(fA3.x, fA3.y);
        uint32_t a0 = *reinterpret_cast<uint32_t*>(&h0);
        uint32_t a1 = *reinterpret_cast<uint32_t*>(&h1);
        uint32_t a2 = *reinterpret_cast<uint32_t*>(&h2);
        uint32_t a3 = *reinterpret_cast<uint32_t*>(&h3);
        #pragma unroll
        for (int nt=0; nt<8; nt++) {
            asm volatile(
                "mma.sync.aligned.m16n8k16.row.col.f32.f16.f16.f32 "
                "{%0,%1,%2,%3}, {%4,%5,%6,%7}, {%8,%9}, {%0,%1,%2,%3};"
                : "+f"(acc[nt][0]), "+f"(acc[nt][1]), "+f"(acc[nt][2]), "+f"(acc[nt][3])
                : "r"(a0), "r"(a1), "r"(a2), "r"(a3), "r"(fB[nt].x), "r"(fB[nt].y));
        }
        if (it+1 < total) {
            int itn = it+1;
            ci = (itn < n) ? (c0 + itn) : 64;   // branchless select
            fA0 = __ldg((const float2*)(Ar0 + ci*16));
            fA1 = __ldg((const float2*)(Ar8 + ci*16));
            fA2 = __ldg((const float2*)(Ar0 + ci*16 + 8));
            fA3 = __ldg((const float2*)(Ar8 + ci*16 + 8));
            const uint2* Bn = Bp + (size_t)ci*1024;
            #pragma unroll
            for (int nt=0; nt<8; nt++) fB[nt] = __ldg(Bn + nt*32);
        }
    }

    if (wn == 0) {
        #pragma unroll
        for (int off=1; off<4; off<<=1) {
            ps0 += __shfl_xor_sync(0xffffffffu, ps0, off);
            pq0 += __shfl_xor_sync(0xffffffffu, pq0, off);
            ps1 += __shfl_xor_sync(0xffffffffu, ps1, off);
            pq1 += __shfl_xor_sync(0xffffffffu, pq1, off);
        }
        if (tig == 0) {
            s_sum[wm*16+g]   = ps0;  s_sq[wm*16+g]   = pq0;
            s_sum[wm*16+g+8] = ps1;  s_sq[wm*16+g+8] = pq1;
        }
    }
    __syncthreads();
    if (t < GBM) {
        float m = s_sum[t] * (1.0f/(float)OUT_);
        float v = s_sq[t]  * (1.0f/(float)OUT_) - m*m;
        s_mu[t] = m;
        s_rs[t] = rsqrtf(v + EPS_);
    }
    __syncthreads();

    float mu0 = s_mu[wm*16+g],   rs0 = s_rs[wm*16+g];
    float mu1 = s_mu[wm*16+g+8], rs1 = s_rs[wm*16+g+8];
    float po0 = 0.f, po1 = 0.f;
    #pragma unroll
    for (int nt=0; nt<8; nt++) {
        #pragma unroll
        for (int e=0; e<2; e++) {
            int col = wn*64 + nt*8 + tig*2 + e;
            float sS = s_s[col], sC = s_c[col], wv = s_w2[col];
            float v0 = (acc[nt][e]   - mu0*sS)*rs0 + sC;
            float v1 = (acc[nt][2+e] - mu1*sS)*rs1 + sC;
            float h0 = 0.5f*v0*(1.0f + erff(v0*0.70710678118654752440f));
            float h1 = 0.5f*v1*(1.0f + erff(v1*0.70710678118654752440f));
            po0 += h0*wv;
            po1 += h1*wv;
        }
    }
    #pragma unroll
    for (int off=1; off<4; off<<=1) {
        po0 += __shfl_xor_sync(0xffffffffu, po0, off);
        po1 += __shfl_xor_sync(0xffffffffu, po1, off);
    }
    if (tig == 0) {
        s_part[wm*16+g][wn]   = po0;
        s_part[wm*16+g+8][wn] = po1;
    }
    __syncthreads();
    if (t < GBM) {
        out[row0 + t] = b2p[0] + s_part[t][0] + s_part[t][1] + s_part[t][2] + s_part[t][3];
    }
}

// ---------------- launch ---------------------------------------------------
extern "C" void kernel_launch(void* const* d_in, const int* in_sizes, int n_in,
                              void* d_out, int out_size) {
    const float* x      = (const float*)d_in[0];
    const float* t      = (const float*)d_in[1];
    const float* te_w1  = (const float*)d_in[2];
    const float* te_b1  = (const float*)d_in[3];
    const float* te_w2  = (const float*)d_in[4];
    const float* te_b2  = (const float*)d_in[5];
    const float* fproj_w= (const float*)d_in[6];
    const float* fproj_b= (const float*)d_in[7];
    const float* bproj_w= (const float*)d_in[8];
    const float* bproj_b= (const float*)d_in[9];
    const float* fz_w   = (const float*)d_in[10];
    const float* fz_b   = (const float*)d_in[11];
    const float* fh_w   = (const float*)d_in[12];
    const float* fh_b   = (const float*)d_in[13];
    const float* bz_w   = (const float*)d_in[14];
    const float* bz_b   = (const float*)d_in[15];
    const float* bh_w   = (const float*)d_in[16];
    const float* bh_b   = (const float*)d_in[17];
    const float* ln_g   = (const float*)d_in[18];
    const float* ln_b   = (const float*)d_in[19];
    const float* tsc    = (const float*)d_in[20];
    const float* gh_w1  = (const float*)d_in[21];
    const float* gh_b1  = (const float*)d_in[22];
    const float* gh_w2  = (const float*)d_in[23];
    const float* gh_b2  = (const float*)d_in[24];
    float* out = (float*)d_out;

    k_zero<<<(4*H_*IN_ + 255)/256, 256>>>();
    k_fold<<<dim3(4, 16), H_>>>(fz_w, fh_w, bz_w, bh_w, fz_b, fh_b, bz_b, bh_b,
                                fproj_w, fproj_b, bproj_w, bproj_b);
    k_prepG<<<24, HH_>>>(gh_w1, gh_b1, ln_g, ln_b, tsc);
    k_te<<<NROW/256, 256>>>(x, t, te_w1, te_b1, te_w2, te_b2);
    k_scanAB1<<<dim3(B_, 2), H_>>>();
    k_scanC1<<<dim3(NC_, B_, 2), H_>>>();
    k_scanB2<<<dim3(B_, 2), H_>>>();
    k_scanC2<<<dim3(NC_, B_, 2), H_>>>();
    k_gemm3<<<NROW/GBM, 512>>>(gh_w2, gh_b2, out);
}

// round 11
// speedup vs baseline: 3.2332x; 2.8244x over previous
#include <cuda_runtime.h>
#include <cuda_fp16.h>
#include <math.h>
#include <stdint.h>

#define B_  16
#define L_  4096
#define H_  512
#define NT_ 8
#define IN_ 10
#define OUT_ 1032
#define KP   1056            // padded K (66 chunks of 16)
#define NCH16 66
#define HH_ 256
#define NC_ 16
#define CH_ 256
#define EPS_ 1e-5f
#define NROW (B_*L_)
#define NTILE (NROW/64)

// ---------------- device scratch (static, allocation-free) ----------------
__device__ float g_xc[NROW*IN_];
__device__ float g_F [(size_t)NROW*KP];             // features (dead regions stay 0)
__device__ float g_W [4][H_][IN_];
__device__ float g_bias[4][H_];
__device__ float g_P [2][B_][NC_][H_];              // chunk a-products
__device__ float g_Ae[2][B_][NC_][H_];              // chunk-entry cumprod states
__device__ float g_Lc[2][B_][NC_][H_];
__device__ float g_Se[2][B_][NC_][H_];
__device__ __half g_Gh[(size_t)NCH16*32*128];       // B fp16 fragment-major (pads 0)
__device__ float g_sv[HH_];
__device__ float g_cv[HH_];
__device__ int   g_tilef[NTILE];                    // per-64-row-tile nonzero flags

// ---------------- zero accumulators / flags --------------------------------
__global__ void k_zero() {
    int i = blockIdx.x*blockDim.x + threadIdx.x;
    if (i < 4*H_*IN_) ((float*)g_W)[i] = 0.f;
    if (i < 4*H_)     ((float*)g_bias)[i] = 0.f;
    if (i < HH_)      { g_sv[i] = 0.f; g_cv[i] = 0.f; }
    if (i < NTILE)    g_tilef[i] = 0;
}

// ---------------- fold gate weights through the 10-dim projection ----------
__global__ void k_fold(const float* __restrict__ fz, const float* __restrict__ fh,
                       const float* __restrict__ bz, const float* __restrict__ bh,
                       const float* __restrict__ fzb, const float* __restrict__ fhb,
                       const float* __restrict__ bzb, const float* __restrict__ bhb,
                       const float* __restrict__ fp, const float* __restrict__ fpb,
                       const float* __restrict__ bp, const float* __restrict__ bpb) {
    int p = blockIdx.x, sl = blockIdx.y;   // 16 slices of 32 rows
    int h = threadIdx.x;
    const float* zw = (p==0)?fz:(p==1)?fh:(p==2)?bz:bh;
    const float* zb = (p==0)?fzb:(p==1)?fhb:(p==2)?bzb:bhb;
    const float* pw = (p<2)?fp:bp;
    const float* pb = (p<2)?fpb:bpb;
    float acc[IN_]; float ab = 0.f;
    #pragma unroll
    for (int i=0;i<IN_;i++) acc[i]=0.f;
    for (int d=sl*32; d<sl*32+32; d++) {
        float w = zw[h*H_+d];
        #pragma unroll
        for (int i=0;i<IN_;i++) acc[i] += w*pw[d*IN_+i];
        ab += w*pb[d];
    }
    #pragma unroll
    for (int i=0;i<IN_;i++) atomicAdd(&g_W[p][h][i], acc[i]);
    atomicAdd(&g_bias[p][h], ab + ((sl==0)? zb[h] : 0.f));
}

// ---------------- fold LN affine into gh_w1, emit fp16 fragment-major B ----
__global__ void k_prepG(const float* __restrict__ gw1, const float* __restrict__ gb1,
                        const float* __restrict__ lng, const float* __restrict__ lnb,
                        const float* __restrict__ tscp) {
    int k = threadIdx.x;                 // output col n, 0..255
    int j0 = blockIdx.x * 43;            // 24 blocks x 43 = 1032
    float tsc = tscp[0];
    int nt = k >> 3, ng = k & 7;
    float s = 0.f, c = 0.f;
    for (int j=j0; j<j0+43; j++) {
        float sc = (j >= OUT_-NT_) ? tsc : 1.0f;
        float w  = gw1[k*OUT_+j];
        __half Gh = __float2half_rn(lng[j]*sc*w);
        int kt = j >> 4, kin = j & 15;
        int lane = ng*4 + ((kin & 7) >> 1);
        int reg = kin >> 3, hs = kin & 1;
        g_Gh[(((size_t)(kt*32 + nt)*32 + lane)*2 + reg)*2 + hs] = Gh;
        s += __half2float(Gh);
        c += lnb[j]*sc*w;
    }
    atomicAdd(&g_sv[k], s);
    atomicAdd(&g_cv[k], c + ((blockIdx.x==0)? gb1[k] : 0.f));
}

// ---------------- time embedding + xc, te into F ---------------------------
__global__ void k_te(const float* __restrict__ x, const float* __restrict__ t,
                     const float* __restrict__ w1, const float* __restrict__ b1,
                     const float* __restrict__ w2, const float* __restrict__ b2) {
    int row = blockIdx.x*blockDim.x + threadIdx.x;
    if (row >= NROW) return;
    int b = row / L_;
    float ts = t[row] - t[b*L_];
    float r[NT_];
    #pragma unroll
    for (int j=0;j<NT_;j++) r[j] = fmaxf(ts*w1[j] + b1[j], 0.0f);
    float te[NT_];
    #pragma unroll
    for (int k=0;k<NT_;k++) {
        float a = b2[k];
        #pragma unroll
        for (int j=0;j<NT_;j++) a += r[j]*w2[k*NT_+j];
        te[k] = a;
        g_xc[row*IN_+2+k] = a;
    }
    float* fte = g_F + (size_t)row*KP + (OUT_-NT_);
    *(float4*)(fte)     = make_float4(te[0], te[1], te[2], te[3]);
    *(float4*)(fte + 4) = make_float4(te[4], te[5], te[6], te[7]);
    g_xc[row*IN_+0] = x[row*2+0];
    g_xc[row*IN_+1] = x[row*2+1];
}

// fast sigmoid pieces
__device__ __forceinline__ void fsig(float arg, float& z, float& omz) {
    float e = __expf(-arg);
    z = __fdividef(1.0f, 1.0f + e);
    omz = e * z;
}

// ---------------- scan pass A: chunk-local a-products (dense, R6) ----------
__global__ void k_scanA() {
    int c = blockIdx.x, b = blockIdx.y, dir = blockIdx.z;
    int h = threadIdx.x;
    __shared__ float xs[CH_][IN_];
    const float* xcb = g_xc + ((size_t)b*L_ + (size_t)c*CH_)*IN_;
    for (int i=h; i<CH_*IN_; i+=H_) ((float*)xs)[i] = xcb[i];
    float wz[IN_]; float bz;
    int pz = dir*2;
    #pragma unroll
    for (int i=0;i<IN_;i++) wz[i] = g_W[pz][h][i];
    bz = g_bias[pz][h];
    __syncthreads();
    float A = 1.0f;
    int s0 = (dir==0)? 0 : CH_-1;
    int ds = (dir==0)? 1 : -1;
    #pragma unroll 4
    for (int k=0;k<CH_;k++) {
        int s = s0 + k*ds;
        float arg = bz;
        #pragma unroll
        for (int i=0;i<IN_;i++) arg += xs[s][i]*wz[i];
        float z, omz; fsig(arg, z, omz);
        A *= omz;
    }
    g_P[dir][b][c][h] = A;
}

// ---------------- scan pass B1: chunk-entry cumprod states (R6) ------------
__global__ void k_scanB1() {
    int b = blockIdx.x, dir = blockIdx.y, h = threadIdx.x;
    float run = 1.0f;
    if (dir==0) { for (int c=0;c<NC_;c++)    { g_Ae[0][b][c][h]=run; run *= g_P[0][b][c][h]; } }
    else        { for (int c=NC_-1;c>=0;c--) { g_Ae[1][b][c][h]=run; run *= g_P[1][b][c][h]; } }
}

// ---------------- scan pass C1: chunk local sums (R6 body + block skip) ----
__global__ void k_scanC1() {
    int c = blockIdx.x, b = blockIdx.y, dir = blockIdx.z;
    int h = threadIdx.x;
    __shared__ float xs[CH_][IN_];
    float A = g_Ae[dir][b][c][h];
    if (!__syncthreads_or(A != 0.f)) { g_Lc[dir][b][c][h] = 0.f; return; }
    const float* xcb = g_xc + ((size_t)b*L_ + (size_t)c*CH_)*IN_;
    for (int i=h; i<CH_*IN_; i+=H_) ((float*)xs)[i] = xcb[i];
    float wz[IN_], wh[IN_]; float bz, bh;
    int pz = dir*2, ph = dir*2+1;
    #pragma unroll
    for (int i=0;i<IN_;i++) { wz[i]=g_W[pz][h][i]; wh[i]=g_W[ph][h][i]; }
    bz = g_bias[pz][h]; bh = g_bias[ph][h];
    __syncthreads();
    float Ls = 0.0f;
    int s0  = (dir==0)? 0 : CH_-1;
    int ds  = (dir==0)? 1 : -1;
    #pragma unroll 4
    for (int k=0;k<CH_;k++) {
        int s = s0 + k*ds;
        float az = bz, ah = bh;
        #pragma unroll
        for (int i=0;i<IN_;i++) { float xv = xs[s][i]; az += xv*wz[i]; ah += xv*wh[i]; }
        float z, omz; fsig(az, z, omz);
        A *= omz;
        Ls += __fdividef(z*ah, fmaxf(A, 1e-12f));
    }
    g_Lc[dir][b][c][h] = Ls;
}

// ---------------- scan pass B2: chunk-entry cumsum states (R6) -------------
__global__ void k_scanB2() {
    int b = blockIdx.x, dir = blockIdx.y, h = threadIdx.x;
    float run = 0.0f;
    if (dir==0) { for (int c=0;c<NC_;c++)    { g_Se[0][b][c][h]=run; run += g_Lc[0][b][c][h]; } }
    else        { for (int c=NC_-1;c>=0;c--) { g_Se[1][b][c][h]=run; run += g_Lc[1][b][c][h]; } }
}

// ---------------- scan pass C2: emit h = A*S (R6) --------------------------
__global__ void k_scanC2() {
    int c = blockIdx.x, b = blockIdx.y, dir = blockIdx.z;
    int h = threadIdx.x;
    __shared__ float xs[CH_][IN_];
    float A = g_Ae[dir][b][c][h];
    if (!__syncthreads_or(A != 0.f)) return;    // region stays exact 0
    const float* xcb = g_xc + ((size_t)b*L_ + (size_t)c*CH_)*IN_;
    for (int i=h; i<CH_*IN_; i+=H_) ((float*)xs)[i] = xcb[i];
    float wz[IN_], wh[IN_]; float bz, bh;
    int pz = dir*2, ph = dir*2+1;
    #pragma unroll
    for (int i=0;i<IN_;i++) { wz[i]=g_W[pz][h][i]; wh[i]=g_W[ph][h][i]; }
    bz = g_bias[pz][h]; bh = g_bias[ph][h];
    float S = g_Se[dir][b][c][h];
    __syncthreads();
    int s0  = (dir==0)? 0 : CH_-1;
    int ds  = (dir==0)? 1 : -1;
    size_t fofs = (dir==0)? (size_t)h : (size_t)(H_ + h);
    int zstep = 0;
    #pragma unroll 4
    for (int k=0;k<CH_;k++) {
        int s = s0 + k*ds;
        int l = c*CH_ + s;
        if (A != 0.f) zstep = k+1;              // predicated select, no branch
        g_F[((size_t)(b*L_ + l))*KP + fofs] = A*S;   // state BEFORE consuming l
        float az = bz, ah = bh;
        #pragma unroll
        for (int i=0;i<IN_;i++) { float xv = xs[s][i]; az += xv*wz[i]; ah += xv*wh[i]; }
        float z, omz; fsig(az, z, omz);
        A *= omz;
        S += __fdividef(z*ah, fmaxf(A, 1e-12f));
    }
    // tile flags: fwd writes ascending from chunk start; bwd descending from end
    int tile0 = (b*L_ + c*CH_) >> 6;
    #pragma unroll
    for (int ti=0; ti<4; ti++) {
        int thr = (dir==0) ? ti*64 : (192 - ti*64);
        int ta = __syncthreads_or(zstep > thr);
        if (ta && h == 0) atomicOr(&g_tilef[tile0 + ti], 1 << dir);
    }
}

// ---------------- fp16 mma GEMM (R6, contiguous live range) ----------------
#define GBM 64
__global__ __launch_bounds__(512, 1) void k_gemm3(const float* __restrict__ w2,
                                                  const float* __restrict__ b2p,
                                                  float* __restrict__ out) {
    __shared__ float s_s[HH_], s_c[HH_], s_w2[HH_];
    __shared__ float s_sum[GBM], s_sq[GBM];
    __shared__ float s_mu[GBM], s_rs[GBM];
    __shared__ float s_part[GBM][4];

    int t = threadIdx.x;
    int lane = t & 31, warp = t >> 5;
    int wm = warp >> 2, wn = warp & 3;      // 4m x 4n warp grid
    int g  = lane >> 2, tig = lane & 3;
    int row0 = blockIdx.x * GBM;
    int r0 = row0 + wm*16 + g;

    if (t < HH_) { s_s[t] = g_sv[t]; s_c[t] = g_cv[t]; s_w2[t] = w2[t]; }

    int flag = g_tilef[blockIdx.x] & 3;
    int c0 = (flag & 1) ? 0 : 32;           // contiguous live chunk range start
    int n  = (flag == 3) ? 64 : (flag ? 32 : 0);
    int total = n + 1;                      // + te chunk (64)

    float acc[8][4];
    #pragma unroll
    for (int i=0;i<8;i++) { acc[i][0]=0.f; acc[i][1]=0.f; acc[i][2]=0.f; acc[i][3]=0.f; }

    const float* Ar0 = g_F + (size_t)r0*KP     + tig*2;
    const float* Ar8 = Ar0 + 8*KP;
    const uint2* Bp  = ((const uint2*)g_Gh) + ((size_t)wn*8)*32 + lane;

    int ci = (0 < n) ? c0 : 64;
    float2 fA0 = __ldg((const float2*)(Ar0 + ci*16));
    float2 fA1 = __ldg((const float2*)(Ar8 + ci*16));
    float2 fA2 = __ldg((const float2*)(Ar0 + ci*16 + 8));
    float2 fA3 = __ldg((const float2*)(Ar8 + ci*16 + 8));
    uint2 fB[8];
    {
        const uint2* Bn = Bp + (size_t)ci*1024;
        #pragma unroll
        for (int nt=0; nt<8; nt++) fB[nt] = __ldg(Bn + nt*32);
    }

    float ps0=0.f, pq0=0.f, ps1=0.f, pq1=0.f;

    for (int it=0; it<total; it++) {
        if (wn == 0) {
            ps0 += fA0.x+fA0.y+fA2.x+fA2.y;
            pq0 += fA0.x*fA0.x + fA0.y*fA0.y + fA2.x*fA2.x + fA2.y*fA2.y;
            ps1 += fA1.x+fA1.y+fA3.x+fA3.y;
            pq1 += fA1.x*fA1.x + fA1.y*fA1.y + fA3.x*fA3.x + fA3.y*fA3.y;
        }
        __half2 h0 = __floats2half2_rn(fA0.x, fA0.y);
        __half2 h1 = __floats2half2_rn(fA1.x, fA1.y);
        __half2 h2 = __floats2half2_rn(fA2.x, fA2.y);
        __half2 h3 = __floats2half2_rn(fA3.x, fA3.y);
        uint32_t a0 = *reinterpret_cast<uint32_t*>(&h0);
        uint32_t a1 = *reinterpret_cast<uint32_t*>(&h1);
        uint32_t a2 = *reinterpret_cast<uint32_t*>(&h2);
        uint32_t a3 = *reinterpret_cast<uint32_t*>(&h3);
        #pragma unroll
        for (int nt=0; nt<8; nt++) {
            asm volatile(
                "mma.sync.aligned.m16n8k16.row.col.f32.f16.f16.f32 "
                "{%0,%1,%2,%3}, {%4,%5,%6,%7}, {%8,%9}, {%0,%1,%2,%3};"
                : "+f"(acc[nt][0]), "+f"(acc[nt][1]), "+f"(acc[nt][2]), "+f"(acc[nt][3])
                : "r"(a0), "r"(a1), "r"(a2), "r"(a3), "r"(fB[nt].x), "r"(fB[nt].y));
        }
        if (it+1 < total) {
            int itn = it+1;
            ci = (itn < n) ? (c0 + itn) : 64;   // branchless select
            fA0 = __ldg((const float2*)(Ar0 + ci*16));
            fA1 = __ldg((const float2*)(Ar8 + ci*16));
            fA2 = __ldg((const float2*)(Ar0 + ci*16 + 8));
            fA3 = __ldg((const float2*)(Ar8 + ci*16 + 8));
            const uint2* Bn = Bp + (size_t)ci*1024;
            #pragma unroll
            for (int nt=0; nt<8; nt++) fB[nt] = __ldg(Bn + nt*32);
        }
    }

    if (wn == 0) {
        #pragma unroll
        for (int off=1; off<4; off<<=1) {
            ps0 += __shfl_xor_sync(0xffffffffu, ps0, off);
            pq0 += __shfl_xor_sync(0xffffffffu, pq0, off);
            ps1 += __shfl_xor_sync(0xffffffffu, ps1, off);
            pq1 += __shfl_xor_sync(0xffffffffu, pq1, off);
        }
        if (tig == 0) {
            s_sum[wm*16+g]   = ps0;  s_sq[wm*16+g]   = pq0;
            s_sum[wm*16+g+8] = ps1;  s_sq[wm*16+g+8] = pq1;
        }
    }
    __syncthreads();
    if (t < GBM) {
        float m = s_sum[t] * (1.0f/(float)OUT_);
        float v = s_sq[t]  * (1.0f/(float)OUT_) - m*m;
        s_mu[t] = m;
        s_rs[t] = rsqrtf(v + EPS_);
    }
    __syncthreads();

    float mu0 = s_mu[wm*16+g],   rs0 = s_rs[wm*16+g];
    float mu1 = s_mu[wm*16+g+8], rs1 = s_rs[wm*16+g+8];
    float po0 = 0.f, po1 = 0.f;
    #pragma unroll
    for (int nt=0; nt<8; nt++) {
        #pragma unroll
        for (int e=0; e<2; e++) {
            int col = wn*64 + nt*8 + tig*2 + e;
            float sS = s_s[col], sC = s_c[col], wv = s_w2[col];
            float v0 = (acc[nt][e]   - mu0*sS)*rs0 + sC;
            float v1 = (acc[nt][2+e] - mu1*sS)*rs1 + sC;
            float h0 = 0.5f*v0*(1.0f + erff(v0*0.70710678118654752440f));
            float h1 = 0.5f*v1*(1.0f + erff(v1*0.70710678118654752440f));
            po0 += h0*wv;
            po1 += h1*wv;
        }
    }
    #pragma unroll
    for (int off=1; off<4; off<<=1) {
        po0 += __shfl_xor_sync(0xffffffffu, po0, off);
        po1 += __shfl_xor_sync(0xffffffffu, po1, off);
    }
    if (tig == 0) {
        s_part[wm*16+g][wn]   = po0;
        s_part[wm*16+g+8][wn] = po1;
    }
    __syncthreads();
    if (t < GBM) {
        out[row0 + t] = b2p[0] + s_part[t][0] + s_part[t][1] + s_part[t][2] + s_part[t][3];
    }
}

// ---------------- launch ---------------------------------------------------
extern "C" void kernel_launch(void* const* d_in, const int* in_sizes, int n_in,
                              void* d_out, int out_size) {
    const float* x      = (const float*)d_in[0];
    const float* t      = (const float*)d_in[1];
    const float* te_w1  = (const float*)d_in[2];
    const float* te_b1  = (const float*)d_in[3];
    const float* te_w2  = (const float*)d_in[4];
    const float* te_b2  = (const float*)d_in[5];
    const float* fproj_w= (const float*)d_in[6];
    const float* fproj_b= (const float*)d_in[7];
    const float* bproj_w= (const float*)d_in[8];
    const float* bproj_b= (const float*)d_in[9];
    const float* fz_w   = (const float*)d_in[10];
    const float* fz_b   = (const float*)d_in[11];
    const float* fh_w   = (const float*)d_in[12];
    const float* fh_b   = (const float*)d_in[13];
    const float* bz_w   = (const float*)d_in[14];
    const float* bz_b   = (const float*)d_in[15];
    const float* bh_w   = (const float*)d_in[16];
    const float* bh_b   = (const float*)d_in[17];
    const float* ln_g   = (const float*)d_in[18];
    const float* ln_b   = (const float*)d_in[19];
    const float* tsc    = (const float*)d_in[20];
    const float* gh_w1  = (const float*)d_in[21];
    const float* gh_b1  = (const float*)d_in[22];
    const float* gh_w2  = (const float*)d_in[23];
    const float* gh_b2  = (const float*)d_in[24];
    float* out = (float*)d_out;

    k_zero<<<(4*H_*IN_ + 255)/256, 256>>>();
    k_fold<<<dim3(4, 16), H_>>>(fz_w, fh_w, bz_w, bh_w, fz_b, fh_b, bz_b, bh_b,
                                fproj_w, fproj_b, bproj_w, bproj_b);
    k_prepG<<<24, HH_>>>(gh_w1, gh_b1, ln_g, ln_b, tsc);
    k_te<<<NROW/256, 256>>>(x, t, te_w1, te_b1, te_w2, te_b2);
    k_scanA <<<dim3(NC_, B_, 2), H_>>>();
    k_scanB1<<<dim3(B_, 2), H_>>>();
    k_scanC1<<<dim3(NC_, B_, 2), H_>>>();
    k_scanB2<<<dim3(B_, 2), H_>>>();
    k_scanC2<<<dim3(NC_, B_, 2), H_>>>();
    k_gemm3<<<NROW/GBM, 512>>>(gh_w2, gh_b2, out);
}

// round 12
// speedup vs baseline: 3.2613x; 1.0087x over previous
#include <cuda_runtime.h>
#include <cuda_fp16.h>
#include <math.h>
#include <stdint.h>

#define B_  16
#define L_  4096
#define H_  512
#define NT_ 8
#define IN_ 10
#define INP 12               // padded xc stride (48B rows -> LDS.128)
#define OUT_ 1032
#define KP   1056            // padded K (66 chunks of 16)
#define NCH16 66
#define HH_ 256
#define NC_ 16
#define CH_ 256
#define EPS_ 1e-5f
#define NROW (B_*L_)
#define NTILE (NROW/64)

// ---------------- device scratch (static, allocation-free) ----------------
__device__ float g_xc[(size_t)NROW*INP];            // pads [10],[11] stay 0
__device__ float g_F [(size_t)NROW*KP];             // features (dead regions stay 0)
__device__ float g_W [4][H_][IN_];
__device__ float g_bias[4][H_];
__device__ float g_P [2][B_][NC_][H_];              // chunk a-products
__device__ float g_Ae[2][B_][NC_][H_];              // chunk-entry cumprod states
__device__ float g_Lc[2][B_][NC_][H_];
__device__ float g_Se[2][B_][NC_][H_];
__device__ __half g_Gh[(size_t)NCH16*32*128];       // B fp16 fragment-major (pads 0)
__device__ float g_sv[HH_];
__device__ float g_cv[HH_];
__device__ int   g_tilef[NTILE];                    // per-64-row-tile nonzero flags

// ---------------- zero accumulators / flags --------------------------------
__global__ void k_zero() {
    int i = blockIdx.x*blockDim.x + threadIdx.x;
    if (i < 4*H_*IN_) ((float*)g_W)[i] = 0.f;
    if (i < 4*H_)     ((float*)g_bias)[i] = 0.f;
    if (i < HH_)      { g_sv[i] = 0.f; g_cv[i] = 0.f; }
    if (i < NTILE)    g_tilef[i] = 0;
}

// ---------------- fold gate weights through the 10-dim projection ----------
__global__ void k_fold(const float* __restrict__ fz, const float* __restrict__ fh,
                       const float* __restrict__ bz, const float* __restrict__ bh,
                       const float* __restrict__ fzb, const float* __restrict__ fhb,
                       const float* __restrict__ bzb, const float* __restrict__ bhb,
                       const float* __restrict__ fp, const float* __restrict__ fpb,
                       const float* __restrict__ bp, const float* __restrict__ bpb) {
    int p = blockIdx.x, sl = blockIdx.y;   // 16 slices of 32 rows
    int h = threadIdx.x;
    const float* zw = (p==0)?fz:(p==1)?fh:(p==2)?bz:bh;
    const float* zb = (p==0)?fzb:(p==1)?fhb:(p==2)?bzb:bhb;
    const float* pw = (p<2)?fp:bp;
    const float* pb = (p<2)?fpb:bpb;
    float acc[IN_]; float ab = 0.f;
    #pragma unroll
    for (int i=0;i<IN_;i++) acc[i]=0.f;
    for (int d=sl*32; d<sl*32+32; d++) {
        float w = zw[h*H_+d];
        #pragma unroll
        for (int i=0;i<IN_;i++) acc[i] += w*pw[d*IN_+i];
        ab += w*pb[d];
    }
    #pragma unroll
    for (int i=0;i<IN_;i++) atomicAdd(&g_W[p][h][i], acc[i]);
    atomicAdd(&g_bias[p][h], ab + ((sl==0)? zb[h] : 0.f));
}

// ---------------- fold LN affine into gh_w1, emit fp16 fragment-major B ----
__global__ void k_prepG(const float* __restrict__ gw1, const float* __restrict__ gb1,
                        const float* __restrict__ lng, const float* __restrict__ lnb,
                        const float* __restrict__ tscp) {
    int k = threadIdx.x;                 // output col n, 0..255
    int j0 = blockIdx.x * 43;            // 24 blocks x 43 = 1032
    float tsc = tscp[0];
    int nt = k >> 3, ng = k & 7;
    float s = 0.f, c = 0.f;
    for (int j=j0; j<j0+43; j++) {
        float sc = (j >= OUT_-NT_) ? tsc : 1.0f;
        float w  = gw1[k*OUT_+j];
        __half Gh = __float2half_rn(lng[j]*sc*w);
        int kt = j >> 4, kin = j & 15;
        int lane = ng*4 + ((kin & 7) >> 1);
        int reg = kin >> 3, hs = kin & 1;
        g_Gh[(((size_t)(kt*32 + nt)*32 + lane)*2 + reg)*2 + hs] = Gh;
        s += __half2float(Gh);
        c += lnb[j]*sc*w;
    }
    atomicAdd(&g_sv[k], s);
    atomicAdd(&g_cv[k], c + ((blockIdx.x==0)? gb1[k] : 0.f));
}

// ---------------- time embedding + xc, te into F ---------------------------
__global__ void k_te(const float* __restrict__ x, const float* __restrict__ t,
                     const float* __restrict__ w1, const float* __restrict__ b1,
                     const float* __restrict__ w2, const float* __restrict__ b2) {
    int row = blockIdx.x*blockDim.x + threadIdx.x;
    if (row >= NROW) return;
    int b = row / L_;
    float ts = t[row] - t[b*L_];
    float r[NT_];
    #pragma unroll
    for (int j=0;j<NT_;j++) r[j] = fmaxf(ts*w1[j] + b1[j], 0.0f);
    float te[NT_];
    #pragma unroll
    for (int k=0;k<NT_;k++) {
        float a = b2[k];
        #pragma unroll
        for (int j=0;j<NT_;j++) a += r[j]*w2[k*NT_+j];
        te[k] = a;
    }
    float x0 = x[row*2+0], x1 = x[row*2+1];
    float* xr = g_xc + (size_t)row*INP;
    *(float4*)(xr+0) = make_float4(x0, x1, te[0], te[1]);
    *(float4*)(xr+4) = make_float4(te[2], te[3], te[4], te[5]);
    *(float4*)(xr+8) = make_float4(te[6], te[7], 0.f, 0.f);
    float* fte = g_F + (size_t)row*KP + (OUT_-NT_);
    *(float4*)(fte)     = make_float4(te[0], te[1], te[2], te[3]);
    *(float4*)(fte + 4) = make_float4(te[4], te[5], te[6], te[7]);
}

// fast sigmoid pieces
__device__ __forceinline__ void fsig(float arg, float& z, float& omz) {
    float e = __expf(-arg);
    z = __fdividef(1.0f, 1.0f + e);
    omz = e * z;
}

// vectorized dot-10 against padded 48B row (order identical to scalar loop)
__device__ __forceinline__ float dot10(const float* xr, const float* w, float b) {
    float4 v0 = *(const float4*)(xr);
    float4 v1 = *(const float4*)(xr+4);
    float2 v2 = *(const float2*)(xr+8);
    float a = b;
    a += v0.x*w[0]; a += v0.y*w[1]; a += v0.z*w[2]; a += v0.w*w[3];
    a += v1.x*w[4]; a += v1.y*w[5]; a += v1.z*w[6]; a += v1.w*w[7];
    a += v2.x*w[8]; a += v2.y*w[9];
    return a;
}
__device__ __forceinline__ void dot10x2(const float* xr, const float* wz, float bz,
                                        const float* wh, float bh, float& az, float& ah) {
    float4 v0 = *(const float4*)(xr);
    float4 v1 = *(const float4*)(xr+4);
    float2 v2 = *(const float2*)(xr+8);
    float a = bz, c = bh;
    a += v0.x*wz[0]; a += v0.y*wz[1]; a += v0.z*wz[2]; a += v0.w*wz[3];
    a += v1.x*wz[4]; a += v1.y*wz[5]; a += v1.z*wz[6]; a += v1.w*wz[7];
    a += v2.x*wz[8]; a += v2.y*wz[9];
    c += v0.x*wh[0]; c += v0.y*wh[1]; c += v0.z*wh[2]; c += v0.w*wh[3];
    c += v1.x*wh[4]; c += v1.y*wh[5]; c += v1.z*wh[6]; c += v1.w*wh[7];
    c += v2.x*wh[8]; c += v2.y*wh[9];
    az = a; ah = c;
}

// ---------------- scan pass A: chunk-local a-products ----------------------
__global__ void k_scanA() {
    int c = blockIdx.x, b = blockIdx.y, dir = blockIdx.z;
    int h = threadIdx.x;
    __shared__ float xs[CH_][INP];
    const float4* xc4 = (const float4*)(g_xc + ((size_t)b*L_ + (size_t)c*CH_)*INP);
    for (int i=h; i<CH_*3; i+=H_) ((float4*)xs)[i] = xc4[i];
    float wz[IN_]; float bz;
    int pz = dir*2;
    #pragma unroll
    for (int i=0;i<IN_;i++) wz[i] = g_W[pz][h][i];
    bz = g_bias[pz][h];
    __syncthreads();
    float A = 1.0f;
    int s0 = (dir==0)? 0 : CH_-1;
    int ds = (dir==0)? 1 : -1;
    #pragma unroll 4
    for (int k=0;k<CH_;k++) {
        int s = s0 + k*ds;
        float arg = dot10(&xs[s][0], wz, bz);
        float z, omz; fsig(arg, z, omz);
        A *= omz;
    }
    g_P[dir][b][c][h] = A;
}

// ---------------- scan pass B1: chunk-entry cumprod states -----------------
__global__ void k_scanB1() {
    int b = blockIdx.x, dir = blockIdx.y, h = threadIdx.x;
    float run = 1.0f;
    if (dir==0) { for (int c=0;c<NC_;c++)    { g_Ae[0][b][c][h]=run; run *= g_P[0][b][c][h]; } }
    else        { for (int c=NC_-1;c>=0;c--) { g_Ae[1][b][c][h]=run; run *= g_P[1][b][c][h]; } }
}

// ---------------- scan pass C1: chunk local sums (block skip) --------------
__global__ void k_scanC1() {
    int c = blockIdx.x, b = blockIdx.y, dir = blockIdx.z;
    int h = threadIdx.x;
    __shared__ float xs[CH_][INP];
    float A = g_Ae[dir][b][c][h];
    if (!__syncthreads_or(A != 0.f)) { g_Lc[dir][b][c][h] = 0.f; return; }
    const float4* xc4 = (const float4*)(g_xc + ((size_t)b*L_ + (size_t)c*CH_)*INP);
    for (int i=h; i<CH_*3; i+=H_) ((float4*)xs)[i] = xc4[i];
    float wz[IN_], wh[IN_]; float bz, bh;
    int pz = dir*2, ph = dir*2+1;
    #pragma unroll
    for (int i=0;i<IN_;i++) { wz[i]=g_W[pz][h][i]; wh[i]=g_W[ph][h][i]; }
    bz = g_bias[pz][h]; bh = g_bias[ph][h];
    __syncthreads();
    float Ls = 0.0f;
    int s0  = (dir==0)? 0 : CH_-1;
    int ds  = (dir==0)? 1 : -1;
    #pragma unroll 4
    for (int k=0;k<CH_;k++) {
        int s = s0 + k*ds;
        float az, ah;
        dot10x2(&xs[s][0], wz, bz, wh, bh, az, ah);
        float z, omz; fsig(az, z, omz);
        A *= omz;
        Ls += __fdividef(z*ah, fmaxf(A, 1e-12f));
    }
    g_Lc[dir][b][c][h] = Ls;
}

// ---------------- scan pass B2: chunk-entry cumsum states ------------------
__global__ void k_scanB2() {
    int b = blockIdx.x, dir = blockIdx.y, h = threadIdx.x;
    float run = 0.0f;
    if (dir==0) { for (int c=0;c<NC_;c++)    { g_Se[0][b][c][h]=run; run += g_Lc[0][b][c][h]; } }
    else        { for (int c=NC_-1;c>=0;c--) { g_Se[1][b][c][h]=run; run += g_Lc[1][b][c][h]; } }
}

// ---------------- scan pass C2: emit h = A*S -------------------------------
__global__ void k_scanC2() {
    int c = blockIdx.x, b = blockIdx.y, dir = blockIdx.z;
    int h = threadIdx.x;
    __shared__ float xs[CH_][INP];
    float A = g_Ae[dir][b][c][h];
    if (!__syncthreads_or(A != 0.f)) return;    // region stays exact 0
    const float4* xc4 = (const float4*)(g_xc + ((size_t)b*L_ + (size_t)c*CH_)*INP);
    for (int i=h; i<CH_*3; i+=H_) ((float4*)xs)[i] = xc4[i];
    float wz[IN_], wh[IN_]; float bz, bh;
    int pz = dir*2, ph = dir*2+1;
    #pragma unroll
    for (int i=0;i<IN_;i++) { wz[i]=g_W[pz][h][i]; wh[i]=g_W[ph][h][i]; }
    bz = g_bias[pz][h]; bh = g_bias[ph][h];
    float S = g_Se[dir][b][c][h];
    __syncthreads();
    int s0  = (dir==0)? 0 : CH_-1;
    int ds  = (dir==0)? 1 : -1;
    size_t fofs = (dir==0)? (size_t)h : (size_t)(H_ + h);
    int zstep = 0;
    #pragma unroll 4
    for (int k=0;k<CH_;k++) {
        int s = s0 + k*ds;
        int l = c*CH_ + s;
        if (A != 0.f) zstep = k+1;              // predicated select, no branch
        g_F[((size_t)(b*L_ + l))*KP + fofs] = A*S;   // state BEFORE consuming l
        float az, ah;
        dot10x2(&xs[s][0], wz, bz, wh, bh, az, ah);
        float z, omz; fsig(az, z, omz);
        A *= omz;
        S += __fdividef(z*ah, fmaxf(A, 1e-12f));
    }
    // tile flags: fwd writes ascending from chunk start; bwd descending from end
    int tile0 = (b*L_ + c*CH_) >> 6;
    #pragma unroll
    for (int ti=0; ti<4; ti++) {
        int thr = (dir==0) ? ti*64 : (192 - ti*64);
        int ta = __syncthreads_or(zstep > thr);
        if (ta && h == 0) atomicOr(&g_tilef[tile0 + ti], 1 << dir);
    }
}

// ---------------- fp16 mma GEMM (smem-staged B, contiguous live range) -----
#define GBM 64
__global__ __launch_bounds__(512, 1) void k_gemm3(const float* __restrict__ w2,
                                                  const float* __restrict__ b2p,
                                                  float* __restrict__ out) {
    __shared__ float s_s[HH_], s_c[HH_], s_w2[HH_];
    __shared__ float s_sum[GBM], s_sq[GBM];
    __shared__ float s_mu[GBM], s_rs[GBM];
    __shared__ float s_part[GBM][4];
    __shared__ uint2 sB[2][1024];               // double-buffered B chunk (8KB x2)

    int t = threadIdx.x;
    int lane = t & 31, warp = t >> 5;
    int wm = warp >> 2, wn = warp & 3;          // 4m x 4n warp grid
    int g  = lane >> 2, tig = lane & 3;
    int row0 = blockIdx.x * GBM;
    int r0 = row0 + wm*16 + g;

    if (t < HH_) { s_s[t] = g_sv[t]; s_c[t] = g_cv[t]; s_w2[t] = w2[t]; }

    int flag = g_tilef[blockIdx.x] & 3;
    int c0 = (flag & 1) ? 0 : 32;               // contiguous live chunk range start
    int n  = (flag == 3) ? 64 : (flag ? 32 : 0);
    int total = n + 1;                          // + te chunk (64)

    float acc[8][4];
    #pragma unroll
    for (int i=0;i<8;i++) { acc[i][0]=0.f; acc[i][1]=0.f; acc[i][2]=0.f; acc[i][3]=0.f; }

    const float* Ar0 = g_F + (size_t)r0*KP     + tig*2;
    const float* Ar8 = Ar0 + 8*KP;
    const uint2* Ghu2 = (const uint2*)g_Gh;

    int ci = (0 < n) ? c0 : 64;
    float2 fA0 = __ldg((const float2*)(Ar0 + ci*16));
    float2 fA1 = __ldg((const float2*)(Ar8 + ci*16));
    float2 fA2 = __ldg((const float2*)(Ar0 + ci*16 + 8));
    float2 fA3 = __ldg((const float2*)(Ar8 + ci*16 + 8));
    {
        const uint2* Bn = Ghu2 + (size_t)ci*1024;
        sB[0][t]       = __ldg(Bn + t);
        sB[0][t + 512] = __ldg(Bn + t + 512);
    }
    __syncthreads();

    float ps0=0.f, pq0=0.f, ps1=0.f, pq1=0.f;
    int cur = 0;

    for (int it=0; it<total; it++) {
        uint2 fB[8];
        #pragma unroll
        for (int nt=0; nt<8; nt++) fB[nt] = sB[cur][wn*256 + nt*32 + lane];
        if (wn == 0) {
            ps0 += fA0.x+fA0.y+fA2.x+fA2.y;
            pq0 += fA0.x*fA0.x + fA0.y*fA0.y + fA2.x*fA2.x + fA2.y*fA2.y;
            ps1 += fA1.x+fA1.y+fA3.x+fA3.y;
            pq1 += fA1.x*fA1.x + fA1.y*fA1.y + fA3.x*fA3.x + fA3.y*fA3.y;
        }
        __half2 h0 = __floats2half2_rn(fA0.x, fA0.y);
        __half2 h1 = __floats2half2_rn(fA1.x, fA1.y);
        __half2 h2 = __floats2half2_rn(fA2.x, fA2.y);
        __half2 h3 = __floats2half2_rn(fA3.x, fA3.y);
        uint32_t a0 = *reinterpret_cast<uint32_t*>(&h0);
        uint32_t a1 = *reinterpret_cast<uint32_t*>(&h1);
        uint32_t a2 = *reinterpret_cast<uint32_t*>(&h2);
        uint32_t a3 = *reinterpret_cast<uint32_t*>(&h3);
        #pragma unroll
        for (int nt=0; nt<8; nt++) {
            asm volatile(
                "mma.sync.aligned.m16n8k16.row.col.f32.f16.f16.f32 "
                "{%0,%1,%2,%3}, {%4,%5,%6,%7}, {%8,%9}, {%0,%1,%2,%3};"
                : "+f"(acc[nt][0]), "+f"(acc[nt][1]), "+f"(acc[nt][2]), "+f"(acc[nt][3])
                : "r"(a0), "r"(a1), "r"(a2), "r"(a3), "r"(fB[nt].x), "r"(fB[nt].y));
        }
        if (it+1 < total) {
            int itn = it+1;
            ci = (itn < n) ? (c0 + itn) : 64;   // branchless select
            const uint2* Bn = Ghu2 + (size_t)ci*1024;
            sB[cur^1][t]       = __ldg(Bn + t);
            sB[cur^1][t + 512] = __ldg(Bn + t + 512);
            fA0 = __ldg((const float2*)(Ar0 + ci*16));
            fA1 = __ldg((const float2*)(Ar8 + ci*16));
            fA2 = __ldg((const float2*)(Ar0 + ci*16 + 8));
            fA3 = __ldg((const float2*)(Ar8 + ci*16 + 8));
        }
        __syncthreads();
        cur ^= 1;
    }

    if (wn == 0) {
        #pragma unroll
        for (int off=1; off<4; off<<=1) {
            ps0 += __shfl_xor_sync(0xffffffffu, ps0, off);
            pq0 += __shfl_xor_sync(0xffffffffu, pq0, off);
            ps1 += __shfl_xor_sync(0xffffffffu, ps1, off);
            pq1 += __shfl_xor_sync(0xffffffffu, pq1, off);
        }
        if (tig == 0) {
            s_sum[wm*16+g]   = ps0;  s_sq[wm*16+g]   = pq0;
            s_sum[wm*16+g+8] = ps1;  s_sq[wm*16+g+8] = pq1;
        }
    }
    __syncthreads();
    if (t < GBM) {
        float m = s_sum[t] * (1.0f/(float)OUT_);
        float v = s_sq[t]  * (1.0f/(float)OUT_) - m*m;
        s_mu[t] = m;
        s_rs[t] = rsqrtf(v + EPS_);
    }
    __syncthreads();

    float mu0 = s_mu[wm*16+g],   rs0 = s_rs[wm*16+g];
    float mu1 = s_mu[wm*16+g+8], rs1 = s_rs[wm*16+g+8];
    float po0 = 0.f, po1 = 0.f;
    #pragma unroll
    for (int nt=0; nt<8; nt++) {
        #pragma unroll
        for (int e=0; e<2; e++) {
            int col = wn*64 + nt*8 + tig*2 + e;
            float sS = s_s[col], sC = s_c[col], wv = s_w2[col];
            float v0 = (acc[nt][e]   - mu0*sS)*rs0 + sC;
            float v1 = (acc[nt][2+e] - mu1*sS)*rs1 + sC;
            float h0 = 0.5f*v0*(1.0f + erff(v0*0.70710678118654752440f));
            float h1 = 0.5f*v1*(1.0f + erff(v1*0.70710678118654752440f));
            po0 += h0*wv;
            po1 += h1*wv;
        }
    }
    #pragma unroll
    for (int off=1; off<4; off<<=1) {
        po0 += __shfl_xor_sync(0xffffffffu, po0, off);
        po1 += __shfl_xor_sync(0xffffffffu, po1, off);
    }
    if (tig == 0) {
        s_part[wm*16+g][wn]   = po0;
        s_part[wm*16+g+8][wn] = po1;
    }
    __syncthreads();
    if (t < GBM) {
        out[row0 + t] = b2p[0] + s_part[t][0] + s_part[t][1] + s_part[t][2] + s_part[t][3];
    }
}

// ---------------- launch ---------------------------------------------------
extern "C" void kernel_launch(void* const* d_in, const int* in_sizes, int n_in,
                              void* d_out, int out_size) {
    const float* x      = (const float*)d_in[0];
    const float* t      = (const float*)d_in[1];
    const float* te_w1  = (const float*)d_in[2];
    const float* te_b1  = (const float*)d_in[3];
    const float* te_w2  = (const float*)d_in[4];
    const float* te_b2  = (const float*)d_in[5];
    const float* fproj_w= (const float*)d_in[6];
    const float* fproj_b= (const float*)d_in[7];
    const float* bproj_w= (const float*)d_in[8];
    const float* bproj_b= (const float*)d_in[9];
    const float* fz_w   = (const float*)d_in[10];
    const float* fz_b   = (const float*)d_in[11];
    const float* fh_w   = (const float*)d_in[12];
    const float* fh_b   = (const float*)d_in[13];
    const float* bz_w   = (const float*)d_in[14];
    const float* bz_b   = (const float*)d_in[15];
    const float* bh_w   = (const float*)d_in[16];
    const float* bh_b   = (const float*)d_in[17];
    const float* ln_g   = (const float*)d_in[18];
    const float* ln_b   = (const float*)d_in[19];
    const float* tsc    = (const float*)d_in[20];
    const float* gh_w1  = (const float*)d_in[21];
    const float* gh_b1  = (const float*)d_in[22];
    const float* gh_w2  = (const float*)d_in[23];
    const float* gh_b2  = (const float*)d_in[24];
    float* out = (float*)d_out;

    k_zero<<<(4*H_*IN_ + 255)/256, 256>>>();
    k_fold<<<dim3(4, 16), H_>>>(fz_w, fh_w, bz_w, bh_w, fz_b, fh_b, bz_b, bh_b,
                                fproj_w, fproj_b, bproj_w, bproj_b);
    k_prepG<<<24, HH_>>>(gh_w1, gh_b1, ln_g, ln_b, tsc);
    k_te<<<NROW/256, 256>>>(x, t, te_w1, te_b1, te_w2, te_b2);
    k_scanA <<<dim3(NC_, B_, 2), H_>>>();
    k_scanB1<<<dim3(B_, 2), H_>>>();
    k_scanC1<<<dim3(NC_, B_, 2), H_>>>();
    k_scanB2<<<dim3(B_, 2), H_>>>();
    k_scanC2<<<dim3(NC_, B_, 2), H_>>>();
    k_gemm3<<<NROW/GBM, 512>>>(gh_w2, gh_b2, out);
}

// round 13
// speedup vs baseline: 3.3485x; 1.0267x over previous
#include <cuda_runtime.h>
#include <cuda_fp16.h>
#include <math.h>
#include <stdint.h>

#define B_  16
#define L_  4096
#define H_  512
#define NT_ 8
#define IN_ 10
#define INP 12               // padded xc stride (48B rows -> LDS.128)
#define OUT_ 1032
#define KP   1056            // padded K (66 chunks of 16)
#define NCH16 66
#define HH_ 256
#define NC_ 16
#define CH_ 256
#define EPS_ 1e-5f
#define NROW (B_*L_)
#define NTILE (NROW/64)

// ---------------- device scratch (static, allocation-free) ----------------
__device__ float g_xc[(size_t)NROW*INP];            // pads [10],[11] stay 0
__device__ float g_F [(size_t)NROW*KP];             // features (dead regions stay 0)
__device__ float g_W [4][H_][IN_];
__device__ float g_bias[4][H_];
__device__ float g_P [2][B_][NC_][H_];              // chunk a-products
__device__ float g_Ae[2][B_][NC_][H_];              // chunk-entry cumprod states
__device__ float g_Lc[2][B_][NC_][H_];
__device__ float g_Se[2][B_][NC_][H_];
__device__ __half g_Gh[(size_t)NCH16*32*128];       // B fp16 fragment-major (pads 0)
__device__ float g_sv[HH_];
__device__ float g_cv[HH_];
__device__ int   g_tilef[NTILE];                    // per-64-row-tile nonzero flags

// ---------------- zero accumulators / flags --------------------------------
__global__ void k_zero() {
    int i = blockIdx.x*blockDim.x + threadIdx.x;
    if (i < 4*H_*IN_) ((float*)g_W)[i] = 0.f;
    if (i < 4*H_)     ((float*)g_bias)[i] = 0.f;
    if (i < HH_)      { g_sv[i] = 0.f; g_cv[i] = 0.f; }
    if (i < NTILE)    g_tilef[i] = 0;
}

// ---------------- fold gate weights through the 10-dim projection ----------
__global__ void k_fold(const float* __restrict__ fz, const float* __restrict__ fh,
                       const float* __restrict__ bz, const float* __restrict__ bh,
                       const float* __restrict__ fzb, const float* __restrict__ fhb,
                       const float* __restrict__ bzb, const float* __restrict__ bhb,
                       const float* __restrict__ fp, const float* __restrict__ fpb,
                       const float* __restrict__ bp, const float* __restrict__ bpb) {
    int p = blockIdx.x, sl = blockIdx.y;   // 16 slices of 32 rows
    int h = threadIdx.x;
    const float* zw = (p==0)?fz:(p==1)?fh:(p==2)?bz:bh;
    const float* zb = (p==0)?fzb:(p==1)?fhb:(p==2)?bzb:bhb;
    const float* pw = (p<2)?fp:bp;
    const float* pb = (p<2)?fpb:bpb;
    float acc[IN_]; float ab = 0.f;
    #pragma unroll
    for (int i=0;i<IN_;i++) acc[i]=0.f;
    for (int d=sl*32; d<sl*32+32; d++) {
        float w = zw[h*H_+d];
        #pragma unroll
        for (int i=0;i<IN_;i++) acc[i] += w*pw[d*IN_+i];
        ab += w*pb[d];
    }
    #pragma unroll
    for (int i=0;i<IN_;i++) atomicAdd(&g_W[p][h][i], acc[i]);
    atomicAdd(&g_bias[p][h], ab + ((sl==0)? zb[h] : 0.f));
}

// ---------------- fold LN affine into gh_w1, emit fp16 fragment-major B ----
__global__ void k_prepG(const float* __restrict__ gw1, const float* __restrict__ gb1,
                        const float* __restrict__ lng, const float* __restrict__ lnb,
                        const float* __restrict__ tscp) {
    int k = threadIdx.x;                 // output col n, 0..255
    int j0 = blockIdx.x * 43;            // 24 blocks x 43 = 1032
    float tsc = tscp[0];
    int nt = k >> 3, ng = k & 7;
    float s = 0.f, c = 0.f;
    for (int j=j0; j<j0+43; j++) {
        float sc = (j >= OUT_-NT_) ? tsc : 1.0f;
        float w  = gw1[k*OUT_+j];
        __half Gh = __float2half_rn(lng[j]*sc*w);
        int kt = j >> 4, kin = j & 15;
        int lane = ng*4 + ((kin & 7) >> 1);
        int reg = kin >> 3, hs = kin & 1;
        g_Gh[(((size_t)(kt*32 + nt)*32 + lane)*2 + reg)*2 + hs] = Gh;
        s += __half2float(Gh);
        c += lnb[j]*sc*w;
    }
    atomicAdd(&g_sv[k], s);
    atomicAdd(&g_cv[k], c + ((blockIdx.x==0)? gb1[k] : 0.f));
}

// ---------------- time embedding + xc, te into F ---------------------------
__global__ void k_te(const float* __restrict__ x, const float* __restrict__ t,
                     const float* __restrict__ w1, const float* __restrict__ b1,
                     const float* __restrict__ w2, const float* __restrict__ b2) {
    int row = blockIdx.x*blockDim.x + threadIdx.x;
    if (row >= NROW) return;
    int b = row / L_;
    float ts = t[row] - t[b*L_];
    float r[NT_];
    #pragma unroll
    for (int j=0;j<NT_;j++) r[j] = fmaxf(ts*w1[j] + b1[j], 0.0f);
    float te[NT_];
    #pragma unroll
    for (int k=0;k<NT_;k++) {
        float a = b2[k];
        #pragma unroll
        for (int j=0;j<NT_;j++) a += r[j]*w2[k*NT_+j];
        te[k] = a;
    }
    float x0 = x[row*2+0], x1 = x[row*2+1];
    float* xr = g_xc + (size_t)row*INP;
    *(float4*)(xr+0) = make_float4(x0, x1, te[0], te[1]);
    *(float4*)(xr+4) = make_float4(te[2], te[3], te[4], te[5]);
    *(float4*)(xr+8) = make_float4(te[6], te[7], 0.f, 0.f);
    float* fte = g_F + (size_t)row*KP + (OUT_-NT_);
    *(float4*)(fte)     = make_float4(te[0], te[1], te[2], te[3]);
    *(float4*)(fte + 4) = make_float4(te[4], te[5], te[6], te[7]);
}

// fast sigmoid pieces (full: z and 1-z)
__device__ __forceinline__ void fsig(float arg, float& z, float& omz) {
    float e = __expf(-arg);
    z = __fdividef(1.0f, 1.0f + e);
    omz = e * z;
}

// vectorized dot-10 against padded 48B row (order identical to scalar loop)
__device__ __forceinline__ float dot10(const float* xr, const float* w, float b) {
    float4 v0 = *(const float4*)(xr);
    float4 v1 = *(const float4*)(xr+4);
    float2 v2 = *(const float2*)(xr+8);
    float a = b;
    a += v0.x*w[0]; a += v0.y*w[1]; a += v0.z*w[2]; a += v0.w*w[3];
    a += v1.x*w[4]; a += v1.y*w[5]; a += v1.z*w[6]; a += v1.w*w[7];
    a += v2.x*w[8]; a += v2.y*w[9];
    return a;
}
__device__ __forceinline__ void dot10x2(const float* xr, const float* wz, float bz,
                                        const float* wh, float bh, float& az, float& ah) {
    float4 v0 = *(const float4*)(xr);
    float4 v1 = *(const float4*)(xr+4);
    float2 v2 = *(const float2*)(xr+8);
    float a = bz, c = bh;
    a += v0.x*wz[0]; a += v0.y*wz[1]; a += v0.z*wz[2]; a += v0.w*wz[3];
    a += v1.x*wz[4]; a += v1.y*wz[5]; a += v1.z*wz[6]; a += v1.w*wz[7];
    a += v2.x*wz[8]; a += v2.y*wz[9];
    c += v0.x*wh[0]; c += v0.y*wh[1]; c += v0.z*wh[2]; c += v0.w*wh[3];
    c += v1.x*wh[4]; c += v1.y*wh[5]; c += v1.z*wh[6]; c += v1.w*wh[7];
    c += v2.x*wh[8]; c += v2.y*wh[9];
    az = a; ah = c;
}

// ---------------- scan pass A: chunk-local a-products ----------------------
// (launched 4th so ncu's skip-count lands here)
__global__ void k_scanA() {
    int c = blockIdx.x, b = blockIdx.y, dir = blockIdx.z;
    int h = threadIdx.x;
    __shared__ float xs[CH_][INP];
    const float4* xc4 = (const float4*)(g_xc + ((size_t)b*L_ + (size_t)c*CH_)*INP);
    for (int i=h; i<CH_*3; i+=H_) ((float4*)xs)[i] = xc4[i];
    float wz[IN_]; float bz;
    int pz = dir*2;
    #pragma unroll
    for (int i=0;i<IN_;i++) wz[i] = g_W[pz][h][i];
    bz = g_bias[pz][h];
    __syncthreads();
    float A = 1.0f;
    int s0 = (dir==0)? 0 : CH_-1;
    int ds = (dir==0)? 1 : -1;
    #pragma unroll 4
    for (int k=0;k<CH_;k++) {
        int s = s0 + k*ds;
        float arg = dot10(&xs[s][0], wz, bz);
        // omz = sigmoid(-arg) = 1/(1+e^{arg}) : z not needed here
        float e2 = __expf(arg);
        A *= __fdividef(1.0f, 1.0f + e2);
    }
    g_P[dir][b][c][h] = A;
}

// ---------------- scan pass B1: chunk-entry cumprod states -----------------
__global__ void k_scanB1() {
    int b = blockIdx.x, dir = blockIdx.y, h = threadIdx.x;
    float run = 1.0f;
    if (dir==0) { for (int c=0;c<NC_;c++)    { g_Ae[0][b][c][h]=run; run *= g_P[0][b][c][h]; } }
    else        { for (int c=NC_-1;c>=0;c--) { g_Ae[1][b][c][h]=run; run *= g_P[1][b][c][h]; } }
}

// ---------------- scan pass C1: chunk local sums (block skip) --------------
__global__ void k_scanC1() {
    int c = blockIdx.x, b = blockIdx.y, dir = blockIdx.z;
    int h = threadIdx.x;
    __shared__ float xs[CH_][INP];
    float A = g_Ae[dir][b][c][h];
    if (!__syncthreads_or(A != 0.f)) { g_Lc[dir][b][c][h] = 0.f; return; }
    const float4* xc4 = (const float4*)(g_xc + ((size_t)b*L_ + (size_t)c*CH_)*INP);
    for (int i=h; i<CH_*3; i+=H_) ((float4*)xs)[i] = xc4[i];
    float wz[IN_], wh[IN_]; float bz, bh;
    int pz = dir*2, ph = dir*2+1;
    #pragma unroll
    for (int i=0;i<IN_;i++) { wz[i]=g_W[pz][h][i]; wh[i]=g_W[ph][h][i]; }
    bz = g_bias[pz][h]; bh = g_bias[ph][h];
    __syncthreads();
    float Ls = 0.0f;
    int s0  = (dir==0)? 0 : CH_-1;
    int ds  = (dir==0)? 1 : -1;
    #pragma unroll 4
    for (int k=0;k<CH_;k++) {
        int s = s0 + k*ds;
        float az, ah;
        dot10x2(&xs[s][0], wz, bz, wh, bh, az, ah);
        float z, omz; fsig(az, z, omz);
        A *= omz;
        Ls += __fdividef(z*ah, fmaxf(A, 1e-12f));
    }
    g_Lc[dir][b][c][h] = Ls;
}

// ---------------- scan pass B2: chunk-entry cumsum states ------------------
__global__ void k_scanB2() {
    int b = blockIdx.x, dir = blockIdx.y, h = threadIdx.x;
    float run = 0.0f;
    if (dir==0) { for (int c=0;c<NC_;c++)    { g_Se[0][b][c][h]=run; run += g_Lc[0][b][c][h]; } }
    else        { for (int c=NC_-1;c>=0;c--) { g_Se[1][b][c][h]=run; run += g_Lc[1][b][c][h]; } }
}

// ---------------- scan pass C2: emit h = A*S -------------------------------
__global__ void k_scanC2() {
    int c = blockIdx.x, b = blockIdx.y, dir = blockIdx.z;
    int h = threadIdx.x;
    __shared__ float xs[CH_][INP];
    float A = g_Ae[dir][b][c][h];
    if (!__syncthreads_or(A != 0.f)) return;    // region stays exact 0
    const float4* xc4 = (const float4*)(g_xc + ((size_t)b*L_ + (size_t)c*CH_)*INP);
    for (int i=h; i<CH_*3; i+=H_) ((float4*)xs)[i] = xc4[i];
    float wz[IN_], wh[IN_]; float bz, bh;
    int pz = dir*2, ph = dir*2+1;
    #pragma unroll
    for (int i=0;i<IN_;i++) { wz[i]=g_W[pz][h][i]; wh[i]=g_W[ph][h][i]; }
    bz = g_bias[pz][h]; bh = g_bias[ph][h];
    float S = g_Se[dir][b][c][h];
    __syncthreads();
    int s0  = (dir==0)? 0 : CH_-1;
    int ds  = (dir==0)? 1 : -1;
    size_t fofs = (dir==0)? (size_t)h : (size_t)(H_ + h);
    // strength-reduced store pointer: row (b*L + c*CH + s0), step ds
    float* fp = g_F + ((size_t)(b*L_ + c*CH_ + s0))*KP + fofs;
    ptrdiff_t fstep = (ptrdiff_t)ds * KP;
    int zstep = 0;
    #pragma unroll 4
    for (int k=0;k<CH_;k++) {
        int s = s0 + k*ds;
        if (A != 0.f) zstep = k+1;              // predicated select, no branch
        *fp = A*S;                              // state BEFORE consuming position
        fp += fstep;
        float az, ah;
        dot10x2(&xs[s][0], wz, bz, wh, bh, az, ah);
        float z, omz; fsig(az, z, omz);
        A *= omz;
        S += __fdividef(z*ah, fmaxf(A, 1e-12f));
    }
    // tile flags: fwd writes ascending from chunk start; bwd descending from end
    int tile0 = (b*L_ + c*CH_) >> 6;
    #pragma unroll
    for (int ti=0; ti<4; ti++) {
        int thr = (dir==0) ? ti*64 : (192 - ti*64);
        int ta = __syncthreads_or(zstep > thr);
        if (ta && h == 0) atomicOr(&g_tilef[tile0 + ti], 1 << dir);
    }
}

// ---------------- fp16 mma GEMM (smem-staged B, contiguous live range) -----
#define GBM 64
__global__ __launch_bounds__(512, 1) void k_gemm3(const float* __restrict__ w2,
                                                  const float* __restrict__ b2p,
                                                  float* __restrict__ out) {
    __shared__ float s_s[HH_], s_c[HH_], s_w2[HH_];
    __shared__ float s_sum[GBM], s_sq[GBM];
    __shared__ float s_mu[GBM], s_rs[GBM];
    __shared__ float s_part[GBM][4];
    __shared__ uint2 sB[2][1024];               // double-buffered B chunk (8KB x2)

    int t = threadIdx.x;
    int lane = t & 31, warp = t >> 5;
    int wm = warp >> 2, wn = warp & 3;          // 4m x 4n warp grid
    int g  = lane >> 2, tig = lane & 3;
    int row0 = blockIdx.x * GBM;
    int r0 = row0 + wm*16 + g;

    if (t < HH_) { s_s[t] = g_sv[t]; s_c[t] = g_cv[t]; s_w2[t] = w2[t]; }

    int flag = g_tilef[blockIdx.x] & 3;
    int c0 = (flag & 1) ? 0 : 32;               // contiguous live chunk range start
    int n  = (flag == 3) ? 64 : (flag ? 32 : 0);
    int total = n + 1;                          // + te chunk (64)

    float acc[8][4];
    #pragma unroll
    for (int i=0;i<8;i++) { acc[i][0]=0.f; acc[i][1]=0.f; acc[i][2]=0.f; acc[i][3]=0.f; }

    const float* Ar0 = g_F + (size_t)r0*KP     + tig*2;
    const float* Ar8 = Ar0 + 8*KP;
    const uint2* Ghu2 = (const uint2*)g_Gh;

    int ci = (0 < n) ? c0 : 64;
    float2 fA0 = __ldg((const float2*)(Ar0 + ci*16));
    float2 fA1 = __ldg((const float2*)(Ar8 + ci*16));
    float2 fA2 = __ldg((const float2*)(Ar0 + ci*16 + 8));
    float2 fA3 = __ldg((const float2*)(Ar8 + ci*16 + 8));
    {
        const uint2* Bn = Ghu2 + (size_t)ci*1024;
        sB[0][t]       = __ldg(Bn + t);
        sB[0][t + 512] = __ldg(Bn + t + 512);
    }
    __syncthreads();

    float ps0=0.f, pq0=0.f, ps1=0.f, pq1=0.f;
    int cur = 0;

    for (int it=0; it<total; it++) {
        uint2 fB[8];
        #pragma unroll
        for (int nt=0; nt<8; nt++) fB[nt] = sB[cur][wn*256 + nt*32 + lane];
        if (wn == 0) {
            ps0 += fA0.x+fA0.y+fA2.x+fA2.y;
            pq0 += fA0.x*fA0.x + fA0.y*fA0.y + fA2.x*fA2.x + fA2.y*fA2.y;
            ps1 += fA1.x+fA1.y+fA3.x+fA3.y;
            pq1 += fA1.x*fA1.x + fA1.y*fA1.y + fA3.x*fA3.x + fA3.y*fA3.y;
        }
        __half2 h0 = __floats2half2_rn(fA0.x, fA0.y);
        __half2 h1 = __floats2half2_rn(fA1.x, fA1.y);
        __half2 h2 = __floats2half2_rn(fA2.x, fA2.y);
        __half2 h3 = __floats2half2_rn(fA3.x, fA3.y);
        uint32_t a0 = *reinterpret_cast<uint32_t*>(&h0);
        uint32_t a1 = *reinterpret_cast<uint32_t*>(&h1);
        uint32_t a2 = *reinterpret_cast<uint32_t*>(&h2);
        uint32_t a3 = *reinterpret_cast<uint32_t*>(&h3);
        #pragma unroll
        for (int nt=0; nt<8; nt++) {
            asm volatile(
                "mma.sync.aligned.m16n8k16.row.col.f32.f16.f16.f32 "
                "{%0,%1,%2,%3}, {%4,%5,%6,%7}, {%8,%9}, {%0,%1,%2,%3};"
                : "+f"(acc[nt][0]), "+f"(acc[nt][1]), "+f"(acc[nt][2]), "+f"(acc[nt][3])
                : "r"(a0), "r"(a1), "r"(a2), "r"(a3), "r"(fB[nt].x), "r"(fB[nt].y));
        }
        if (it+1 < total) {
            int itn = it+1;
            ci = (itn < n) ? (c0 + itn) : 64;   // branchless select
            const uint2* Bn = Ghu2 + (size_t)ci*1024;
            sB[cur^1][t]       = __ldg(Bn + t);
            sB[cur^1][t + 512] = __ldg(Bn + t + 512);
            fA0 = __ldg((const float2*)(Ar0 + ci*16));
            fA1 = __ldg((const float2*)(Ar8 + ci*16));
            fA2 = __ldg((const float2*)(Ar0 + ci*16 + 8));
            fA3 = __ldg((const float2*)(Ar8 + ci*16 + 8));
        }
        __syncthreads();
        cur ^= 1;
    }

    if (wn == 0) {
        #pragma unroll
        for (int off=1; off<4; off<<=1) {
            ps0 += __shfl_xor_sync(0xffffffffu, ps0, off);
            pq0 += __shfl_xor_sync(0xffffffffu, pq0, off);
            ps1 += __shfl_xor_sync(0xffffffffu, ps1, off);
            pq1 += __shfl_xor_sync(0xffffffffu, pq1, off);
        }
        if (tig == 0) {
            s_sum[wm*16+g]   = ps0;  s_sq[wm*16+g]   = pq0;
            s_sum[wm*16+g+8] = ps1;  s_sq[wm*16+g+8] = pq1;
        }
    }
    __syncthreads();
    if (t < GBM) {
        float m = s_sum[t] * (1.0f/(float)OUT_);
        float v = s_sq[t]  * (1.0f/(float)OUT_) - m*m;
        s_mu[t] = m;
        s_rs[t] = rsqrtf(v + EPS_);
    }
    __syncthreads();

    float mu0 = s_mu[wm*16+g],   rs0 = s_rs[wm*16+g];
    float mu1 = s_mu[wm*16+g+8], rs1 = s_rs[wm*16+g+8];
    float po0 = 0.f, po1 = 0.f;
    #pragma unroll
    for (int nt=0; nt<8; nt++) {
        #pragma unroll
        for (int e=0; e<2; e++) {
            int col = wn*64 + nt*8 + tig*2 + e;
            float sS = s_s[col], sC = s_c[col], wv = s_w2[col];
            float v0 = (acc[nt][e]   - mu0*sS)*rs0 + sC;
            float v1 = (acc[nt][2+e] - mu1*sS)*rs1 + sC;
            float h0 = 0.5f*v0*(1.0f + erff(v0*0.70710678118654752440f));
            float h1 = 0.5f*v1*(1.0f + erff(v1*0.70710678118654752440f));
            po0 += h0*wv;
            po1 += h1*wv;
        }
    }
    #pragma unroll
    for (int off=1; off<4; off<<=1) {
        po0 += __shfl_xor_sync(0xffffffffu, po0, off);
        po1 += __shfl_xor_sync(0xffffffffu, po1, off);
    }
    if (tig == 0) {
        s_part[wm*16+g][wn]   = po0;
        s_part[wm*16+g+8][wn] = po1;
    }
    __syncthreads();
    if (t < GBM) {
        out[row0 + t] = b2p[0] + s_part[t][0] + s_part[t][1] + s_part[t][2] + s_part[t][3];
    }
}

// ---------------- launch ---------------------------------------------------
extern "C" void kernel_launch(void* const* d_in, const int* in_sizes, int n_in,
                              void* d_out, int out_size) {
    const float* x      = (const float*)d_in[0];
    const float* t      = (const float*)d_in[1];
    const float* te_w1  = (const float*)d_in[2];
    const float* te_b1  = (const float*)d_in[3];
    const float* te_w2  = (const float*)d_in[4];
    const float* te_b2  = (const float*)d_in[5];
    const float* fproj_w= (const float*)d_in[6];
    const float* fproj_b= (const float*)d_in[7];
    const float* bproj_w= (const float*)d_in[8];
    const float* bproj_b= (const float*)d_in[9];
    const float* fz_w   = (const float*)d_in[10];
    const float* fz_b   = (const float*)d_in[11];
    const float* fh_w   = (const float*)d_in[12];
    const float* fh_b   = (const float*)d_in[13];
    const float* bz_w   = (const float*)d_in[14];
    const float* bz_b   = (const float*)d_in[15];
    const float* bh_w   = (const float*)d_in[16];
    const float* bh_b   = (const float*)d_in[17];
    const float* ln_g   = (const float*)d_in[18];
    const float* ln_b   = (const float*)d_in[19];
    const float* tsc    = (const float*)d_in[20];
    const float* gh_w1  = (const float*)d_in[21];
    const float* gh_b1  = (const float*)d_in[22];
    const float* gh_w2  = (const float*)d_in[23];
    const float* gh_b2  = (const float*)d_in[24];
    float* out = (float*)d_out;

    // order chosen so ncu's fixed skip-count lands on k_scanA (4th launch);
    // stream is serial, so the reorder is timing-neutral.
    k_zero<<<(4*H_*IN_ + 255)/256, 256>>>();
    k_fold<<<dim3(4, 16), H_>>>(fz_w, fh_w, bz_w, bh_w, fz_b, fh_b, bz_b, bh_b,
                                fproj_w, fproj_b, bproj_w, bproj_b);
    k_te<<<NROW/256, 256>>>(x, t, te_w1, te_b1, te_w2, te_b2);
    k_scanA <<<dim3(NC_, B_, 2), H_>>>();
    k_prepG<<<24, HH_>>>(gh_w1, gh_b1, ln_g, ln_b, tsc);
    k_scanB1<<<dim3(B_, 2), H_>>>();
    k_scanC1<<<dim3(NC_, B_, 2), H_>>>();
    k_scanB2<<<dim3(B_, 2), H_>>>();
    k_scanC2<<<dim3(NC_, B_, 2), H_>>>();
    k_gemm3<<<NROW/GBM, 512>>>(gh_w2, gh_b2, out);
}

// round 14
// speedup vs baseline: 3.8567x; 1.1518x over previous
#include <cuda_runtime.h>
#include <cuda_fp16.h>
#include <math.h>
#include <stdint.h>

#define B_  16
#define L_  4096
#define H_  512
#define NT_ 8
#define IN_ 10
#define INP 12               // padded xc stride (48B rows -> LDS.128)
#define OUT_ 1032
#define KP   1056            // padded K (66 chunks of 16)
#define NCH16 66
#define HH_ 256
#define NC_ 16
#define CH_ 256
#define EPS_ 1e-5f
#define NROW (B_*L_)
#define NTILE (NROW/64)

// ---------------- device scratch (static, allocation-free) ----------------
__device__ float g_xc[(size_t)NROW*INP];            // pads [10],[11] stay 0
__device__ float g_F [(size_t)NROW*KP];             // features (dead regions stay 0)
__device__ float g_W [4][H_][IN_];
__device__ float g_bias[4][H_];
__device__ float g_P [2][B_][NC_][H_];              // chunk a-products (skipped stay 0)
__device__ float g_Ae[2][B_][NC_][H_];              // chunk-entry cumprod states
__device__ float g_Lc[2][B_][NC_][H_];
__device__ float g_Se[2][B_][NC_][H_];
__device__ __half g_Gh[(size_t)NCH16*32*128];       // B fp16 fragment-major (pads 0)
__device__ float g_sv[HH_];
__device__ float g_cv[HH_];
__device__ int   g_tilef[NTILE];                    // per-64-row-tile nonzero flags
__device__ int   g_live[2][B_];                     // per-(dir,b) liveness after 2 chunks

// ---------------- zero accumulators / flags --------------------------------
__global__ void k_zero() {
    int i = blockIdx.x*blockDim.x + threadIdx.x;
    if (i < 4*H_*IN_) ((float*)g_W)[i] = 0.f;
    if (i < 4*H_)     ((float*)g_bias)[i] = 0.f;
    if (i < HH_)      { g_sv[i] = 0.f; g_cv[i] = 0.f; }
    if (i < NTILE)    g_tilef[i] = 0;
}

// ---------------- fold gate weights through the 10-dim projection ----------
__global__ void k_fold(const float* __restrict__ fz, const float* __restrict__ fh,
                       const float* __restrict__ bz, const float* __restrict__ bh,
                       const float* __restrict__ fzb, const float* __restrict__ fhb,
                       const float* __restrict__ bzb, const float* __restrict__ bhb,
                       const float* __restrict__ fp, const float* __restrict__ fpb,
                       const float* __restrict__ bp, const float* __restrict__ bpb) {
    int p = blockIdx.x, sl = blockIdx.y;   // 16 slices of 32 rows
    int h = threadIdx.x;
    const float* zw = (p==0)?fz:(p==1)?fh:(p==2)?bz:bh;
    const float* zb = (p==0)?fzb:(p==1)?fhb:(p==2)?bzb:bhb;
    const float* pw = (p<2)?fp:bp;
    const float* pb = (p<2)?fpb:bpb;
    float acc[IN_]; float ab = 0.f;
    #pragma unroll
    for (int i=0;i<IN_;i++) acc[i]=0.f;
    for (int d=sl*32; d<sl*32+32; d++) {
        float w = zw[h*H_+d];
        #pragma unroll
        for (int i=0;i<IN_;i++) acc[i] += w*pw[d*IN_+i];
        ab += w*pb[d];
    }
    #pragma unroll
    for (int i=0;i<IN_;i++) atomicAdd(&g_W[p][h][i], acc[i]);
    atomicAdd(&g_bias[p][h], ab + ((sl==0)? zb[h] : 0.f));
}

// ---------------- fold LN affine into gh_w1, emit fp16 fragment-major B ----
__global__ void k_prepG(const float* __restrict__ gw1, const float* __restrict__ gb1,
                        const float* __restrict__ lng, const float* __restrict__ lnb,
                        const float* __restrict__ tscp) {
    int k = threadIdx.x;                 // output col n, 0..255
    int j0 = blockIdx.x * 43;            // 24 blocks x 43 = 1032
    float tsc = tscp[0];
    int nt = k >> 3, ng = k & 7;
    float s = 0.f, c = 0.f;
    for (int j=j0; j<j0+43; j++) {
        float sc = (j >= OUT_-NT_) ? tsc : 1.0f;
        float w  = gw1[k*OUT_+j];
        __half Gh = __float2half_rn(lng[j]*sc*w);
        int kt = j >> 4, kin = j & 15;
        int lane = ng*4 + ((kin & 7) >> 1);
        int reg = kin >> 3, hs = kin & 1;
        g_Gh[(((size_t)(kt*32 + nt)*32 + lane)*2 + reg)*2 + hs] = Gh;
        s += __half2float(Gh);
        c += lnb[j]*sc*w;
    }
    atomicAdd(&g_sv[k], s);
    atomicAdd(&g_cv[k], c + ((blockIdx.x==0)? gb1[k] : 0.f));
}

// ---------------- time embedding + xc, te into F ---------------------------
__global__ void k_te(const float* __restrict__ x, const float* __restrict__ t,
                     const float* __restrict__ w1, const float* __restrict__ b1,
                     const float* __restrict__ w2, const float* __restrict__ b2) {
    int row = blockIdx.x*blockDim.x + threadIdx.x;
    if (row >= NROW) return;
    int b = row / L_;
    float ts = t[row] - t[b*L_];
    float r[NT_];
    #pragma unroll
    for (int j=0;j<NT_;j++) r[j] = fmaxf(ts*w1[j] + b1[j], 0.0f);
    float te[NT_];
    #pragma unroll
    for (int k=0;k<NT_;k++) {
        float a = b2[k];
        #pragma unroll
        for (int j=0;j<NT_;j++) a += r[j]*w2[k*NT_+j];
        te[k] = a;
    }
    float x0 = x[row*2+0], x1 = x[row*2+1];
    float* xr = g_xc + (size_t)row*INP;
    *(float4*)(xr+0) = make_float4(x0, x1, te[0], te[1]);
    *(float4*)(xr+4) = make_float4(te[2], te[3], te[4], te[5]);
    *(float4*)(xr+8) = make_float4(te[6], te[7], 0.f, 0.f);
    float* fte = g_F + (size_t)row*KP + (OUT_-NT_);
    *(float4*)(fte)     = make_float4(te[0], te[1], te[2], te[3]);
    *(float4*)(fte + 4) = make_float4(te[4], te[5], te[6], te[7]);
}

// fast sigmoid pieces (full: z and 1-z)
__device__ __forceinline__ void fsig(float arg, float& z, float& omz) {
    float e = __expf(-arg);
    z = __fdividef(1.0f, 1.0f + e);
    omz = e * z;
}

// vectorized dot-10 against padded 48B row (order identical to scalar loop)
__device__ __forceinline__ float dot10(const float* xr, const float* w, float b) {
    float4 v0 = *(const float4*)(xr);
    float4 v1 = *(const float4*)(xr+4);
    float2 v2 = *(const float2*)(xr+8);
    float a = b;
    a += v0.x*w[0]; a += v0.y*w[1]; a += v0.z*w[2]; a += v0.w*w[3];
    a += v1.x*w[4]; a += v1.y*w[5]; a += v1.z*w[6]; a += v1.w*w[7];
    a += v2.x*w[8]; a += v2.y*w[9];
    return a;
}
__device__ __forceinline__ void dot10x2(const float* xr, const float* wz, float bz,
                                        const float* wh, float bh, float& az, float& ah) {
    float4 v0 = *(const float4*)(xr);
    float4 v1 = *(const float4*)(xr+4);
    float2 v2 = *(const float2*)(xr+8);
    float a = bz, c = bh;
    a += v0.x*wz[0]; a += v0.y*wz[1]; a += v0.z*wz[2]; a += v0.w*wz[3];
    a += v1.x*wz[4]; a += v1.y*wz[5]; a += v1.z*wz[6]; a += v1.w*wz[7];
    a += v2.x*wz[8]; a += v2.y*wz[9];
    c += v0.x*wh[0]; c += v0.y*wh[1]; c += v0.z*wh[2]; c += v0.w*wh[3];
    c += v1.x*wh[4]; c += v1.y*wh[5]; c += v1.z*wh[6]; c += v1.w*wh[7];
    c += v2.x*wh[8]; c += v2.y*wh[9];
    az = a; ah = c;
}

// common scanA body: chunk product for actual chunk c
__device__ __forceinline__ void scanA_body(int c, int b, int dir, int h) {
    __shared__ float xs[CH_][INP];
    const float4* xc4 = (const float4*)(g_xc + ((size_t)b*L_ + (size_t)c*CH_)*INP);
    for (int i=h; i<CH_*3; i+=H_) ((float4*)xs)[i] = xc4[i];
    float wz[IN_]; float bz;
    int pz = dir*2;
    #pragma unroll
    for (int i=0;i<IN_;i++) wz[i] = g_W[pz][h][i];
    bz = g_bias[pz][h];
    __syncthreads();
    float A = 1.0f;
    int s0 = (dir==0)? 0 : CH_-1;
    int ds = (dir==0)? 1 : -1;
    #pragma unroll 4
    for (int k=0;k<CH_;k++) {
        int s = s0 + k*ds;
        float arg = dot10(&xs[s][0], wz, bz);
        float e2 = __expf(arg);                 // omz = 1/(1+e^{arg})
        A *= __fdividef(1.0f, 1.0f + e2);
    }
    g_P[dir][b][c][h] = A;
}

// ---------------- scanA phase 1: first 2 scan-order chunks -----------------
__global__ void k_scanA01() {
    int cs = blockIdx.x, b = blockIdx.y, dir = blockIdx.z;      // cs in {0,1}
    int c = dir ? (NC_-1-cs) : cs;
    scanA_body(c, b, dir, threadIdx.x);
}

// ---------------- liveness after 2 chunks: OR_h (P0*P1 != 0) ---------------
__global__ void k_live() {
    int b = blockIdx.x, dir = blockIdx.y, h = threadIdx.x;
    int c0 = dir ? NC_-1 : 0;
    int c1 = dir ? NC_-2 : 1;
    float p = g_P[dir][b][c0][h] * g_P[dir][b][c1][h];  // == B1's run after 2 chunks
    int lv = __syncthreads_or(p != 0.f);
    if (h == 0) g_live[dir][b] = lv;
}

// ---------------- scanA phase 2: remaining chunks, only if live ------------
__global__ void k_scanA2() {
    int cs = blockIdx.x + 2, b = blockIdx.y, dir = blockIdx.z;  // cs in {2..15}
    if (!g_live[dir][b]) return;        // uniform: skipped P stays 0, multiplied into 0-run
    int c = dir ? (NC_-1-cs) : cs;
    scanA_body(c, b, dir, threadIdx.x);
}

// ---------------- scan pass B1: chunk-entry cumprod states -----------------
__global__ void k_scanB1() {
    int b = blockIdx.x, dir = blockIdx.y, h = threadIdx.x;
    float run = 1.0f;
    if (dir==0) { for (int c=0;c<NC_;c++)    { g_Ae[0][b][c][h]=run; run *= g_P[0][b][c][h]; } }
    else        { for (int c=NC_-1;c>=0;c--) { g_Ae[1][b][c][h]=run; run *= g_P[1][b][c][h]; } }
}

// ---------------- scan pass C1: chunk local sums (block skip) --------------
__global__ void k_scanC1() {
    int c = blockIdx.x, b = blockIdx.y, dir = blockIdx.z;
    int h = threadIdx.x;
    __shared__ float xs[CH_][INP];
    float A = g_Ae[dir][b][c][h];
    if (!__syncthreads_or(A != 0.f)) { g_Lc[dir][b][c][h] = 0.f; return; }
    const float4* xc4 = (const float4*)(g_xc + ((size_t)b*L_ + (size_t)c*CH_)*INP);
    for (int i=h; i<CH_*3; i+=H_) ((float4*)xs)[i] = xc4[i];
    float wz[IN_], wh[IN_]; float bz, bh;
    int pz = dir*2, ph = dir*2+1;
    #pragma unroll
    for (int i=0;i<IN_;i++) { wz[i]=g_W[pz][h][i]; wh[i]=g_W[ph][h][i]; }
    bz = g_bias[pz][h]; bh = g_bias[ph][h];
    __syncthreads();
    float Ls = 0.0f;
    int s0  = (dir==0)? 0 : CH_-1;
    int ds  = (dir==0)? 1 : -1;
    #pragma unroll 4
    for (int k=0;k<CH_;k++) {
        int s = s0 + k*ds;
        float az, ah;
        dot10x2(&xs[s][0], wz, bz, wh, bh, az, ah);
        float z, omz; fsig(az, z, omz);
        A *= omz;
        Ls += __fdividef(z*ah, fmaxf(A, 1e-12f));
    }
    g_Lc[dir][b][c][h] = Ls;
}

// ---------------- scan pass B2: chunk-entry cumsum states ------------------
__global__ void k_scanB2() {
    int b = blockIdx.x, dir = blockIdx.y, h = threadIdx.x;
    float run = 0.0f;
    if (dir==0) { for (int c=0;c<NC_;c++)    { g_Se[0][b][c][h]=run; run += g_Lc[0][b][c][h]; } }
    else        { for (int c=NC_-1;c>=0;c--) { g_Se[1][b][c][h]=run; run += g_Lc[1][b][c][h]; } }
}

// ---------------- scan pass C2: emit h = A*S -------------------------------
__global__ void k_scanC2() {
    int c = blockIdx.x, b = blockIdx.y, dir = blockIdx.z;
    int h = threadIdx.x;
    __shared__ float xs[CH_][INP];
    float A = g_Ae[dir][b][c][h];
    if (!__syncthreads_or(A != 0.f)) return;    // region stays exact 0
    const float4* xc4 = (const float4*)(g_xc + ((size_t)b*L_ + (size_t)c*CH_)*INP);
    for (int i=h; i<CH_*3; i+=H_) ((float4*)xs)[i] = xc4[i];
    float wz[IN_], wh[IN_]; float bz, bh;
    int pz = dir*2, ph = dir*2+1;
    #pragma unroll
    for (int i=0;i<IN_;i++) { wz[i]=g_W[pz][h][i]; wh[i]=g_W[ph][h][i]; }
    bz = g_bias[pz][h]; bh = g_bias[ph][h];
    float S = g_Se[dir][b][c][h];
    __syncthreads();
    int s0  = (dir==0)? 0 : CH_-1;
    int ds  = (dir==0)? 1 : -1;
    size_t fofs = (dir==0)? (size_t)h : (size_t)(H_ + h);
    float* fp = g_F + ((size_t)(b*L_ + c*CH_ + s0))*KP + fofs;
    ptrdiff_t fstep = (ptrdiff_t)ds * KP;
    int zstep = 0;
    #pragma unroll 4
    for (int k=0;k<CH_;k++) {
        int s = s0 + k*ds;
        if (A != 0.f) zstep = k+1;              // predicated select, no branch
        *fp = A*S;                              // state BEFORE consuming position
        fp += fstep;
        float az, ah;
        dot10x2(&xs[s][0], wz, bz, wh, bh, az, ah);
        float z, omz; fsig(az, z, omz);
        A *= omz;
        S += __fdividef(z*ah, fmaxf(A, 1e-12f));
    }
    // tile flags: fwd writes ascending from chunk start; bwd descending from end
    int tile0 = (b*L_ + c*CH_) >> 6;
    #pragma unroll
    for (int ti=0; ti<4; ti++) {
        int thr = (dir==0) ? ti*64 : (192 - ti*64);
        int ta = __syncthreads_or(zstep > thr);
        if (ta && h == 0) atomicOr(&g_tilef[tile0 + ti], 1 << dir);
    }
}

// ---------------- fp16 mma GEMM (smem-staged B, contiguous live range) -----
#define GBM 64
__global__ __launch_bounds__(512, 1) void k_gemm3(const float* __restrict__ w2,
                                                  const float* __restrict__ b2p,
                                                  float* __restrict__ out) {
    __shared__ float s_s[HH_], s_c[HH_], s_w2[HH_];
    __shared__ float s_sum[GBM], s_sq[GBM];
    __shared__ float s_mu[GBM], s_rs[GBM];
    __shared__ float s_part[GBM][4];
    __shared__ uint2 sB[2][1024];               // double-buffered B chunk (8KB x2)

    int t = threadIdx.x;
    int lane = t & 31, warp = t >> 5;
    int wm = warp >> 2, wn = warp & 3;          // 4m x 4n warp grid
    int g  = lane >> 2, tig = lane & 3;
    int row0 = blockIdx.x * GBM;
    int r0 = row0 + wm*16 + g;

    if (t < HH_) { s_s[t] = g_sv[t]; s_c[t] = g_cv[t]; s_w2[t] = w2[t]; }

    int flag = g_tilef[blockIdx.x] & 3;
    int c0 = (flag & 1) ? 0 : 32;               // contiguous live chunk range start
    int n  = (flag == 3) ? 64 : (flag ? 32 : 0);
    int total = n + 1;                          // + te chunk (64)

    float acc[8][4];
    #pragma unroll
    for (int i=0;i<8;i++) { acc[i][0]=0.f; acc[i][1]=0.f; acc[i][2]=0.f; acc[i][3]=0.f; }

    const float* Ar0 = g_F + (size_t)r0*KP     + tig*2;
    const float* Ar8 = Ar0 + 8*KP;
    const uint2* Ghu2 = (const uint2*)g_Gh;

    int ci = (0 < n) ? c0 : 64;
    float2 fA0 = __ldg((const float2*)(Ar0 + ci*16));
    float2 fA1 = __ldg((const float2*)(Ar8 + ci*16));
    float2 fA2 = __ldg((const float2*)(Ar0 + ci*16 + 8));
    float2 fA3 = __ldg((const float2*)(Ar8 + ci*16 + 8));
    {
        const uint2* Bn = Ghu2 + (size_t)ci*1024;
        sB[0][t]       = __ldg(Bn + t);
        sB[0][t + 512] = __ldg(Bn + t + 512);
    }
    __syncthreads();

    float ps0=0.f, pq0=0.f, ps1=0.f, pq1=0.f;
    int cur = 0;

    for (int it=0; it<total; it++) {
        uint2 fB[8];
        #pragma unroll
        for (int nt=0; nt<8; nt++) fB[nt] = sB[cur][wn*256 + nt*32 + lane];
        if (wn == 0) {
            ps0 += fA0.x+fA0.y+fA2.x+fA2.y;
            pq0 += fA0.x*fA0.x + fA0.y*fA0.y + fA2.x*fA2.x + fA2.y*fA2.y;
            ps1 += fA1.x+fA1.y+fA3.x+fA3.y;
            pq1 += fA1.x*fA1.x + fA1.y*fA1.y + fA3.x*fA3.x + fA3.y*fA3.y;
        }
        __half2 h0 = __floats2half2_rn(fA0.x, fA0.y);
        __half2 h1 = __floats2half2_rn(fA1.x, fA1.y);
        __half2 h2 = __floats2half2_rn(fA2.x, fA2.y);
        __half2 h3 = __floats2half2_rn(fA3.x, fA3.y);
        uint32_t a0 = *reinterpret_cast<uint32_t*>(&h0);
        uint32_t a1 = *reinterpret_cast<uint32_t*>(&h1);
        uint32_t a2 = *reinterpret_cast<uint32_t*>(&h2);
        uint32_t a3 = *reinterpret_cast<uint32_t*>(&h3);
        #pragma unroll
        for (int nt=0; nt<8; nt++) {
            asm volatile(
                "mma.sync.aligned.m16n8k16.row.col.f32.f16.f16.f32 "
                "{%0,%1,%2,%3}, {%4,%5,%6,%7}, {%8,%9}, {%0,%1,%2,%3};"
                : "+f"(acc[nt][0]), "+f"(acc[nt][1]), "+f"(acc[nt][2]), "+f"(acc[nt][3])
                : "r"(a0), "r"(a1), "r"(a2), "r"(a3), "r"(fB[nt].x), "r"(fB[nt].y));
        }
        if (it+1 < total) {
            int itn = it+1;
            ci = (itn < n) ? (c0 + itn) : 64;   // branchless select
            const uint2* Bn = Ghu2 + (size_t)ci*1024;
            sB[cur^1][t]       = __ldg(Bn + t);
            sB[cur^1][t + 512] = __ldg(Bn + t + 512);
            fA0 = __ldg((const float2*)(Ar0 + ci*16));
            fA1 = __ldg((const float2*)(Ar8 + ci*16));
            fA2 = __ldg((const float2*)(Ar0 + ci*16 + 8));
            fA3 = __ldg((const float2*)(Ar8 + ci*16 + 8));
        }
        __syncthreads();
        cur ^= 1;
    }

    if (wn == 0) {
        #pragma unroll
        for (int off=1; off<4; off<<=1) {
            ps0 += __shfl_xor_sync(0xffffffffu, ps0, off);
            pq0 += __shfl_xor_sync(0xffffffffu, pq0, off);
            ps1 += __shfl_xor_sync(0xffffffffu, ps1, off);
            pq1 += __shfl_xor_sync(0xffffffffu, pq1, off);
        }
        if (tig == 0) {
            s_sum[wm*16+g]   = ps0;  s_sq[wm*16+g]   = pq0;
            s_sum[wm*16+g+8] = ps1;  s_sq[wm*16+g+8] = pq1;
        }
    }
    __syncthreads();
    if (t < GBM) {
        float m = s_sum[t] * (1.0f/(float)OUT_);
        float v = s_sq[t]  * (1.0f/(float)OUT_) - m*m;
        s_mu[t] = m;
        s_rs[t] = rsqrtf(v + EPS_);
    }
    __syncthreads();

    float mu0 = s_mu[wm*16+g],   rs0 = s_rs[wm*16+g];
    float mu1 = s_mu[wm*16+g+8], rs1 = s_rs[wm*16+g+8];
    float po0 = 0.f, po1 = 0.f;
    #pragma unroll
    for (int nt=0; nt<8; nt++) {
        #pragma unroll
        for (int e=0; e<2; e++) {
            int col = wn*64 + nt*8 + tig*2 + e;
            float sS = s_s[col], sC = s_c[col], wv = s_w2[col];
            float v0 = (acc[nt][e]   - mu0*sS)*rs0 + sC;
            float v1 = (acc[nt][2+e] - mu1*sS)*rs1 + sC;
            float h0 = 0.5f*v0*(1.0f + erff(v0*0.70710678118654752440f));
            float h1 = 0.5f*v1*(1.0f + erff(v1*0.70710678118654752440f));
            po0 += h0*wv;
            po1 += h1*wv;
        }
    }
    #pragma unroll
    for (int off=1; off<4; off<<=1) {
        po0 += __shfl_xor_sync(0xffffffffu, po0, off);
        po1 += __shfl_xor_sync(0xffffffffu, po1, off);
    }
    if (tig == 0) {
        s_part[wm*16+g][wn]   = po0;
        s_part[wm*16+g+8][wn] = po1;
    }
    __syncthreads();
    if (t < GBM) {
        out[row0 + t] = b2p[0] + s_part[t][0] + s_part[t][1] + s_part[t][2] + s_part[t][3];
    }
}

// ---------------- launch ---------------------------------------------------
extern "C" void kernel_launch(void* const* d_in, const int* in_sizes, int n_in,
                              void* d_out, int out_size) {
    const float* x      = (const float*)d_in[0];
    const float* t      = (const float*)d_in[1];
    const float* te_w1  = (const float*)d_in[2];
    const float* te_b1  = (const float*)d_in[3];
    const float* te_w2  = (const float*)d_in[4];
    const float* te_b2  = (const float*)d_in[5];
    const float* fproj_w= (const float*)d_in[6];
    const float* fproj_b= (const float*)d_in[7];
    const float* bproj_w= (const float*)d_in[8];
    const float* bproj_b= (const float*)d_in[9];
    const float* fz_w   = (const float*)d_in[10];
    const float* fz_b   = (const float*)d_in[11];
    const float* fh_w   = (const float*)d_in[12];
    const float* fh_b   = (const float*)d_in[13];
    const float* bz_w   = (const float*)d_in[14];
    const float* bz_b   = (const float*)d_in[15];
    const float* bh_w   = (const float*)d_in[16];
    const float* bh_b   = (const float*)d_in[17];
    const float* ln_g   = (const float*)d_in[18];
    const float* ln_b   = (const float*)d_in[19];
    const float* tsc    = (const float*)d_in[20];
    const float* gh_w1  = (const float*)d_in[21];
    const float* gh_b1  = (const float*)d_in[22];
    const float* gh_w2  = (const float*)d_in[23];
    const float* gh_b2  = (const float*)d_in[24];
    float* out = (float*)d_out;

    // prepG placed 4th so ncu's fixed-skip capture profiles it this round.
    k_zero<<<(4*H_*IN_ + 255)/256, 256>>>();
    k_fold<<<dim3(4, 16), H_>>>(fz_w, fh_w, bz_w, bh_w, fz_b, fh_b, bz_b, bh_b,
                                fproj_w, fproj_b, bproj_w, bproj_b);
    k_te<<<NROW/256, 256>>>(x, t, te_w1, te_b1, te_w2, te_b2);
    k_prepG<<<24, HH_>>>(gh_w1, gh_b1, ln_g, ln_b, tsc);
    k_scanA01<<<dim3(2, B_, 2), H_>>>();
    k_live<<<dim3(B_, 2), H_>>>();
    k_scanA2<<<dim3(NC_-2, B_, 2), H_>>>();
    k_scanB1<<<dim3(B_, 2), H_>>>();
    k_scanC1<<<dim3(NC_, B_, 2), H_>>>();
    k_scanB2<<<dim3(B_, 2), H_>>>();
    k_scanC2<<<dim3(NC_, B_, 2), H_>>>();
    k_gemm3<<<NROW/GBM, 512>>>(gh_w2, gh_b2, out);
}

// round 15
// speedup vs baseline: 4.1268x; 1.0700x over previous
#include <cuda_runtime.h>
#include <cuda_fp16.h>
#include <math.h>
#include <stdint.h>

#define B_  16
#define L_  4096
#define H_  512
#define NT_ 8
#define IN_ 10
#define INP 12               // padded xc stride (48B rows -> LDS.128)
#define OUT_ 1032
#define KP   1056            // padded K (66 chunks of 16)
#define NCH16 66
#define HH_ 256
#define NC_ 16
#define CH_ 256
#define EPS_ 1e-5f
#define NROW (B_*L_)
#define NTILE (NROW/64)

// ---------------- device scratch (static, allocation-free) ----------------
__device__ float g_xc[(size_t)NROW*INP];            // pads [10],[11] stay 0
__device__ float g_F [(size_t)NROW*KP];             // features (dead regions stay 0)
__device__ float g_W [4][H_][IN_];
__device__ float g_bias[4][H_];
__device__ float g_P [2][B_][NC_][H_];              // chunk a-products (skipped stay 0)
__device__ float g_Ae[2][B_][NC_][H_];              // chunk-entry cumprod states
__device__ float g_Lc[2][B_][NC_][H_];
__device__ float g_Se[2][B_][NC_][H_];
__device__ __half g_Gh[(size_t)NCH16*32*128];       // B fp16 fragment-major (pads 0)
__device__ float g_sv[HH_];
__device__ float g_cv[HH_];
__device__ int   g_tilef[NTILE];                    // per-64-row-tile nonzero flags
__device__ int   g_live[2][B_];                     // per-(dir,b) liveness after 2 chunks

// ---------------- zero tile flags (preps now store directly) ----------------
__global__ void k_zero() {
    int i = blockIdx.x*blockDim.x + threadIdx.x;
    if (i < NTILE) g_tilef[i] = 0;
}

// ---------------- fold gate weights: warp-per-h, coalesced -----------------
// grid (4, 32), block 512 = 16 warps; warp w owns h = blockIdx.y*16 + w.
__global__ void k_fold(const float* __restrict__ fz, const float* __restrict__ fh,
                       const float* __restrict__ bz, const float* __restrict__ bh,
                       const float* __restrict__ fzb, const float* __restrict__ fhb,
                       const float* __restrict__ bzb, const float* __restrict__ bhb,
                       const float* __restrict__ fp, const float* __restrict__ fpb,
                       const float* __restrict__ bp, const float* __restrict__ bpb) {
    int p = blockIdx.x;
    int t = threadIdx.x;
    int warp = t >> 5, lane = t & 31;
    int h = blockIdx.y*16 + warp;
    const float* zw = (p==0)?fz:(p==1)?fh:(p==2)?bz:bh;
    const float* zb = (p==0)?fzb:(p==1)?fhb:(p==2)?bzb:bhb;
    const float* pw = (p<2)?fp:bp;
    const float* pb = (p<2)?fpb:bpb;
    __shared__ float spw[H_*IN_];   // 20KB
    __shared__ float spb[H_];
    for (int i=t; i<H_*IN_; i+=512) spw[i] = pw[i];
    for (int i=t; i<H_;     i+=512) spb[i] = pb[i];
    __syncthreads();
    float acc[IN_]; float ab = 0.f;
    #pragma unroll
    for (int i=0;i<IN_;i++) acc[i]=0.f;
    #pragma unroll 4
    for (int it=0; it<16; it++) {
        int d = it*32 + lane;                 // coalesced zw row read
        float w = __ldg(&zw[h*H_ + d]);
        #pragma unroll
        for (int i=0;i<IN_;i++) acc[i] += w*spw[d*IN_+i];
        ab += w*spb[d];
    }
    #pragma unroll
    for (int off=16; off>0; off>>=1) {
        #pragma unroll
        for (int i=0;i<IN_;i++) acc[i] += __shfl_down_sync(0xffffffffu, acc[i], off);
        ab += __shfl_down_sync(0xffffffffu, ab, off);
    }
    if (lane == 0) {
        #pragma unroll
        for (int i=0;i<IN_;i++) g_W[p][h][i] = acc[i];
        g_bias[p][h] = ab + zb[h];
    }
}

// ---------------- fold LN affine into gh_w1: block-per-k, coalesced --------
// grid 256, block 128: thread j-strided coalesced gw1 row read, block reduce.
__global__ void k_prepG(const float* __restrict__ gw1, const float* __restrict__ gb1,
                        const float* __restrict__ lng, const float* __restrict__ lnb,
                        const float* __restrict__ tscp) {
    int k = blockIdx.x;
    int t = threadIdx.x;
    float tsc = tscp[0];
    int nt = k >> 3, ng = k & 7;
    float s = 0.f, c = 0.f;
    for (int j=t; j<OUT_; j+=128) {
        float sc = (j >= OUT_-NT_) ? tsc : 1.0f;
        float w  = gw1[k*OUT_+j];             // coalesced across threads
        __half Gh = __float2half_rn(lng[j]*sc*w);
        int kt = j >> 4, kin = j & 15;
        int lane = ng*4 + ((kin & 7) >> 1);
        int reg = kin >> 3, hs = kin & 1;
        g_Gh[(((size_t)(kt*32 + nt)*32 + lane)*2 + reg)*2 + hs] = Gh;
        s += __half2float(Gh);
        c += lnb[j]*sc*w;
    }
    __shared__ float rs[128], rc[128];
    rs[t] = s; rc[t] = c;
    __syncthreads();
    #pragma unroll
    for (int off=64; off>0; off>>=1) {
        if (t < off) { rs[t] += rs[t+off]; rc[t] += rc[t+off]; }
        __syncthreads();
    }
    if (t == 0) { g_sv[k] = rs[0]; g_cv[k] = rc[0] + gb1[k]; }
}

// ---------------- time embedding + xc, te into F ---------------------------
__global__ void k_te(const float* __restrict__ x, const float* __restrict__ t,
                     const float* __restrict__ w1, const float* __restrict__ b1,
                     const float* __restrict__ w2, const float* __restrict__ b2) {
    int row = blockIdx.x*blockDim.x + threadIdx.x;
    if (row >= NROW) return;
    int b = row / L_;
    float ts = t[row] - t[b*L_];
    float r[NT_];
    #pragma unroll
    for (int j=0;j<NT_;j++) r[j] = fmaxf(ts*w1[j] + b1[j], 0.0f);
    float te[NT_];
    #pragma unroll
    for (int k=0;k<NT_;k++) {
        float a = b2[k];
        #pragma unroll
        for (int j=0;j<NT_;j++) a += r[j]*w2[k*NT_+j];
        te[k] = a;
    }
    float x0 = x[row*2+0], x1 = x[row*2+1];
    float* xr = g_xc + (size_t)row*INP;
    *(float4*)(xr+0) = make_float4(x0, x1, te[0], te[1]);
    *(float4*)(xr+4) = make_float4(te[2], te[3], te[4], te[5]);
    *(float4*)(xr+8) = make_float4(te[6], te[7], 0.f, 0.f);
    float* fte = g_F + (size_t)row*KP + (OUT_-NT_);
    *(float4*)(fte)     = make_float4(te[0], te[1], te[2], te[3]);
    *(float4*)(fte + 4) = make_float4(te[4], te[5], te[6], te[7]);
}

// fast sigmoid pieces (full: z and 1-z)
__device__ __forceinline__ void fsig(float arg, float& z, float& omz) {
    float e = __expf(-arg);
    z = __fdividef(1.0f, 1.0f + e);
    omz = e * z;
}

// vectorized dot-10 against padded 48B row (order identical to scalar loop)
__device__ __forceinline__ float dot10(const float* xr, const float* w, float b) {
    float4 v0 = *(const float4*)(xr);
    float4 v1 = *(const float4*)(xr+4);
    float2 v2 = *(const float2*)(xr+8);
    float a = b;
    a += v0.x*w[0]; a += v0.y*w[1]; a += v0.z*w[2]; a += v0.w*w[3];
    a += v1.x*w[4]; a += v1.y*w[5]; a += v1.z*w[6]; a += v1.w*w[7];
    a += v2.x*w[8]; a += v2.y*w[9];
    return a;
}
__device__ __forceinline__ void dot10x2(const float* xr, const float* wz, float bz,
                                        const float* wh, float bh, float& az, float& ah) {
    float4 v0 = *(const float4*)(xr);
    float4 v1 = *(const float4*)(xr+4);
    float2 v2 = *(const float2*)(xr+8);
    float a = bz, c = bh;
    a += v0.x*wz[0]; a += v0.y*wz[1]; a += v0.z*wz[2]; a += v0.w*wz[3];
    a += v1.x*wz[4]; a += v1.y*wz[5]; a += v1.z*wz[6]; a += v1.w*wz[7];
    a += v2.x*wz[8]; a += v2.y*wz[9];
    c += v0.x*wh[0]; c += v0.y*wh[1]; c += v0.z*wh[2]; c += v0.w*wh[3];
    c += v1.x*wh[4]; c += v1.y*wh[5]; c += v1.z*wh[6]; c += v1.w*wh[7];
    c += v2.x*wh[8]; c += v2.y*wh[9];
    az = a; ah = c;
}

// common scanA body: chunk product for actual chunk c
__device__ __forceinline__ void scanA_body(int c, int b, int dir, int h) {
    __shared__ float xs[CH_][INP];
    const float4* xc4 = (const float4*)(g_xc + ((size_t)b*L_ + (size_t)c*CH_)*INP);
    for (int i=h; i<CH_*3; i+=H_) ((float4*)xs)[i] = xc4[i];
    float wz[IN_]; float bz;
    int pz = dir*2;
    #pragma unroll
    for (int i=0;i<IN_;i++) wz[i] = g_W[pz][h][i];
    bz = g_bias[pz][h];
    __syncthreads();
    float A = 1.0f;
    int s0 = (dir==0)? 0 : CH_-1;
    int ds = (dir==0)? 1 : -1;
    #pragma unroll 4
    for (int k=0;k<CH_;k++) {
        int s = s0 + k*ds;
        float arg = dot10(&xs[s][0], wz, bz);
        float e2 = __expf(arg);                 // omz = 1/(1+e^{arg})
        A *= __fdividef(1.0f, 1.0f + e2);
    }
    g_P[dir][b][c][h] = A;
}

// ---------------- scanA phase 1: first 2 scan-order chunks -----------------
// (launched 4th so ncu's fixed-skip capture lands here)
__global__ void k_scanA01() {
    int cs = blockIdx.x, b = blockIdx.y, dir = blockIdx.z;      // cs in {0,1}
    int c = dir ? (NC_-1-cs) : cs;
    scanA_body(c, b, dir, threadIdx.x);
}

// ---------------- liveness after 2 chunks: OR_h (P0*P1 != 0) ---------------
__global__ void k_live() {
    int b = blockIdx.x, dir = blockIdx.y, h = threadIdx.x;
    int c0 = dir ? NC_-1 : 0;
    int c1 = dir ? NC_-2 : 1;
    float p = g_P[dir][b][c0][h] * g_P[dir][b][c1][h];  // == B1's run after 2 chunks
    int lv = __syncthreads_or(p != 0.f);
    if (h == 0) g_live[dir][b] = lv;
}

// ---------------- scanA phase 2: remaining chunks, only if live ------------
__global__ void k_scanA2() {
    int cs = blockIdx.x + 2, b = blockIdx.y, dir = blockIdx.z;  // cs in {2..15}
    if (!g_live[dir][b]) return;        // uniform: skipped P stays 0, multiplied into 0-run
    int c = dir ? (NC_-1-cs) : cs;
    scanA_body(c, b, dir, threadIdx.x);
}

// ---------------- scan pass B1: chunk-entry cumprod states -----------------
__global__ void k_scanB1() {
    int b = blockIdx.x, dir = blockIdx.y, h = threadIdx.x;
    float run = 1.0f;
    if (dir==0) { for (int c=0;c<NC_;c++)    { g_Ae[0][b][c][h]=run; run *= g_P[0][b][c][h]; } }
    else        { for (int c=NC_-1;c>=0;c--) { g_Ae[1][b][c][h]=run; run *= g_P[1][b][c][h]; } }
}

// ---------------- scan pass C1: chunk local sums (block skip) --------------
__global__ void k_scanC1() {
    int c = blockIdx.x, b = blockIdx.y, dir = blockIdx.z;
    int h = threadIdx.x;
    __shared__ float xs[CH_][INP];
    float A = g_Ae[dir][b][c][h];
    if (!__syncthreads_or(A != 0.f)) { g_Lc[dir][b][c][h] = 0.f; return; }
    const float4* xc4 = (const float4*)(g_xc + ((size_t)b*L_ + (size_t)c*CH_)*INP);
    for (int i=h; i<CH_*3; i+=H_) ((float4*)xs)[i] = xc4[i];
    float wz[IN_], wh[IN_]; float bz, bh;
    int pz = dir*2, ph = dir*2+1;
    #pragma unroll
    for (int i=0;i<IN_;i++) { wz[i]=g_W[pz][h][i]; wh[i]=g_W[ph][h][i]; }
    bz = g_bias[pz][h]; bh = g_bias[ph][h];
    __syncthreads();
    float Ls = 0.0f;
    int s0  = (dir==0)? 0 : CH_-1;
    int ds  = (dir==0)? 1 : -1;
    #pragma unroll 4
    for (int k=0;k<CH_;k++) {
        int s = s0 + k*ds;
        float az, ah;
        dot10x2(&xs[s][0], wz, bz, wh, bh, az, ah);
        float z, omz; fsig(az, z, omz);
        A *= omz;
        Ls += __fdividef(z*ah, fmaxf(A, 1e-12f));
    }
    g_Lc[dir][b][c][h] = Ls;
}

// ---------------- scan pass B2: chunk-entry cumsum states ------------------
__global__ void k_scanB2() {
    int b = blockIdx.x, dir = blockIdx.y, h = threadIdx.x;
    float run = 0.0f;
    if (dir==0) { for (int c=0;c<NC_;c++)    { g_Se[0][b][c][h]=run; run += g_Lc[0][b][c][h]; } }
    else        { for (int c=NC_-1;c>=0;c--) { g_Se[1][b][c][h]=run; run += g_Lc[1][b][c][h]; } }
}

// ---------------- scan pass C2: emit h = A*S -------------------------------
__global__ void k_scanC2() {
    int c = blockIdx.x, b = blockIdx.y, dir = blockIdx.z;
    int h = threadIdx.x;
    __shared__ float xs[CH_][INP];
    float A = g_Ae[dir][b][c][h];
    if (!__syncthreads_or(A != 0.f)) return;    // region stays exact 0
    const float4* xc4 = (const float4*)(g_xc + ((size_t)b*L_ + (size_t)c*CH_)*INP);
    for (int i=h; i<CH_*3; i+=H_) ((float4*)xs)[i] = xc4[i];
    float wz[IN_], wh[IN_]; float bz, bh;
    int pz = dir*2, ph = dir*2+1;
    #pragma unroll
    for (int i=0;i<IN_;i++) { wz[i]=g_W[pz][h][i]; wh[i]=g_W[ph][h][i]; }
    bz = g_bias[pz][h]; bh = g_bias[ph][h];
    float S = g_Se[dir][b][c][h];
    __syncthreads();
    int s0  = (dir==0)? 0 : CH_-1;
    int ds  = (dir==0)? 1 : -1;
    size_t fofs = (dir==0)? (size_t)h : (size_t)(H_ + h);
    float* fp = g_F + ((size_t)(b*L_ + c*CH_ + s0))*KP + fofs;
    ptrdiff_t fstep = (ptrdiff_t)ds * KP;
    int zstep = 0;
    #pragma unroll 4
    for (int k=0;k<CH_;k++) {
        int s = s0 + k*ds;
        if (A != 0.f) zstep = k+1;              // predicated select, no branch
        *fp = A*S;                              // state BEFORE consuming position
        fp += fstep;
        float az, ah;
        dot10x2(&xs[s][0], wz, bz, wh, bh, az, ah);
        float z, omz; fsig(az, z, omz);
        A *= omz;
        S += __fdividef(z*ah, fmaxf(A, 1e-12f));
    }
    // tile flags: fwd writes ascending from chunk start; bwd descending from end
    int tile0 = (b*L_ + c*CH_) >> 6;
    #pragma unroll
    for (int ti=0; ti<4; ti++) {
        int thr = (dir==0) ? ti*64 : (192 - ti*64);
        int ta = __syncthreads_or(zstep > thr);
        if (ta && h == 0) atomicOr(&g_tilef[tile0 + ti], 1 << dir);
    }
}

// ---------------- fp16 mma GEMM (smem-staged B, contiguous live range) -----
#define GBM 64
__global__ __launch_bounds__(512, 1) void k_gemm3(const float* __restrict__ w2,
                                                  const float* __restrict__ b2p,
                                                  float* __restrict__ out) {
    __shared__ float s_s[HH_], s_c[HH_], s_w2[HH_];
    __shared__ float s_sum[GBM], s_sq[GBM];
    __shared__ float s_mu[GBM], s_rs[GBM];
    __shared__ float s_part[GBM][4];
    __shared__ uint2 sB[2][1024];               // double-buffered B chunk (8KB x2)

    int t = threadIdx.x;
    int lane = t & 31, warp = t >> 5;
    int wm = warp >> 2, wn = warp & 3;          // 4m x 4n warp grid
    int g  = lane >> 2, tig = lane & 3;
    int row0 = blockIdx.x * GBM;
    int r0 = row0 + wm*16 + g;

    if (t < HH_) { s_s[t] = g_sv[t]; s_c[t] = g_cv[t]; s_w2[t] = w2[t]; }

    int flag = g_tilef[blockIdx.x] & 3;
    int c0 = (flag & 1) ? 0 : 32;               // contiguous live chunk range start
    int n  = (flag == 3) ? 64 : (flag ? 32 : 0);
    int total = n + 1;                          // + te chunk (64)

    float acc[8][4];
    #pragma unroll
    for (int i=0;i<8;i++) { acc[i][0]=0.f; acc[i][1]=0.f; acc[i][2]=0.f; acc[i][3]=0.f; }

    const float* Ar0 = g_F + (size_t)r0*KP     + tig*2;
    const float* Ar8 = Ar0 + 8*KP;
    const uint2* Ghu2 = (const uint2*)g_Gh;

    int ci = (0 < n) ? c0 : 64;
    float2 fA0 = __ldg((const float2*)(Ar0 + ci*16));
    float2 fA1 = __ldg((const float2*)(Ar8 + ci*16));
    float2 fA2 = __ldg((const float2*)(Ar0 + ci*16 + 8));
    float2 fA3 = __ldg((const float2*)(Ar8 + ci*16 + 8));
    {
        const uint2* Bn = Ghu2 + (size_t)ci*1024;
        sB[0][t]       = __ldg(Bn + t);
        sB[0][t + 512] = __ldg(Bn + t + 512);
    }
    __syncthreads();

    float ps0=0.f, pq0=0.f, ps1=0.f, pq1=0.f;
    int cur = 0;

    for (int it=0; it<total; it++) {
        uint2 fB[8];
        #pragma unroll
        for (int nt=0; nt<8; nt++) fB[nt] = sB[cur][wn*256 + nt*32 + lane];
        if (wn == 0) {
            ps0 += fA0.x+fA0.y+fA2.x+fA2.y;
            pq0 += fA0.x*fA0.x + fA0.y*fA0.y + fA2.x*fA2.x + fA2.y*fA2.y;
            ps1 += fA1.x+fA1.y+fA3.x+fA3.y;
            pq1 += fA1.x*fA1.x + fA1.y*fA1.y + fA3.x*fA3.x + fA3.y*fA3.y;
        }
        __half2 h0 = __floats2half2_rn(fA0.x, fA0.y);
        __half2 h1 = __floats2half2_rn(fA1.x, fA1.y);
        __half2 h2 = __floats2half2_rn(fA2.x, fA2.y);
        __half2 h3 = __floats2half2_rn(fA3.x, fA3.y);
        uint32_t a0 = *reinterpret_cast<uint32_t*>(&h0);
        uint32_t a1 = *reinterpret_cast<uint32_t*>(&h1);
        uint32_t a2 = *reinterpret_cast<uint32_t*>(&h2);
        uint32_t a3 = *reinterpret_cast<uint32_t*>(&h3);
        #pragma unroll
        for (int nt=0; nt<8; nt++) {
            asm volatile(
                "mma.sync.aligned.m16n8k16.row.col.f32.f16.f16.f32 "
                "{%0,%1,%2,%3}, {%4,%5,%6,%7}, {%8,%9}, {%0,%1,%2,%3};"
                : "+f"(acc[nt][0]), "+f"(acc[nt][1]), "+f"(acc[nt][2]), "+f"(acc[nt][3])
                : "r"(a0), "r"(a1), "r"(a2), "r"(a3), "r"(fB[nt].x), "r"(fB[nt].y));
        }
        if (it+1 < total) {
            int itn = it+1;
            ci = (itn < n) ? (c0 + itn) : 64;   // branchless select
            const uint2* Bn = Ghu2 + (size_t)ci*1024;
            sB[cur^1][t]       = __ldg(Bn + t);
            sB[cur^1][t + 512] = __ldg(Bn + t + 512);
            fA0 = __ldg((const float2*)(Ar0 + ci*16));
            fA1 = __ldg((const float2*)(Ar8 + ci*16));
            fA2 = __ldg((const float2*)(Ar0 + ci*16 + 8));
            fA3 = __ldg((const float2*)(Ar8 + ci*16 + 8));
        }
        __syncthreads();
        cur ^= 1;
    }

    if (wn == 0) {
        #pragma unroll
        for (int off=1; off<4; off<<=1) {
            ps0 += __shfl_xor_sync(0xffffffffu, ps0, off);
            pq0 += __shfl_xor_sync(0xffffffffu, pq0, off);
            ps1 += __shfl_xor_sync(0xffffffffu, ps1, off);
            pq1 += __shfl_xor_sync(0xffffffffu, pq1, off);
        }
        if (tig == 0) {
            s_sum[wm*16+g]   = ps0;  s_sq[wm*16+g]   = pq0;
            s_sum[wm*16+g+8] = ps1;  s_sq[wm*16+g+8] = pq1;
        }
    }
    __syncthreads();
    if (t < GBM) {
        float m = s_sum[t] * (1.0f/(float)OUT_);
        float v = s_sq[t]  * (1.0f/(float)OUT_) - m*m;
        s_mu[t] = m;
        s_rs[t] = rsqrtf(v + EPS_);
    }
    __syncthreads();

    float mu0 = s_mu[wm*16+g],   rs0 = s_rs[wm*16+g];
    float mu1 = s_mu[wm*16+g+8], rs1 = s_rs[wm*16+g+8];
    float po0 = 0.f, po1 = 0.f;
    #pragma unroll
    for (int nt=0; nt<8; nt++) {
        #pragma unroll
        for (int e=0; e<2; e++) {
            int col = wn*64 + nt*8 + tig*2 + e;
            float sS = s_s[col], sC = s_c[col], wv = s_w2[col];
            float v0 = (acc[nt][e]   - mu0*sS)*rs0 + sC;
            float v1 = (acc[nt][2+e] - mu1*sS)*rs1 + sC;
            float h0 = 0.5f*v0*(1.0f + erff(v0*0.70710678118654752440f));
            float h1 = 0.5f*v1*(1.0f + erff(v1*0.70710678118654752440f));
            po0 += h0*wv;
            po1 += h1*wv;
        }
    }
    #pragma unroll
    for (int off=1; off<4; off<<=1) {
        po0 += __shfl_xor_sync(0xffffffffu, po0, off);
        po1 += __shfl_xor_sync(0xffffffffu, po1, off);
    }
    if (tig == 0) {
        s_part[wm*16+g][wn]   = po0;
        s_part[wm*16+g+8][wn] = po1;
    }
    __syncthreads();
    if (t < GBM) {
        out[row0 + t] = b2p[0] + s_part[t][0] + s_part[t][1] + s_part[t][2] + s_part[t][3];
    }
}

// ---------------- launch ---------------------------------------------------
extern "C" void kernel_launch(void* const* d_in, const int* in_sizes, int n_in,
                              void* d_out, int out_size) {
    const float* x      = (const float*)d_in[0];
    const float* t      = (const float*)d_in[1];
    const float* te_w1  = (const float*)d_in[2];
    const float* te_b1  = (const float*)d_in[3];
    const float* te_w2  = (const float*)d_in[4];
    const float* te_b2  = (const float*)d_in[5];
    const float* fproj_w= (const float*)d_in[6];
    const float* fproj_b= (const float*)d_in[7];
    const float* bproj_w= (const float*)d_in[8];
    const float* bproj_b= (const float*)d_in[9];
    const float* fz_w   = (const float*)d_in[10];
    const float* fz_b   = (const float*)d_in[11];
    const float* fh_w   = (const float*)d_in[12];
    const float* fh_b   = (const float*)d_in[13];
    const float* bz_w   = (const float*)d_in[14];
    const float* bz_b   = (const float*)d_in[15];
    const float* bh_w   = (const float*)d_in[16];
    const float* bh_b   = (const float*)d_in[17];
    const float* ln_g   = (const float*)d_in[18];
    const float* ln_b   = (const float*)d_in[19];
    const float* tsc    = (const float*)d_in[20];
    const float* gh_w1  = (const float*)d_in[21];
    const float* gh_b1  = (const float*)d_in[22];
    const float* gh_w2  = (const float*)d_in[23];
    const float* gh_b2  = (const float*)d_in[24];
    float* out = (float*)d_out;

    // scanA01 placed 4th so ncu's fixed-skip capture profiles it this round.
    k_zero<<<4, 256>>>();
    k_fold<<<dim3(4, 32), 512>>>(fz_w, fh_w, bz_w, bh_w, fz_b, fh_b, bz_b, bh_b,
                                 fproj_w, fproj_b, bproj_w, bproj_b);
    k_te<<<NROW/256, 256>>>(x, t, te_w1, te_b1, te_w2, te_b2);
    k_scanA01<<<dim3(2, B_, 2), H_>>>();
    k_live<<<dim3(B_, 2), H_>>>();
    k_scanA2<<<dim3(NC_-2, B_, 2), H_>>>();
    k_prepG<<<HH_, 128>>>(gh_w1, gh_b1, ln_g, ln_b, tsc);
    k_scanB1<<<dim3(B_, 2), H_>>>();
    k_scanC1<<<dim3(NC_, B_, 2), H_>>>();
    k_scanB2<<<dim3(B_, 2), H_>>>();
    k_scanC2<<<dim3(NC_, B_, 2), H_>>>();
    k_gemm3<<<NROW/GBM, 512>>>(gh_w2, gh_b2, out);
}

// round 16
// speedup vs baseline: 6.3310x; 1.5341x over previous
#include <cuda_runtime.h>
#include <cuda_fp16.h>
#include <math.h>
#include <stdint.h>

#define B_  16
#define L_  4096
#define H_  512
#define NT_ 8
#define IN_ 10
#define INP 12               // padded xc stride (48B rows -> LDS.128)
#define OUT_ 1032
#define KP   1056            // padded K (66 chunks of 16)
#define NCH16 66
#define HH_ 256
#define NC_ 64               // 64 chunks of 64 (was 16 x 256)
#define CH_ 64
#define NLIVE 8              // liveness window = 8 chunks = 512 steps
#define EPS_ 1e-5f
#define NROW (B_*L_)
#define NTILE (NROW/64)

// ---------------- device scratch (static, allocation-free) ----------------
__device__ float g_xc[(size_t)NROW*INP];            // pads [10],[11] stay 0
__device__ float g_F [(size_t)NROW*KP];             // features (dead regions stay 0)
__device__ float g_W [4][H_][IN_];
__device__ float g_bias[4][H_];
__device__ float g_P [2][B_][NC_][H_];              // chunk a-products (skipped stay 0)
__device__ float g_Ae[2][B_][NC_][H_];              // chunk-entry cumprod states
__device__ float g_Lc[2][B_][NC_][H_];
__device__ float g_Se[2][B_][NC_][H_];
__device__ __half g_Gh[(size_t)NCH16*32*128];       // B fp16 fragment-major (pads 0)
__device__ float g_sv[HH_];
__device__ float g_cv[HH_];
__device__ int   g_tilef[NTILE];                    // per-64-row-tile nonzero flags
__device__ int   g_live[2][B_];                     // per-(dir,b) liveness after NLIVE chunks

// ---------------- zero tile flags ------------------------------------------
__global__ void k_zero() {
    int i = blockIdx.x*blockDim.x + threadIdx.x;
    if (i < NTILE) g_tilef[i] = 0;
}

// ---------------- fold gate weights: warp-per-h, coalesced -----------------
__global__ void k_fold(const float* __restrict__ fz, const float* __restrict__ fh,
                       const float* __restrict__ bz, const float* __restrict__ bh,
                       const float* __restrict__ fzb, const float* __restrict__ fhb,
                       const float* __restrict__ bzb, const float* __restrict__ bhb,
                       const float* __restrict__ fp, const float* __restrict__ fpb,
                       const float* __restrict__ bp, const float* __restrict__ bpb) {
    int p = blockIdx.x;
    int t = threadIdx.x;
    int warp = t >> 5, lane = t & 31;
    int h = blockIdx.y*16 + warp;
    const float* zw = (p==0)?fz:(p==1)?fh:(p==2)?bz:bh;
    const float* zb = (p==0)?fzb:(p==1)?fhb:(p==2)?bzb:bhb;
    const float* pw = (p<2)?fp:bp;
    const float* pb = (p<2)?fpb:bpb;
    __shared__ float spw[H_*IN_];   // 20KB
    __shared__ float spb[H_];
    for (int i=t; i<H_*IN_; i+=512) spw[i] = pw[i];
    for (int i=t; i<H_;     i+=512) spb[i] = pb[i];
    __syncthreads();
    float acc[IN_]; float ab = 0.f;
    #pragma unroll
    for (int i=0;i<IN_;i++) acc[i]=0.f;
    #pragma unroll 4
    for (int it=0; it<16; it++) {
        int d = it*32 + lane;                 // coalesced zw row read
        float w = __ldg(&zw[h*H_ + d]);
        #pragma unroll
        for (int i=0;i<IN_;i++) acc[i] += w*spw[d*IN_+i];
        ab += w*spb[d];
    }
    #pragma unroll
    for (int off=16; off>0; off>>=1) {
        #pragma unroll
        for (int i=0;i<IN_;i++) acc[i] += __shfl_down_sync(0xffffffffu, acc[i], off);
        ab += __shfl_down_sync(0xffffffffu, ab, off);
    }
    if (lane == 0) {
        #pragma unroll
        for (int i=0;i<IN_;i++) g_W[p][h][i] = acc[i];
        g_bias[p][h] = ab + zb[h];
    }
}

// ---------------- fold LN affine into gh_w1: block-per-k, coalesced --------
__global__ void k_prepG(const float* __restrict__ gw1, const float* __restrict__ gb1,
                        const float* __restrict__ lng, const float* __restrict__ lnb,
                        const float* __restrict__ tscp) {
    int k = blockIdx.x;
    int t = threadIdx.x;
    float tsc = tscp[0];
    int nt = k >> 3, ng = k & 7;
    float s = 0.f, c = 0.f;
    for (int j=t; j<OUT_; j+=128) {
        float sc = (j >= OUT_-NT_) ? tsc : 1.0f;
        float w  = gw1[k*OUT_+j];             // coalesced across threads
        __half Gh = __float2half_rn(lng[j]*sc*w);
        int kt = j >> 4, kin = j & 15;
        int lane = ng*4 + ((kin & 7) >> 1);
        int reg = kin >> 3, hs = kin & 1;
        g_Gh[(((size_t)(kt*32 + nt)*32 + lane)*2 + reg)*2 + hs] = Gh;
        s += __half2float(Gh);
        c += lnb[j]*sc*w;
    }
    __shared__ float rs[128], rc[128];
    rs[t] = s; rc[t] = c;
    __syncthreads();
    #pragma unroll
    for (int off=64; off>0; off>>=1) {
        if (t < off) { rs[t] += rs[t+off]; rc[t] += rc[t+off]; }
        __syncthreads();
    }
    if (t == 0) { g_sv[k] = rs[0]; g_cv[k] = rc[0] + gb1[k]; }
}

// ---------------- time embedding + xc, te into F ---------------------------
__global__ void k_te(const float* __restrict__ x, const float* __restrict__ t,
                     const float* __restrict__ w1, const float* __restrict__ b1,
                     const float* __restrict__ w2, const float* __restrict__ b2) {
    int row = blockIdx.x*blockDim.x + threadIdx.x;
    if (row >= NROW) return;
    int b = row / L_;
    float ts = t[row] - t[b*L_];
    float r[NT_];
    #pragma unroll
    for (int j=0;j<NT_;j++) r[j] = fmaxf(ts*w1[j] + b1[j], 0.0f);
    float te[NT_];
    #pragma unroll
    for (int k=0;k<NT_;k++) {
        float a = b2[k];
        #pragma unroll
        for (int j=0;j<NT_;j++) a += r[j]*w2[k*NT_+j];
        te[k] = a;
    }
    float x0 = x[row*2+0], x1 = x[row*2+1];
    float* xr = g_xc + (size_t)row*INP;
    *(float4*)(xr+0) = make_float4(x0, x1, te[0], te[1]);
    *(float4*)(xr+4) = make_float4(te[2], te[3], te[4], te[5]);
    *(float4*)(xr+8) = make_float4(te[6], te[7], 0.f, 0.f);
    float* fte = g_F + (size_t)row*KP + (OUT_-NT_);
    *(float4*)(fte)     = make_float4(te[0], te[1], te[2], te[3]);
    *(float4*)(fte + 4) = make_float4(te[4], te[5], te[6], te[7]);
}

// fast sigmoid pieces (full: z and 1-z)
__device__ __forceinline__ void fsig(float arg, float& z, float& omz) {
    float e = __expf(-arg);
    z = __fdividef(1.0f, 1.0f + e);
    omz = e * z;
}

// vectorized dot-10 against padded 48B row (order identical to scalar loop)
__device__ __forceinline__ float dot10(const float* xr, const float* w, float b) {
    float4 v0 = *(const float4*)(xr);
    float4 v1 = *(const float4*)(xr+4);
    float2 v2 = *(const float2*)(xr+8);
    float a = b;
    a += v0.x*w[0]; a += v0.y*w[1]; a += v0.z*w[2]; a += v0.w*w[3];
    a += v1.x*w[4]; a += v1.y*w[5]; a += v1.z*w[6]; a += v1.w*w[7];
    a += v2.x*w[8]; a += v2.y*w[9];
    return a;
}
__device__ __forceinline__ void dot10x2(const float* xr, const float* wz, float bz,
                                        const float* wh, float bh, float& az, float& ah) {
    float4 v0 = *(const float4*)(xr);
    float4 v1 = *(const float4*)(xr+4);
    float2 v2 = *(const float2*)(xr+8);
    float a = bz, c = bh;
    a += v0.x*wz[0]; a += v0.y*wz[1]; a += v0.z*wz[2]; a += v0.w*wz[3];
    a += v1.x*wz[4]; a += v1.y*wz[5]; a += v1.z*wz[6]; a += v1.w*wz[7];
    a += v2.x*wz[8]; a += v2.y*wz[9];
    c += v0.x*wh[0]; c += v0.y*wh[1]; c += v0.z*wh[2]; c += v0.w*wh[3];
    c += v1.x*wh[4]; c += v1.y*wh[5]; c += v1.z*wh[6]; c += v1.w*wh[7];
    c += v2.x*wh[8]; c += v2.y*wh[9];
    az = a; ah = c;
}

// common scanA body: chunk product for actual chunk c
__device__ __forceinline__ void scanA_body(int c, int b, int dir, int h) {
    __shared__ float xs[CH_][INP];
    const float4* xc4 = (const float4*)(g_xc + ((size_t)b*L_ + (size_t)c*CH_)*INP);
    for (int i=h; i<CH_*3; i+=H_) ((float4*)xs)[i] = xc4[i];
    float wz[IN_]; float bz;
    int pz = dir*2;
    #pragma unroll
    for (int i=0;i<IN_;i++) wz[i] = g_W[pz][h][i];
    bz = g_bias[pz][h];
    __syncthreads();
    float A = 1.0f;
    int s0 = (dir==0)? 0 : CH_-1;
    int ds = (dir==0)? 1 : -1;
    #pragma unroll 4
    for (int k=0;k<CH_;k++) {
        int s = s0 + k*ds;
        float arg = dot10(&xs[s][0], wz, bz);
        float e2 = __expf(arg);                 // omz = 1/(1+e^{arg})
        A *= __fdividef(1.0f, 1.0f + e2);
    }
    g_P[dir][b][c][h] = A;
}

// ---------------- scanA phase 1: first NLIVE scan-order chunks -------------
// (launched 4th so ncu's fixed-skip capture lands here)
__global__ void k_scanA01() {
    int cs = blockIdx.x, b = blockIdx.y, dir = blockIdx.z;      // cs in {0..NLIVE-1}
    int c = dir ? (NC_-1-cs) : cs;
    scanA_body(c, b, dir, threadIdx.x);
}

// ---------------- liveness after NLIVE chunks ------------------------------
__global__ void k_live() {
    int b = blockIdx.x, dir = blockIdx.y, h = threadIdx.x;
    float p = 1.0f;
    #pragma unroll
    for (int cs=0; cs<NLIVE; cs++) {
        int c = dir ? (NC_-1-cs) : cs;
        p *= g_P[dir][b][c][h];                 // == B1's run after NLIVE chunks
    }
    int lv = __syncthreads_or(p != 0.f);
    if (h == 0) g_live[dir][b] = lv;
}

// ---------------- scanA phase 2: remaining chunks, only if live ------------
__global__ void k_scanA2() {
    int cs = blockIdx.x + NLIVE, b = blockIdx.y, dir = blockIdx.z;
    if (!g_live[dir][b]) return;        // uniform: skipped P stays 0, multiplied into 0-run
    int c = dir ? (NC_-1-cs) : cs;
    scanA_body(c, b, dir, threadIdx.x);
}

// ---------------- scan pass B1: chunk-entry cumprod states -----------------
__global__ void k_scanB1() {
    int b = blockIdx.x, dir = blockIdx.y, h = threadIdx.x;
    float run = 1.0f;
    if (dir==0) { for (int c=0;c<NC_;c++)    { g_Ae[0][b][c][h]=run; run *= g_P[0][b][c][h]; } }
    else        { for (int c=NC_-1;c>=0;c--) { g_Ae[1][b][c][h]=run; run *= g_P[1][b][c][h]; } }
}

// ---------------- scan pass C1: chunk local sums (block skip) --------------
__global__ void k_scanC1() {
    int c = blockIdx.x, b = blockIdx.y, dir = blockIdx.z;
    int h = threadIdx.x;
    __shared__ float xs[CH_][INP];
    float A = g_Ae[dir][b][c][h];
    if (!__syncthreads_or(A != 0.f)) { g_Lc[dir][b][c][h] = 0.f; return; }
    const float4* xc4 = (const float4*)(g_xc + ((size_t)b*L_ + (size_t)c*CH_)*INP);
    for (int i=h; i<CH_*3; i+=H_) ((float4*)xs)[i] = xc4[i];
    float wz[IN_], wh[IN_]; float bz, bh;
    int pz = dir*2, ph = dir*2+1;
    #pragma unroll
    for (int i=0;i<IN_;i++) { wz[i]=g_W[pz][h][i]; wh[i]=g_W[ph][h][i]; }
    bz = g_bias[pz][h]; bh = g_bias[ph][h];
    __syncthreads();
    float Ls = 0.0f;
    int s0  = (dir==0)? 0 : CH_-1;
    int ds  = (dir==0)? 1 : -1;
    #pragma unroll 4
    for (int k=0;k<CH_;k++) {
        int s = s0 + k*ds;
        float az, ah;
        dot10x2(&xs[s][0], wz, bz, wh, bh, az, ah);
        float z, omz; fsig(az, z, omz);
        A *= omz;
        Ls += __fdividef(z*ah, fmaxf(A, 1e-12f));
    }
    g_Lc[dir][b][c][h] = Ls;
}

// ---------------- scan pass B2: chunk-entry cumsum states ------------------
__global__ void k_scanB2() {
    int b = blockIdx.x, dir = blockIdx.y, h = threadIdx.x;
    float run = 0.0f;
    if (dir==0) { for (int c=0;c<NC_;c++)    { g_Se[0][b][c][h]=run; run += g_Lc[0][b][c][h]; } }
    else        { for (int c=NC_-1;c>=0;c--) { g_Se[1][b][c][h]=run; run += g_Lc[1][b][c][h]; } }
}

// ---------------- scan pass C2: emit h = A*S (1 chunk == 1 tile) -----------
__global__ void k_scanC2() {
    int c = blockIdx.x, b = blockIdx.y, dir = blockIdx.z;
    int h = threadIdx.x;
    __shared__ float xs[CH_][INP];
    float A = g_Ae[dir][b][c][h];
    if (!__syncthreads_or(A != 0.f)) return;    // region stays exact 0
    const float4* xc4 = (const float4*)(g_xc + ((size_t)b*L_ + (size_t)c*CH_)*INP);
    for (int i=h; i<CH_*3; i+=H_) ((float4*)xs)[i] = xc4[i];
    float wz[IN_], wh[IN_]; float bz, bh;
    int pz = dir*2, ph = dir*2+1;
    #pragma unroll
    for (int i=0;i<IN_;i++) { wz[i]=g_W[pz][h][i]; wh[i]=g_W[ph][h][i]; }
    bz = g_bias[pz][h]; bh = g_bias[ph][h];
    float S = g_Se[dir][b][c][h];
    __syncthreads();
    int s0  = (dir==0)? 0 : CH_-1;
    int ds  = (dir==0)? 1 : -1;
    size_t fofs = (dir==0)? (size_t)h : (size_t)(H_ + h);
    float* fp = g_F + ((size_t)(b*L_ + c*CH_ + s0))*KP + fofs;
    ptrdiff_t fstep = (ptrdiff_t)ds * KP;
    int zstep = 0;
    #pragma unroll 4
    for (int k=0;k<CH_;k++) {
        int s = s0 + k*ds;
        if (A != 0.f) zstep = k+1;              // predicated select, no branch
        *fp = A*S;                              // state BEFORE consuming position
        fp += fstep;
        float az, ah;
        dot10x2(&xs[s][0], wz, bz, wh, bh, az, ah);
        float z, omz; fsig(az, z, omz);
        A *= omz;
        S += __fdividef(z*ah, fmaxf(A, 1e-12f));
    }
    // this chunk IS one 64-row tile
    int ta = __syncthreads_or(zstep > 0);
    if (ta && h == 0) atomicOr(&g_tilef[(b*L_ + c*CH_) >> 6], 1 << dir);
}

// ---------------- fp16 mma GEMM (smem-staged B, contiguous live range) -----
#define GBM 64
__global__ __launch_bounds__(512, 1) void k_gemm3(const float* __restrict__ w2,
                                                  const float* __restrict__ b2p,
                                                  float* __restrict__ out) {
    __shared__ float s_s[HH_], s_c[HH_], s_w2[HH_];
    __shared__ float s_sum[GBM], s_sq[GBM];
    __shared__ float s_mu[GBM], s_rs[GBM];
    __shared__ float s_part[GBM][4];
    __shared__ uint2 sB[2][1024];               // double-buffered B chunk (8KB x2)

    int t = threadIdx.x;
    int lane = t & 31, warp = t >> 5;
    int wm = warp >> 2, wn = warp & 3;          // 4m x 4n warp grid
    int g  = lane >> 2, tig = lane & 3;
    int row0 = blockIdx.x * GBM;
    int r0 = row0 + wm*16 + g;

    if (t < HH_) { s_s[t] = g_sv[t]; s_c[t] = g_cv[t]; s_w2[t] = w2[t]; }

    int flag = g_tilef[blockIdx.x] & 3;
    int c0 = (flag & 1) ? 0 : 32;               // contiguous live chunk range start
    int n  = (flag == 3) ? 64 : (flag ? 32 : 0);
    int total = n + 1;                          // + te chunk (64)

    float acc[8][4];
    #pragma unroll
    for (int i=0;i<8;i++) { acc[i][0]=0.f; acc[i][1]=0.f; acc[i][2]=0.f; acc[i][3]=0.f; }

    const float* Ar0 = g_F + (size_t)r0*KP     + tig*2;
    const float* Ar8 = Ar0 + 8*KP;
    const uint2* Ghu2 = (const uint2*)g_Gh;

    int ci = (0 < n) ? c0 : 64;
    float2 fA0 = __ldg((const float2*)(Ar0 + ci*16));
    float2 fA1 = __ldg((const float2*)(Ar8 + ci*16));
    float2 fA2 = __ldg((const float2*)(Ar0 + ci*16 + 8));
    float2 fA3 = __ldg((const float2*)(Ar8 + ci*16 + 8));
    {
        const uint2* Bn = Ghu2 + (size_t)ci*1024;
        sB[0][t]       = __ldg(Bn + t);
        sB[0][t + 512] = __ldg(Bn + t + 512);
    }
    __syncthreads();

    float ps0=0.f, pq0=0.f, ps1=0.f, pq1=0.f;
    int cur = 0;

    for (int it=0; it<total; it++) {
        uint2 fB[8];
        #pragma unroll
        for (int nt=0; nt<8; nt++) fB[nt] = sB[cur][wn*256 + nt*32 + lane];
        if (wn == 0) {
            ps0 += fA0.x+fA0.y+fA2.x+fA2.y;
            pq0 += fA0.x*fA0.x + fA0.y*fA0.y + fA2.x*fA2.x + fA2.y*fA2.y;
            ps1 += fA1.x+fA1.y+fA3.x+fA3.y;
            pq1 += fA1.x*fA1.x + fA1.y*fA1.y + fA3.x*fA3.x + fA3.y*fA3.y;
        }
        __half2 h0 = __floats2half2_rn(fA0.x, fA0.y);
        __half2 h1 = __floats2half2_rn(fA1.x, fA1.y);
        __half2 h2 = __floats2half2_rn(fA2.x, fA2.y);
        __half2 h3 = __floats2half2_rn(fA3.x, fA3.y);
        uint32_t a0 = *reinterpret_cast<uint32_t*>(&h0);
        uint32_t a1 = *reinterpret_cast<uint32_t*>(&h1);
        uint32_t a2 = *reinterpret_cast<uint32_t*>(&h2);
        uint32_t a3 = *reinterpret_cast<uint32_t*>(&h3);
        #pragma unroll
        for (int nt=0; nt<8; nt++) {
            asm volatile(
                "mma.sync.aligned.m16n8k16.row.col.f32.f16.f16.f32 "
                "{%0,%1,%2,%3}, {%4,%5,%6,%7}, {%8,%9}, {%0,%1,%2,%3};"
                : "+f"(acc[nt][0]), "+f"(acc[nt][1]), "+f"(acc[nt][2]), "+f"(acc[nt][3])
                : "r"(a0), "r"(a1), "r"(a2), "r"(a3), "r"(fB[nt].x), "r"(fB[nt].y));
        }
        if (it+1 < total) {
            int itn = it+1;
            ci = (itn < n) ? (c0 + itn) : 64;   // branchless select
            const uint2* Bn = Ghu2 + (size_t)ci*1024;
            sB[cur^1][t]       = __ldg(Bn + t);
            sB[cur^1][t + 512] = __ldg(Bn + t + 512);
            fA0 = __ldg((const float2*)(Ar0 + ci*16));
            fA1 = __ldg((const float2*)(Ar8 + ci*16));
            fA2 = __ldg((const float2*)(Ar0 + ci*16 + 8));
            fA3 = __ldg((const float2*)(Ar8 + ci*16 + 8));
        }
        __syncthreads();
        cur ^= 1;
    }

    if (wn == 0) {
        #pragma unroll
        for (int off=1; off<4; off<<=1) {
            ps0 += __shfl_xor_sync(0xffffffffu, ps0, off);
            pq0 += __shfl_xor_sync(0xffffffffu, pq0, off);
            ps1 += __shfl_xor_sync(0xffffffffu, ps1, off);
            pq1 += __shfl_xor_sync(0xffffffffu, pq1, off);
        }
        if (tig == 0) {
            s_sum[wm*16+g]   = ps0;  s_sq[wm*16+g]   = pq0;
            s_sum[wm*16+g+8] = ps1;  s_sq[wm*16+g+8] = pq1;
        }
    }
    __syncthreads();
    if (t < GBM) {
        float m = s_sum[t] * (1.0f/(float)OUT_);
        float v = s_sq[t]  * (1.0f/(float)OUT_) - m*m;
        s_mu[t] = m;
        s_rs[t] = rsqrtf(v + EPS_);
    }
    __syncthreads();

    float mu0 = s_mu[wm*16+g],   rs0 = s_rs[wm*16+g];
    float mu1 = s_mu[wm*16+g+8], rs1 = s_rs[wm*16+g+8];
    float po0 = 0.f, po1 = 0.f;
    #pragma unroll
    for (int nt=0; nt<8; nt++) {
        #pragma unroll
        for (int e=0; e<2; e++) {
            int col = wn*64 + nt*8 + tig*2 + e;
            float sS = s_s[col], sC = s_c[col], wv = s_w2[col];
            float v0 = (acc[nt][e]   - mu0*sS)*rs0 + sC;
            float v1 = (acc[nt][2+e] - mu1*sS)*rs1 + sC;
            float h0 = 0.5f*v0*(1.0f + erff(v0*0.70710678118654752440f));
            float h1 = 0.5f*v1*(1.0f + erff(v1*0.70710678118654752440f));
            po0 += h0*wv;
            po1 += h1*wv;
        }
    }
    #pragma unroll
    for (int off=1; off<4; off<<=1) {
        po0 += __shfl_xor_sync(0xffffffffu, po0, off);
        po1 += __shfl_xor_sync(0xffffffffu, po1, off);
    }
    if (tig == 0) {
        s_part[wm*16+g][wn]   = po0;
        s_part[wm*16+g+8][wn] = po1;
    }
    __syncthreads();
    if (t < GBM) {
        out[row0 + t] = b2p[0] + s_part[t][0] + s_part[t][1] + s_part[t][2] + s_part[t][3];
    }
}

// ---------------- launch ---------------------------------------------------
extern "C" void kernel_launch(void* const* d_in, const int* in_sizes, int n_in,
                              void* d_out, int out_size) {
    const float* x      = (const float*)d_in[0];
    const float* t      = (const float*)d_in[1];
    const float* te_w1  = (const float*)d_in[2];
    const float* te_b1  = (const float*)d_in[3];
    const float* te_w2  = (const float*)d_in[4];
    const float* te_b2  = (const float*)d_in[5];
    const float* fproj_w= (const float*)d_in[6];
    const float* fproj_b= (const float*)d_in[7];
    const float* bproj_w= (const float*)d_in[8];
    const float* bproj_b= (const float*)d_in[9];
    const float* fz_w   = (const float*)d_in[10];
    const float* fz_b   = (const float*)d_in[11];
    const float* fh_w   = (const float*)d_in[12];
    const float* fh_b   = (const float*)d_in[13];
    const float* bz_w   = (const float*)d_in[14];
    const float* bz_b   = (const float*)d_in[15];
    const float* bh_w   = (const float*)d_in[16];
    const float* bh_b   = (const float*)d_in[17];
    const float* ln_g   = (const float*)d_in[18];
    const float* ln_b   = (const float*)d_in[19];
    const float* tsc    = (const float*)d_in[20];
    const float* gh_w1  = (const float*)d_in[21];
    const float* gh_b1  = (const float*)d_in[22];
    const float* gh_w2  = (const float*)d_in[23];
    const float* gh_b2  = (const float*)d_in[24];
    float* out = (float*)d_out;

    // scanA01 stays 4th: direct predict-verify of the CH=64 latency model.
    k_zero<<<4, 256>>>();
    k_fold<<<dim3(4, 32), 512>>>(fz_w, fh_w, bz_w, bh_w, fz_b, fh_b, bz_b, bh_b,
                                 fproj_w, fproj_b, bproj_w, bproj_b);
    k_te<<<NROW/256, 256>>>(x, t, te_w1, te_b1, te_w2, te_b2);
    k_scanA01<<<dim3(NLIVE, B_, 2), H_>>>();
    k_live<<<dim3(B_, 2), H_>>>();
    k_scanA2<<<dim3(NC_-NLIVE, B_, 2), H_>>>();
    k_prepG<<<HH_, 128>>>(gh_w1, gh_b1, ln_g, ln_b, tsc);
    k_scanB1<<<dim3(B_, 2), H_>>>();
    k_scanC1<<<dim3(NC_, B_, 2), H_>>>();
    k_scanB2<<<dim3(B_, 2), H_>>>();
    k_scanC2<<<dim3(NC_, B_, 2), H_>>>();
    k_gemm3<<<NROW/GBM, 512>>>(gh_w2, gh_b2, out);
}

// round 17
// speedup vs baseline: 6.5470x; 1.0341x over previous
#include <cuda_runtime.h>
#include <cuda_fp16.h>
#include <math.h>
#include <stdint.h>

#define B_  16
#define L_  4096
#define H_  512
#define NT_ 8
#define IN_ 10
#define INP 12               // padded xc stride (48B rows -> LDS.128)
#define OUT_ 1032
#define KP   1056            // padded K (66 chunks of 16)
#define NCH16 66
#define HH_ 256
#define NC_ 64               // 64 chunks of 64
#define CH_ 64
#define NLIVE 8              // liveness window = 8 chunks = 512 steps
#define EPS_ 1e-5f
#define NROW (B_*L_)
#define NTILE (NROW/64)

// ---------------- device scratch (static, allocation-free) ----------------
__device__ float g_xc[(size_t)NROW*INP];            // pads [10],[11] stay 0
__device__ float g_F [(size_t)NROW*KP];             // features (dead regions stay 0)
__device__ float g_W [4][H_][IN_];
__device__ float g_bias[4][H_];
__device__ float g_P [2][B_][NC_][H_];              // chunk a-products (skipped stay 0)
__device__ float g_Ae[2][B_][NC_][H_];              // chunk-entry cumprod states
__device__ float g_Lc[2][B_][NC_][H_];
__device__ float g_Se[2][B_][NC_][H_];
__device__ __half g_Gh[(size_t)NCH16*32*128];       // B fp16 fragment-major (pads 0)
__device__ float g_sv[HH_];
__device__ float g_cv[HH_];
__device__ int   g_tilef[NTILE];                    // per-64-row-tile nonzero flags
__device__ int   g_live[2][B_];                     // per-(dir,b) liveness after NLIVE chunks

// ---------------- fold gate weights: warp-per-h, coalesced -----------------
__global__ void k_fold(const float* __restrict__ fz, const float* __restrict__ fh,
                       const float* __restrict__ bz, const float* __restrict__ bh,
                       const float* __restrict__ fzb, const float* __restrict__ fhb,
                       const float* __restrict__ bzb, const float* __restrict__ bhb,
                       const float* __restrict__ fp, const float* __restrict__ fpb,
                       const float* __restrict__ bp, const float* __restrict__ bpb) {
    int p = blockIdx.x;
    int t = threadIdx.x;
    int warp = t >> 5, lane = t & 31;
    int h = blockIdx.y*16 + warp;
    const float* zw = (p==0)?fz:(p==1)?fh:(p==2)?bz:bh;
    const float* zb = (p==0)?fzb:(p==1)?fhb:(p==2)?bzb:bhb;
    const float* pw = (p<2)?fp:bp;
    const float* pb = (p<2)?fpb:bpb;
    __shared__ float spw[H_*IN_];   // 20KB
    __shared__ float spb[H_];
    for (int i=t; i<H_*IN_; i+=512) spw[i] = pw[i];
    for (int i=t; i<H_;     i+=512) spb[i] = pb[i];
    __syncthreads();
    float acc[IN_]; float ab = 0.f;
    #pragma unroll
    for (int i=0;i<IN_;i++) acc[i]=0.f;
    #pragma unroll 4
    for (int it=0; it<16; it++) {
        int d = it*32 + lane;                 // coalesced zw row read
        float w = __ldg(&zw[h*H_ + d]);
        #pragma unroll
        for (int i=0;i<IN_;i++) acc[i] += w*spw[d*IN_+i];
        ab += w*spb[d];
    }
    #pragma unroll
    for (int off=16; off>0; off>>=1) {
        #pragma unroll
        for (int i=0;i<IN_;i++) acc[i] += __shfl_down_sync(0xffffffffu, acc[i], off);
        ab += __shfl_down_sync(0xffffffffu, ab, off);
    }
    if (lane == 0) {
        #pragma unroll
        for (int i=0;i<IN_;i++) g_W[p][h][i] = acc[i];
        g_bias[p][h] = ab + zb[h];
    }
}

// ---------------- fold LN affine into gh_w1: block-per-k, coalesced --------
__global__ void k_prepG(const float* __restrict__ gw1, const float* __restrict__ gb1,
                        const float* __restrict__ lng, const float* __restrict__ lnb,
                        const float* __restrict__ tscp) {
    int k = blockIdx.x;
    int t = threadIdx.x;
    float tsc = tscp[0];
    int nt = k >> 3, ng = k & 7;
    float s = 0.f, c = 0.f;
    for (int j=t; j<OUT_; j+=128) {
        float sc = (j >= OUT_-NT_) ? tsc : 1.0f;
        float w  = gw1[k*OUT_+j];             // coalesced across threads
        __half Gh = __float2half_rn(lng[j]*sc*w);
        int kt = j >> 4, kin = j & 15;
        int lane = ng*4 + ((kin & 7) >> 1);
        int reg = kin >> 3, hs = kin & 1;
        g_Gh[(((size_t)(kt*32 + nt)*32 + lane)*2 + reg)*2 + hs] = Gh;
        s += __half2float(Gh);
        c += lnb[j]*sc*w;
    }
    __shared__ float rs[128], rc[128];
    rs[t] = s; rc[t] = c;
    __syncthreads();
    #pragma unroll
    for (int off=64; off>0; off>>=1) {
        if (t < off) { rs[t] += rs[t+off]; rc[t] += rc[t+off]; }
        __syncthreads();
    }
    if (t == 0) { g_sv[k] = rs[0]; g_cv[k] = rc[0] + gb1[k]; }
}

// ---------------- time embedding + xc, te into F (+ flag zero) -------------
__global__ void k_te(const float* __restrict__ x, const float* __restrict__ t,
                     const float* __restrict__ w1, const float* __restrict__ b1,
                     const float* __restrict__ w2, const float* __restrict__ b2) {
    int row = blockIdx.x*blockDim.x + threadIdx.x;
    if (row >= NROW) return;
    if (row < NTILE) g_tilef[row] = 0;
    int b = row / L_;
    float ts = t[row] - t[b*L_];
    float r[NT_];
    #pragma unroll
    for (int j=0;j<NT_;j++) r[j] = fmaxf(ts*w1[j] + b1[j], 0.0f);
    float te[NT_];
    #pragma unroll
    for (int k=0;k<NT_;k++) {
        float a = b2[k];
        #pragma unroll
        for (int j=0;j<NT_;j++) a += r[j]*w2[k*NT_+j];
        te[k] = a;
    }
    float x0 = x[row*2+0], x1 = x[row*2+1];
    float* xr = g_xc + (size_t)row*INP;
    *(float4*)(xr+0) = make_float4(x0, x1, te[0], te[1]);
    *(float4*)(xr+4) = make_float4(te[2], te[3], te[4], te[5]);
    *(float4*)(xr+8) = make_float4(te[6], te[7], 0.f, 0.f);
    float* fte = g_F + (size_t)row*KP + (OUT_-NT_);
    *(float4*)(fte)     = make_float4(te[0], te[1], te[2], te[3]);
    *(float4*)(fte + 4) = make_float4(te[4], te[5], te[6], te[7]);
}

// fast sigmoid pieces (full: z and 1-z)
__device__ __forceinline__ void fsig(float arg, float& z, float& omz) {
    float e = __expf(-arg);
    z = __fdividef(1.0f, 1.0f + e);
    omz = e * z;
}

// vectorized dot-10 against padded 48B row (order identical to scalar loop)
__device__ __forceinline__ float dot10(const float* xr, const float* w, float b) {
    float4 v0 = *(const float4*)(xr);
    float4 v1 = *(const float4*)(xr+4);
    float2 v2 = *(const float2*)(xr+8);
    float a = b;
    a += v0.x*w[0]; a += v0.y*w[1]; a += v0.z*w[2]; a += v0.w*w[3];
    a += v1.x*w[4]; a += v1.y*w[5]; a += v1.z*w[6]; a += v1.w*w[7];
    a += v2.x*w[8]; a += v2.y*w[9];
    return a;
}
__device__ __forceinline__ void dot10x2(const float* xr, const float* wz, float bz,
                                        const float* wh, float bh, float& az, float& ah) {
    float4 v0 = *(const float4*)(xr);
    float4 v1 = *(const float4*)(xr+4);
    float2 v2 = *(const float2*)(xr+8);
    float a = bz, c = bh;
    a += v0.x*wz[0]; a += v0.y*wz[1]; a += v0.z*wz[2]; a += v0.w*wz[3];
    a += v1.x*wz[4]; a += v1.y*wz[5]; a += v1.z*wz[6]; a += v1.w*wz[7];
    a += v2.x*wz[8]; a += v2.y*wz[9];
    c += v0.x*wh[0]; c += v0.y*wh[1]; c += v0.z*wh[2]; c += v0.w*wh[3];
    c += v1.x*wh[4]; c += v1.y*wh[5]; c += v1.z*wh[6]; c += v1.w*wh[7];
    c += v2.x*wh[8]; c += v2.y*wh[9];
    az = a; ah = c;
}

// common scanA body (256-thread half-block): chunk product for actual chunk c
__device__ __forceinline__ void scanA_body(int c, int b, int dir, int h, int tid) {
    __shared__ float xs[CH_][INP];
    const float4* xc4 = (const float4*)(g_xc + ((size_t)b*L_ + (size_t)c*CH_)*INP);
    if (tid < CH_*3) ((float4*)xs)[tid] = xc4[tid];
    float wz[IN_]; float bz;
    int pz = dir*2;
    #pragma unroll
    for (int i=0;i<IN_;i++) wz[i] = g_W[pz][h][i];
    bz = g_bias[pz][h];
    __syncthreads();
    float A = 1.0f;
    int s0 = (dir==0)? 0 : CH_-1;
    int ds = (dir==0)? 1 : -1;
    #pragma unroll 4
    for (int k=0;k<CH_;k++) {
        int s = s0 + k*ds;
        float arg = dot10(&xs[s][0], wz, bz);
        float e2 = __expf(arg);                 // omz = 1/(1+e^{arg})
        A *= __fdividef(1.0f, 1.0f + e2);
    }
    g_P[dir][b][c][h] = A;
}

// ---------------- scanA phase 1: first NLIVE chunks, h-split ---------------
// grid (NLIVE*2, B_, 2), block 256. (4th launch -> ncu capture)
__global__ void k_scanA01() {
    int cs = blockIdx.x >> 1, half = blockIdx.x & 1;
    int b = blockIdx.y, dir = blockIdx.z;
    int c = dir ? (NC_-1-cs) : cs;
    scanA_body(c, b, dir, half*256 + threadIdx.x, threadIdx.x);
}

// ---------------- liveness after NLIVE chunks ------------------------------
__global__ void k_live() {
    int b = blockIdx.x, dir = blockIdx.y, h = threadIdx.x;
    float p = 1.0f;
    #pragma unroll
    for (int cs=0; cs<NLIVE; cs++) {
        int c = dir ? (NC_-1-cs) : cs;
        p *= g_P[dir][b][c][h];                 // == B1's run after NLIVE chunks
    }
    int lv = __syncthreads_or(p != 0.f);
    if (h == 0) g_live[dir][b] = lv;
}

// ---------------- scanA phase 2: remaining chunks, h-split, if live --------
__global__ void k_scanA2() {
    int cs = (blockIdx.x >> 1) + NLIVE, half = blockIdx.x & 1;
    int b = blockIdx.y, dir = blockIdx.z;
    if (!g_live[dir][b]) return;        // uniform: skipped P stays 0
    int c = dir ? (NC_-1-cs) : cs;
    scanA_body(c, b, dir, half*256 + threadIdx.x, threadIdx.x);
}

// ---------------- scan pass B1: entry cumprod states + tile flags ----------
// flag equivalence: tile live in dir <=> OR_h(Ae != 0); Ae-liveness is
// monotone per h, so block-max of last-live chunk index gives the flag set.
__global__ void k_scanB1() {
    int b = blockIdx.x, dir = blockIdx.y, h = threadIdx.x;
    __shared__ int sred[H_];
    float run = 1.0f;
    int cm = -1;
    for (int cs=0; cs<NC_; cs++) {
        int c = dir ? (NC_-1-cs) : cs;
        g_Ae[dir][b][c][h] = run;
        if (run != 0.f) cm = cs;
        run *= g_P[dir][b][c][h];
    }
    sred[h] = cm;
    __syncthreads();
    #pragma unroll
    for (int off=256; off>0; off>>=1) {
        if (h < off) sred[h] = max(sred[h], sred[h+off]);
        __syncthreads();
    }
    if (h == 0) {
        int cmax = sred[0];
        for (int cs=0; cs<=cmax; cs++) {
            int c = dir ? (NC_-1-cs) : cs;
            atomicOr(&g_tilef[b*NC_ + c], 1 << dir);
        }
    }
}

// ---------------- scan pass C1: chunk local sums, h-split ------------------
// grid (NC_*2, B_, 2), block 256
__global__ void k_scanC1() {
    int c = blockIdx.x >> 1, half = blockIdx.x & 1;
    int b = blockIdx.y, dir = blockIdx.z;
    int tid = threadIdx.x, h = half*256 + tid;
    __shared__ float xs[CH_][INP];
    float A = g_Ae[dir][b][c][h];
    if (!__syncthreads_or(A != 0.f)) { g_Lc[dir][b][c][h] = 0.f; return; }
    const float4* xc4 = (const float4*)(g_xc + ((size_t)b*L_ + (size_t)c*CH_)*INP);
    if (tid < CH_*3) ((float4*)xs)[tid] = xc4[tid];
    float wz[IN_], wh[IN_]; float bz, bh;
    int pz = dir*2, ph = dir*2+1;
    #pragma unroll
    for (int i=0;i<IN_;i++) { wz[i]=g_W[pz][h][i]; wh[i]=g_W[ph][h][i]; }
    bz = g_bias[pz][h]; bh = g_bias[ph][h];
    __syncthreads();
    float Ls = 0.0f;
    int s0  = (dir==0)? 0 : CH_-1;
    int ds  = (dir==0)? 1 : -1;
    #pragma unroll 4
    for (int k=0;k<CH_;k++) {
        int s = s0 + k*ds;
        float az, ah;
        dot10x2(&xs[s][0], wz, bz, wh, bh, az, ah);
        float z, omz; fsig(az, z, omz);
        A *= omz;
        Ls += __fdividef(z*ah, fmaxf(A, 1e-12f));
    }
    g_Lc[dir][b][c][h] = Ls;
}

// ---------------- scan pass B2: chunk-entry cumsum states ------------------
__global__ void k_scanB2() {
    int b = blockIdx.x, dir = blockIdx.y, h = threadIdx.x;
    float run = 0.0f;
    if (dir==0) { for (int c=0;c<NC_;c++)    { g_Se[0][b][c][h]=run; run += g_Lc[0][b][c][h]; } }
    else        { for (int c=NC_-1;c>=0;c--) { g_Se[1][b][c][h]=run; run += g_Lc[1][b][c][h]; } }
}

// ---------------- scan pass C2: emit h = A*S, h-split ----------------------
// grid (NC_*2, B_, 2), block 256
__global__ void k_scanC2() {
    int c = blockIdx.x >> 1, half = blockIdx.x & 1;
    int b = blockIdx.y, dir = blockIdx.z;
    int tid = threadIdx.x, h = half*256 + tid;
    __shared__ float xs[CH_][INP];
    float A = g_Ae[dir][b][c][h];
    if (!__syncthreads_or(A != 0.f)) return;    // region stays exact 0
    const float4* xc4 = (const float4*)(g_xc + ((size_t)b*L_ + (size_t)c*CH_)*INP);
    if (tid < CH_*3) ((float4*)xs)[tid] = xc4[tid];
    float wz[IN_], wh[IN_]; float bz, bh;
    int pz = dir*2, ph = dir*2+1;
    #pragma unroll
    for (int i=0;i<IN_;i++) { wz[i]=g_W[pz][h][i]; wh[i]=g_W[ph][h][i]; }
    bz = g_bias[pz][h]; bh = g_bias[ph][h];
    float S = g_Se[dir][b][c][h];
    __syncthreads();
    int s0  = (dir==0)? 0 : CH_-1;
    int ds  = (dir==0)? 1 : -1;
    size_t fofs = (dir==0)? (size_t)h : (size_t)(H_ + h);
    float* fp = g_F + ((size_t)(b*L_ + c*CH_ + s0))*KP + fofs;
    ptrdiff_t fstep = (ptrdiff_t)ds * KP;
    #pragma unroll 4
    for (int k=0;k<CH_;k++) {
        int s = s0 + k*ds;
        *fp = A*S;                              // state BEFORE consuming position
        fp += fstep;
        float az, ah;
        dot10x2(&xs[s][0], wz, bz, wh, bh, az, ah);
        float z, omz; fsig(az, z, omz);
        A *= omz;
        S += __fdividef(z*ah, fmaxf(A, 1e-12f));
    }
}

// ---------------- fp16 mma GEMM (smem-staged B, contiguous live range) -----
#define GBM 64
__global__ __launch_bounds__(512, 1) void k_gemm3(const float* __restrict__ w2,
                                                  const float* __restrict__ b2p,
                                                  float* __restrict__ out) {
    __shared__ float s_s[HH_], s_c[HH_], s_w2[HH_];
    __shared__ float s_sum[GBM], s_sq[GBM];
    __shared__ float s_mu[GBM], s_rs[GBM];
    __shared__ float s_part[GBM][4];
    __shared__ uint2 sB[2][1024];               // double-buffered B chunk (8KB x2)

    int t = threadIdx.x;
    int lane = t & 31, warp = t >> 5;
    int wm = warp >> 2, wn = warp & 3;          // 4m x 4n warp grid
    int g  = lane >> 2, tig = lane & 3;
    int row0 = blockIdx.x * GBM;
    int r0 = row0 + wm*16 + g;

    if (t < HH_) { s_s[t] = g_sv[t]; s_c[t] = g_cv[t]; s_w2[t] = w2[t]; }

    int flag = g_tilef[blockIdx.x] & 3;
    int c0 = (flag & 1) ? 0 : 32;               // contiguous live chunk range start
    int n  = (flag == 3) ? 64 : (flag ? 32 : 0);
    int total = n + 1;                          // + te chunk (64)

    float acc[8][4];
    #pragma unroll
    for (int i=0;i<8;i++) { acc[i][0]=0.f; acc[i][1]=0.f; acc[i][2]=0.f; acc[i][3]=0.f; }

    const float* Ar0 = g_F + (size_t)r0*KP     + tig*2;
    const float* Ar8 = Ar0 + 8*KP;
    const uint2* Ghu2 = (const uint2*)g_Gh;

    int ci = (0 < n) ? c0 : 64;
    float2 fA0 = __ldg((const float2*)(Ar0 + ci*16));
    float2 fA1 = __ldg((const float2*)(Ar8 + ci*16));
    float2 fA2 = __ldg((const float2*)(Ar0 + ci*16 + 8));
    float2 fA3 = __ldg((const float2*)(Ar8 + ci*16 + 8));
    {
        const uint2* Bn = Ghu2 + (size_t)ci*1024;
        sB[0][t]       = __ldg(Bn + t);
        sB[0][t + 512] = __ldg(Bn + t + 512);
    }
    __syncthreads();

    float ps0=0.f, pq0=0.f, ps1=0.f, pq1=0.f;
    int cur = 0;

    for (int it=0; it<total; it++) {
        uint2 fB[8];
        #pragma unroll
        for (int nt=0; nt<8; nt++) fB[nt] = sB[cur][wn*256 + nt*32 + lane];
        if (wn == 0) {
            ps0 += fA0.x+fA0.y+fA2.x+fA2.y;
            pq0 += fA0.x*fA0.x + fA0.y*fA0.y + fA2.x*fA2.x + fA2.y*fA2.y;
            ps1 += fA1.x+fA1.y+fA3.x+fA3.y;
            pq1 += fA1.x*fA1.x + fA1.y*fA1.y + fA3.x*fA3.x + fA3.y*fA3.y;
        }
        __half2 h0 = __floats2half2_rn(fA0.x, fA0.y);
        __half2 h1 = __floats2half2_rn(fA1.x, fA1.y);
        __half2 h2 = __floats2half2_rn(fA2.x, fA2.y);
        __half2 h3 = __floats2half2_rn(fA3.x, fA3.y);
        uint32_t a0 = *reinterpret_cast<uint32_t*>(&h0);
        uint32_t a1 = *reinterpret_cast<uint32_t*>(&h1);
        uint32_t a2 = *reinterpret_cast<uint32_t*>(&h2);
        uint32_t a3 = *reinterpret_cast<uint32_t*>(&h3);
        #pragma unroll
        for (int nt=0; nt<8; nt++) {
            asm volatile(
                "mma.sync.aligned.m16n8k16.row.col.f32.f16.f16.f32 "
                "{%0,%1,%2,%3}, {%4,%5,%6,%7}, {%8,%9}, {%0,%1,%2,%3};"
                : "+f"(acc[nt][0]), "+f"(acc[nt][1]), "+f"(acc[nt][2]), "+f"(acc[nt][3])
                : "r"(a0), "r"(a1), "r"(a2), "r"(a3), "r"(fB[nt].x), "r"(fB[nt].y));
        }
        if (it+1 < total) {
            int itn = it+1;
            ci = (itn < n) ? (c0 + itn) : 64;   // branchless select
            const uint2* Bn = Ghu2 + (size_t)ci*1024;
            sB[cur^1][t]       = __ldg(Bn + t);
            sB[cur^1][t + 512] = __ldg(Bn + t + 512);
            fA0 = __ldg((const float2*)(Ar0 + ci*16));
            fA1 = __ldg((const float2*)(Ar8 + ci*16));
            fA2 = __ldg((const float2*)(Ar0 + ci*16 + 8));
            fA3 = __ldg((const float2*)(Ar8 + ci*16 + 8));
        }
        __syncthreads();
        cur ^= 1;
    }

    if (wn == 0) {
        #pragma unroll
        for (int off=1; off<4; off<<=1) {
            ps0 += __shfl_xor_sync(0xffffffffu, ps0, off);
            pq0 += __shfl_xor_sync(0xffffffffu, pq0, off);
            ps1 += __shfl_xor_sync(0xffffffffu, ps1, off);
            pq1 += __shfl_xor_sync(0xffffffffu, pq1, off);
        }
        if (tig == 0) {
            s_sum[wm*16+g]   = ps0;  s_sq[wm*16+g]   = pq0;
            s_sum[wm*16+g+8] = ps1;  s_sq[wm*16+g+8] = pq1;
        }
    }
    __syncthreads();
    if (t < GBM) {
        float m = s_sum[t] * (1.0f/(float)OUT_);
        float v = s_sq[t]  * (1.0f/(float)OUT_) - m*m;
        s_mu[t] = m;
        s_rs[t] = rsqrtf(v + EPS_);
    }
    __syncthreads();

    float mu0 = s_mu[wm*16+g],   rs0 = s_rs[wm*16+g];
    float mu1 = s_mu[wm*16+g+8], rs1 = s_rs[wm*16+g+8];
    float po0 = 0.f, po1 = 0.f;
    #pragma unroll
    for (int nt=0; nt<8; nt++) {
        #pragma unroll
        for (int e=0; e<2; e++) {
            int col = wn*64 + nt*8 + tig*2 + e;
            float sS = s_s[col], sC = s_c[col], wv = s_w2[col];
            float v0 = (acc[nt][e]   - mu0*sS)*rs0 + sC;
            float v1 = (acc[nt][2+e] - mu1*sS)*rs1 + sC;
            float h0 = 0.5f*v0*(1.0f + erff(v0*0.70710678118654752440f));
            float h1 = 0.5f*v1*(1.0f + erff(v1*0.70710678118654752440f));
            po0 += h0*wv;
            po1 += h1*wv;
        }
    }
    #pragma unroll
    for (int off=1; off<4; off<<=1) {
        po0 += __shfl_xor_sync(0xffffffffu, po0, off);
        po1 += __shfl_xor_sync(0xffffffffu, po1, off);
    }
    if (tig == 0) {
        s_part[wm*16+g][wn]   = po0;
        s_part[wm*16+g+8][wn] = po1;
    }
    __syncthreads();
    if (t < GBM) {
        out[row0 + t] = b2p[0] + s_part[t][0] + s_part[t][1] + s_part[t][2] + s_part[t][3];
    }
}

// ---------------- launch ---------------------------------------------------
extern "C" void kernel_launch(void* const* d_in, const int* in_sizes, int n_in,
                              void* d_out, int out_size) {
    const float* x      = (const float*)d_in[0];
    const float* t      = (const float*)d_in[1];
    const float* te_w1  = (const float*)d_in[2];
    const float* te_b1  = (const float*)d_in[3];
    const float* te_w2  = (const float*)d_in[4];
    const float* te_b2  = (const float*)d_in[5];
    const float* fproj_w= (const float*)d_in[6];
    const float* fproj_b= (const float*)d_in[7];
    const float* bproj_w= (const float*)d_in[8];
    const float* bproj_b= (const float*)d_in[9];
    const float* fz_w   = (const float*)d_in[10];
    const float* fz_b   = (const float*)d_in[11];
    const float* fh_w   = (const float*)d_in[12];
    const float* fh_b   = (const float*)d_in[13];
    const float* bz_w   = (const float*)d_in[14];
    const float* bz_b   = (const float*)d_in[15];
    const float* bh_w   = (const float*)d_in[16];
    const float* bh_b   = (const float*)d_in[17];
    const float* ln_g   = (const float*)d_in[18];
    const float* ln_b   = (const float*)d_in[19];
    const float* tsc    = (const float*)d_in[20];
    const float* gh_w1  = (const float*)d_in[21];
    const float* gh_b1  = (const float*)d_in[22];
    const float* gh_w2  = (const float*)d_in[23];
    const float* gh_b2  = (const float*)d_in[24];
    float* out = (float*)d_out;

    // 4th launch = split scanA01 -> ncu capture verifies the occupancy theory
    k_te<<<NROW/256, 256>>>(x, t, te_w1, te_b1, te_w2, te_b2);
    k_prepG<<<HH_, 128>>>(gh_w1, gh_b1, ln_g, ln_b, tsc);
    k_fold<<<dim3(4, 32), 512>>>(fz_w, fh_w, bz_w, bh_w, fz_b, fh_b, bz_b, bh_b,
                                 fproj_w, fproj_b, bproj_w, bproj_b);
    k_scanA01<<<dim3(NLIVE*2, B_, 2), 256>>>();
    k_live<<<dim3(B_, 2), H_>>>();
    k_scanA2<<<dim3((NC_-NLIVE)*2, B_, 2), 256>>>();
    k_scanB1<<<dim3(B_, 2), H_>>>();
    k_scanC1<<<dim3(NC_*2, B_, 2), 256>>>();
    k_scanB2<<<dim3(B_, 2), H_>>>();
    k_scanC2<<<dim3(NC_*2, B_, 2), 256>>>();
    k_gemm3<<<NROW/GBM, 512>>>(gh_w2, gh_b2, out);
}